// round 1
// baseline (speedup 1.0000x reference)
#include <cuda_runtime.h>
#include <cstdint>

// ---------------------------------------------------------------------------
// Problem constants
// ---------------------------------------------------------------------------
#define CB   8      // batch
#define CL   512    // query length
#define CM   512    // xl memory length
#define CH   8      // heads
#define CDK  128
#define CDV  128
#define CS   512    // codebook size
#define CDM  1024
#define CW   1024   // W_REC = M + L
#define NBH  64     // B*H
#define NROWS 4096  // B*L
#define SCW  1536   // W + S  (joint softmax width)

static __device__ __constant__ const float TAUI = 0.08838834764831845f; // 1/sqrt(128)

// ---------------------------------------------------------------------------
// Scratch (static device allocations; no runtime alloc)
// ---------------------------------------------------------------------------
__device__ float g_xt   [(size_t)NROWS * CDM];        // LN(input)
__device__ float g_qraw [(size_t)NROWS * CDM];        // x_t @ W_q
__device__ float g_kvg  [(size_t)NROWS * 3072];       // x_t @ W_kvg
__device__ float g_qu   [(size_t)NBH * CL * CDK];     // LN(q)+x_u  (B,H,L,DK)
__device__ float g_qvb  [(size_t)NBH * CL * CDK];     // LN(q)+x_v
__device__ float g_kl   [(size_t)NBH * CL * CDK];     // LN(k)
__device__ float g_vv   [(size_t)NBH * CL * CDV];     // v          (B,H,L,DV)
__device__ float g_gate [(size_t)NROWS * CDM];        // silu(g)    (B,L,H*DV)
__device__ float g_rbd  [(size_t)NBH * CL * CW];      // qv @ xl_r^T / TAU
__device__ float g_scores[(size_t)NBH * CL * SCW];    // joint scores / probs
__device__ float g_wvg  [(size_t)NROWS * CDM];        // (wv * g)   (B,L,H*DV)
__device__ unsigned long long g_zpk[NBH * CL];        // packed (d2,idx) argmin
__device__ float g_csq  [CH * CS];                    // |codebook|^2

// ---------------------------------------------------------------------------
// Block reductions
// ---------------------------------------------------------------------------
__device__ __forceinline__ float block_sum(float v) {
    __shared__ float sb_[8];
    int tid = threadIdx.x;
    int nw  = blockDim.x >> 5;
    #pragma unroll
    for (int o = 16; o; o >>= 1) v += __shfl_down_sync(0xffffffffu, v, o);
    __syncthreads();                       // protect sb_ reuse (WAR)
    if ((tid & 31) == 0) sb_[tid >> 5] = v;
    __syncthreads();
    float r = 0.f;
    for (int i = 0; i < nw; ++i) r += sb_[i];
    return r;
}

// ---------------------------------------------------------------------------
// LayerNorm over DM=1024 (input features). 256 threads, 4 elems/thread.
// ---------------------------------------------------------------------------
__global__ void __launch_bounds__(256) ln_rows_kernel(const float* __restrict__ x,
                                                      float* __restrict__ y) {
    int row = blockIdx.x;
    const float* xr = x + (size_t)row * CDM;
    float*       yr = y + (size_t)row * CDM;
    int tid = threadIdx.x;
    float v[4]; float s = 0.f;
    #pragma unroll
    for (int i = 0; i < 4; ++i) { v[i] = xr[tid + i * 256]; s += v[i]; }
    float mu = block_sum(s) * (1.f / 1024.f);
    float s2 = 0.f;
    #pragma unroll
    for (int i = 0; i < 4; ++i) { v[i] -= mu; s2 += v[i] * v[i]; }
    float rstd = rsqrtf(block_sum(s2) * (1.f / 1024.f) + 1e-6f);
    #pragma unroll
    for (int i = 0; i < 4; ++i) yr[tid + i * 256] = v[i] * rstd;
}

// ---------------------------------------------------------------------------
// Generic SGEMM: C(MxN) = A(MxK) @ B(KxN), row-major, no bounds checks
// (all dims multiples of 128/16). 128x128 tile, BK=16, 256 thr, 8x8 micro.
// ---------------------------------------------------------------------------
__global__ void __launch_bounds__(256) sgemm_kernel(const float* __restrict__ A,
                                                    const float* __restrict__ B,
                                                    float* __restrict__ C,
                                                    int M, int N, int K) {
    __shared__ float As[16][128];
    __shared__ float Bs[16][128];
    int bm = blockIdx.y * 128;
    int bn = blockIdx.x * 128;
    int tid = threadIdx.x;
    int tr = (tid >> 4) << 3;
    int tc = (tid & 15) << 3;
    float acc[8][8] = {};
    for (int k0 = 0; k0 < K; k0 += 16) {
        #pragma unroll
        for (int i = 0; i < 2; ++i) {
            int p = tid * 2 + i;
            int r = p >> 2;
            int c = (p & 3) << 2;
            float4 av = *(const float4*)(A + (size_t)(bm + r) * K + k0 + c);
            As[c + 0][r] = av.x; As[c + 1][r] = av.y;
            As[c + 2][r] = av.z; As[c + 3][r] = av.w;
            int rr = p >> 5;
            int cc = (p & 31) << 2;
            *(float4*)&Bs[rr][cc] = *(const float4*)(B + (size_t)(k0 + rr) * N + bn + cc);
        }
        __syncthreads();
        #pragma unroll
        for (int k = 0; k < 16; ++k) {
            float a[8], b[8];
            *(float4*)(a)     = *(const float4*)&As[k][tr];
            *(float4*)(a + 4) = *(const float4*)&As[k][tr + 4];
            *(float4*)(b)     = *(const float4*)&Bs[k][tc];
            *(float4*)(b + 4) = *(const float4*)&Bs[k][tc + 4];
            #pragma unroll
            for (int i = 0; i < 8; ++i)
                #pragma unroll
                for (int j = 0; j < 8; ++j)
                    acc[i][j] = fmaf(a[i], b[j], acc[i][j]);
        }
        __syncthreads();
    }
    #pragma unroll
    for (int i = 0; i < 8; ++i) {
        float* crow = C + (size_t)(bm + tr + i) * N + bn + tc;
        #pragma unroll
        for (int j = 0; j < 8; j += 4) {
            float4 v4 = make_float4(acc[i][j], acc[i][j + 1], acc[i][j + 2], acc[i][j + 3]);
            *(float4*)(crow + j) = v4;
        }
    }
}

// ---------------------------------------------------------------------------
// Per-(b,l,h): LN(q)->qu/qv, LN(k)->kl, copy v, silu(g). 128 threads.
// ---------------------------------------------------------------------------
__global__ void __launch_bounds__(128) transform_kernel(const float* __restrict__ qraw,
                                                        const float* __restrict__ kvg,
                                                        const float* __restrict__ x_u,
                                                        const float* __restrict__ x_v,
                                                        float* __restrict__ qu,
                                                        float* __restrict__ qv,
                                                        float* __restrict__ kl,
                                                        float* __restrict__ vv,
                                                        float* __restrict__ gate) {
    int idx = blockIdx.x;        // (b*L+l)*H + h
    int h  = idx & 7;
    int bl = idx >> 3;
    int b = bl >> 9, l = bl & 511;
    int d = threadIdx.x;

    float q  = qraw[(size_t)bl * CDM + h * CDK + d];
    float mu = block_sum(q) * (1.f / 128.f);
    float qc = q - mu;
    float var = block_sum(qc * qc) * (1.f / 128.f);
    float qn  = qc * rsqrtf(var + 1e-6f);
    size_t o = (((size_t)b * CH + h) * CL + l) * CDK + d;
    qu[o] = qn + x_u[h * CDK + d];
    qv[o] = qn + x_v[h * CDK + d];

    float k   = kvg[(size_t)bl * 3072 + h * CDK + d];
    float kmu = block_sum(k) * (1.f / 128.f);
    float kc  = k - kmu;
    float kvar = block_sum(kc * kc) * (1.f / 128.f);
    kl[o] = kc * rsqrtf(kvar + 1e-6f);

    vv[o] = kvg[(size_t)bl * 3072 + 1024 + h * CDK + d];

    float gg = kvg[(size_t)bl * 3072 + 2048 + h * CDK + d];
    gate[(size_t)bl * CDM + h * CDK + d] = gg / (1.f + __expf(-gg));
}

// ---------------------------------------------------------------------------
// |codebook row|^2
// ---------------------------------------------------------------------------
__global__ void __launch_bounds__(128) csq_kernel(const float* __restrict__ cb,
                                                  float* __restrict__ csq) {
    int row = blockIdx.x;  // H*S
    float v = cb[(size_t)row * CDK + threadIdx.x];
    v = block_sum(v * v);
    if (threadIdx.x == 0) csq[row] = v;
}

__global__ void zinit_kernel(unsigned long long* zpk) {
    zpk[blockIdx.x * 512 + threadIdx.x] = ~0ull;
}

// ---------------------------------------------------------------------------
// Batched attention GEMM: C = A(bh) @ Brows^T, K=128, 128x128 tile.
// Modes: 0=BD (xl_r), 1=RECENT (xl_k_hat | codebook[z], +rbd shift +mask),
//        2=CACHE (codebook, +log bias), 3=VQ (argmin epilogue).
// ---------------------------------------------------------------------------
template <int MODE>
__global__ void __launch_bounds__(256) battn_kernel(
    const float* __restrict__ Abase,
    const float* __restrict__ xl_k_hat,
    const float* __restrict__ codebook,
    const float* __restrict__ xl_r,
    const float* __restrict__ agg_lower,
    const float* __restrict__ csq,
    const unsigned long long* __restrict__ zpk_in,
    unsigned long long* zpk_out,
    const float* __restrict__ rbd_in,
    float* __restrict__ outp) {
    int bh = blockIdx.z;
    int h  = bh & 7;
    int bm = blockIdx.y * 128;
    int bn = blockIdx.x * 128;
    const float* A = Abase + (size_t)bh * CL * CDK;

    __shared__ float As[16][128];
    __shared__ float Bs[16][128];
    int tid = threadIdx.x;
    int tr = (tid >> 4) << 3;
    int tc = (tid & 15) << 3;
    float acc[8][8] = {};

    #pragma unroll 1
    for (int k0 = 0; k0 < 128; k0 += 16) {
        #pragma unroll
        for (int i = 0; i < 2; ++i) {
            int p = tid * 2 + i;
            int r = p >> 2;
            int c = (p & 3) << 2;
            float4 av = *(const float4*)(A + (size_t)(bm + r) * CDK + k0 + c);
            As[c + 0][r] = av.x; As[c + 1][r] = av.y;
            As[c + 2][r] = av.z; As[c + 3][r] = av.w;

            int n = bn + r;
            const float* bp;
            if constexpr (MODE == 0) {
                bp = xl_r + ((size_t)h * CW + n) * CDK;
            } else if constexpr (MODE == 1) {
                if (n < CM) bp = xl_k_hat + ((size_t)bh * CM + n) * CDK;
                else {
                    unsigned zi = (unsigned)(zpk_in[(size_t)bh * CL + (n - CM)] & 0xffffffffull);
                    bp = codebook + ((size_t)h * CS + zi) * CDK;
                }
            } else {
                bp = codebook + ((size_t)h * CS + n) * CDK;
            }
            float4 bv = *(const float4*)(bp + k0 + c);
            Bs[c + 0][r] = bv.x; Bs[c + 1][r] = bv.y;
            Bs[c + 2][r] = bv.z; Bs[c + 3][r] = bv.w;
        }
        __syncthreads();
        #pragma unroll
        for (int k = 0; k < 16; ++k) {
            float a[8], b[8];
            *(float4*)(a)     = *(const float4*)&As[k][tr];
            *(float4*)(a + 4) = *(const float4*)&As[k][tr + 4];
            *(float4*)(b)     = *(const float4*)&Bs[k][tc];
            *(float4*)(b + 4) = *(const float4*)&Bs[k][tc + 4];
            #pragma unroll
            for (int i = 0; i < 8; ++i)
                #pragma unroll
                for (int j = 0; j < 8; ++j)
                    acc[i][j] = fmaf(a[i], b[j], acc[i][j]);
        }
        __syncthreads();
    }

    if constexpr (MODE == 0) {           // Rbd = qv @ xl_r^T / TAU
        #pragma unroll
        for (int i = 0; i < 8; ++i) {
            int l = bm + tr + i;
            float* orow = outp + ((size_t)bh * CL + l) * CW + bn + tc;
            #pragma unroll
            for (int j = 0; j < 8; j += 4) {
                float4 v4 = make_float4(acc[i][j] * TAUI, acc[i][j + 1] * TAUI,
                                        acc[i][j + 2] * TAUI, acc[i][j + 3] * TAUI);
                *(float4*)(orow + j) = v4;
            }
        }
    } else if constexpr (MODE == 1) {    // recent scores (+rel_shift bias, +mask)
        #pragma unroll
        for (int i = 0; i < 8; ++i) {
            int l = bm + tr + i;
            const float* rrow = rbd_in + ((size_t)bh * CL + l) * CW;
            float* orow = outp + ((size_t)bh * CL + l) * SCW;
            #pragma unroll
            for (int j = 0; j < 8; ++j) {
                int w = bn + tc + j;
                float sc = -1e30f;
                if (w <= l + CM) sc = acc[i][j] * TAUI + rrow[w + (CL - 1) - l];
                orow[w] = sc;
            }
        }
    } else if constexpr (MODE == 2) {    // cache scores (+log bias)
        #pragma unroll
        for (int i = 0; i < 8; ++i) {
            int l = bm + tr + i;
            float* orow = outp + ((size_t)bh * CL + l) * SCW + CW;
            #pragma unroll
            for (int j = 0; j < 8; ++j) {
                int s = bn + tc + j;
                float al = agg_lower[(size_t)bh * CS + s];
                float bias = (al > 0.f) ? logf(fmaxf(al, 1e-30f)) : -1e30f;
                orow[s] = acc[i][j] * TAUI + bias;
            }
        }
    } else {                              // VQ argmin over codes
        __shared__ unsigned long long rkey[128][17];
        #pragma unroll
        for (int i = 0; i < 8; ++i) {
            unsigned long long bk = ~0ull;
            #pragma unroll
            for (int j = 0; j < 8; ++j) {
                int s = bn + tc + j;
                float val = csq[h * CS + s] - 2.f * acc[i][j];
                unsigned u = __float_as_uint(val);
                u = (u & 0x80000000u) ? ~u : (u | 0x80000000u);
                unsigned long long key = ((unsigned long long)u << 32) | (unsigned)s;
                if (key < bk) bk = key;
            }
            rkey[tr + i][tid & 15] = bk;
        }
        __syncthreads();
        if (tid < 128) {
            unsigned long long bk = rkey[tid][0];
            #pragma unroll
            for (int t = 1; t < 16; ++t) {
                unsigned long long k2 = rkey[tid][t];
                if (k2 < bk) bk = k2;
            }
            atomicMin(&zpk_out[(size_t)bh * CL + bm + tid], bk);
        }
    }
}

// ---------------------------------------------------------------------------
// Joint softmax over 1536 keys; writes normalized probabilities in place.
// ---------------------------------------------------------------------------
__global__ void __launch_bounds__(256) softmax_kernel(float* __restrict__ scores) {
    float* row = scores + (size_t)blockIdx.x * SCW;
    int tid = threadIdx.x;
    __shared__ float sb[8];
    float v[6];
    float m = -3.4e38f;
    #pragma unroll
    for (int i = 0; i < 6; ++i) { v[i] = row[tid + i * 256]; m = fmaxf(m, v[i]); }
    #pragma unroll
    for (int o = 16; o; o >>= 1) m = fmaxf(m, __shfl_down_sync(0xffffffffu, m, o));
    if ((tid & 31) == 0) sb[tid >> 5] = m;
    __syncthreads();
    m = sb[0];
    #pragma unroll
    for (int i = 1; i < 8; ++i) m = fmaxf(m, sb[i]);
    __syncthreads();
    float s = 0.f;
    #pragma unroll
    for (int i = 0; i < 6; ++i) { v[i] = __expf(v[i] - m); s += v[i]; }
    #pragma unroll
    for (int o = 16; o; o >>= 1) s += __shfl_down_sync(0xffffffffu, s, o);
    if ((tid & 31) == 0) sb[tid >> 5] = s;
    __syncthreads();
    float tot = sb[0];
    #pragma unroll
    for (int i = 1; i < 8; ++i) tot += sb[i];
    float inv = 1.f / tot;
    #pragma unroll
    for (int i = 0; i < 6; ++i) row[tid + i * 256] = v[i] * inv;
}

// ---------------------------------------------------------------------------
// wv = P(512x1536) @ Vgather(1536x128), fused *gate, write (B,L,H*DV)
// ---------------------------------------------------------------------------
__global__ void __launch_bounds__(256) wv_kernel(const float* __restrict__ P,
                                                 const float* __restrict__ xl_v,
                                                 const float* __restrict__ vcur,
                                                 const float* __restrict__ aggu,
                                                 const float* __restrict__ gate,
                                                 float* __restrict__ wvg) {
    int bh = blockIdx.z;
    int b = bh >> 3, h = bh & 7;
    int bm = blockIdx.y * 128;
    const float* A = P + (size_t)bh * CL * SCW;
    __shared__ float As[16][128];
    __shared__ float Bs[16][128];
    int tid = threadIdx.x;
    int tr = (tid >> 4) << 3;
    int tc = (tid & 15) << 3;
    float acc[8][8] = {};
    #pragma unroll 1
    for (int k0 = 0; k0 < SCW; k0 += 16) {
        #pragma unroll
        for (int i = 0; i < 2; ++i) {
            int p = tid * 2 + i;
            int r = p >> 2;
            int c = (p & 3) << 2;
            float4 av = *(const float4*)(A + (size_t)(bm + r) * SCW + k0 + c);
            As[c + 0][r] = av.x; As[c + 1][r] = av.y;
            As[c + 2][r] = av.z; As[c + 3][r] = av.w;
            int rr = p >> 5;
            int cc = (p & 31) << 2;
            int j = k0 + rr;
            const float* bp;
            if (j < CM)       bp = xl_v + ((size_t)bh * CM + j) * CDV;
            else if (j < CW)  bp = vcur + ((size_t)bh * CL + (j - CM)) * CDV;
            else              bp = aggu + ((size_t)bh * CS + (j - CW)) * CDV;
            *(float4*)&Bs[rr][cc] = *(const float4*)(bp + cc);
        }
        __syncthreads();
        #pragma unroll
        for (int k = 0; k < 16; ++k) {
            float a[8], bq[8];
            *(float4*)(a)      = *(const float4*)&As[k][tr];
            *(float4*)(a + 4)  = *(const float4*)&As[k][tr + 4];
            *(float4*)(bq)     = *(const float4*)&Bs[k][tc];
            *(float4*)(bq + 4) = *(const float4*)&Bs[k][tc + 4];
            #pragma unroll
            for (int i = 0; i < 8; ++i)
                #pragma unroll
                for (int j = 0; j < 8; ++j)
                    acc[i][j] = fmaf(a[i], bq[j], acc[i][j]);
        }
        __syncthreads();
    }
    #pragma unroll
    for (int i = 0; i < 8; ++i) {
        int l = bm + tr + i;
        size_t base = ((size_t)b * CL + l) * CDM + h * CDV + tc;
        #pragma unroll
        for (int j = 0; j < 8; ++j)
            wvg[base + j] = acc[i][j] * gate[base + j];
    }
}

// ---------------------------------------------------------------------------
// Host launcher (graph-capturable: kernel launches only)
// ---------------------------------------------------------------------------
extern "C" void kernel_launch(void* const* d_in, const int* in_sizes, int n_in,
                              void* d_out, int out_size) {
    const float* input     = (const float*)d_in[0];
    const float* xl_k_hat  = (const float*)d_in[2];
    const float* xl_v      = (const float*)d_in[3];
    const float* agg_upper = (const float*)d_in[4];
    const float* agg_lower = (const float*)d_in[5];
    const float* W_q       = (const float*)d_in[6];
    const float* W_kvg     = (const float*)d_in[7];
    const float* W_res     = (const float*)d_in[8];
    const float* x_u       = (const float*)d_in[9];
    const float* x_v       = (const float*)d_in[10];
    const float* xl_r      = (const float*)d_in[11];
    const float* codebook  = (const float*)d_in[12];
    float* out = (float*)d_out;

    float *xt, *qraw, *kvg, *qu, *qv, *kl, *vv, *gate, *rbd, *scores, *wvg, *csq;
    unsigned long long* zpk;
    cudaGetSymbolAddress((void**)&xt, g_xt);
    cudaGetSymbolAddress((void**)&qraw, g_qraw);
    cudaGetSymbolAddress((void**)&kvg, g_kvg);
    cudaGetSymbolAddress((void**)&qu, g_qu);
    cudaGetSymbolAddress((void**)&qv, g_qvb);
    cudaGetSymbolAddress((void**)&kl, g_kl);
    cudaGetSymbolAddress((void**)&vv, g_vv);
    cudaGetSymbolAddress((void**)&gate, g_gate);
    cudaGetSymbolAddress((void**)&rbd, g_rbd);
    cudaGetSymbolAddress((void**)&scores, g_scores);
    cudaGetSymbolAddress((void**)&wvg, g_wvg);
    cudaGetSymbolAddress((void**)&zpk, g_zpk);
    cudaGetSymbolAddress((void**)&csq, g_csq);

    // 1. LN(input) -> x_t
    ln_rows_kernel<<<NROWS, 256>>>(input, xt);
    // 2. projections
    sgemm_kernel<<<dim3(1024 / 128, 4096 / 128), 256>>>(xt, W_q, qraw, 4096, 1024, 1024);
    sgemm_kernel<<<dim3(3072 / 128, 4096 / 128), 256>>>(xt, W_kvg, kvg, 4096, 3072, 1024);
    // 3. per-head LN, biases, silu
    transform_kernel<<<NROWS * CH, 128>>>(qraw, kvg, x_u, x_v, qu, qv, kl, vv, gate);
    // 4. VQ
    csq_kernel<<<CH * CS, 128>>>(codebook, csq);
    zinit_kernel<<<NBH, 512>>>(zpk);
    battn_kernel<3><<<dim3(4, 4, NBH), 256>>>(kl, xl_k_hat, codebook, xl_r, agg_lower,
                                              csq, zpk, zpk, rbd, rbd);
    // 5. scores
    battn_kernel<0><<<dim3(8, 4, NBH), 256>>>(qv, xl_k_hat, codebook, xl_r, agg_lower,
                                              csq, zpk, zpk, rbd, rbd);
    battn_kernel<1><<<dim3(8, 4, NBH), 256>>>(qu, xl_k_hat, codebook, xl_r, agg_lower,
                                              csq, zpk, zpk, rbd, scores);
    battn_kernel<2><<<dim3(4, 4, NBH), 256>>>(qu, xl_k_hat, codebook, xl_r, agg_lower,
                                              csq, zpk, zpk, rbd, scores);
    // 6. joint softmax
    softmax_kernel<<<NBH * CL, 256>>>(scores);
    // 7. weighted values (fused * gate)
    wv_kernel<<<dim3(1, 4, NBH), 256>>>(scores, xl_v, vv, agg_upper, gate, wvg);
    // 8. output projection
    sgemm_kernel<<<dim3(1024 / 128, 4096 / 128), 256>>>(wvg, W_res, out, 4096, 1024, 1024);
}

// round 2
// speedup vs baseline: 1.0481x; 1.0481x over previous
#include <cuda_runtime.h>
#include <cstdint>

// ---------------------------------------------------------------------------
// Problem constants
// ---------------------------------------------------------------------------
#define CB   8      // batch
#define CL   512    // query length
#define CM   512    // xl memory length
#define CH   8      // heads
#define CDK  128
#define CDV  128
#define CS   512    // codebook size
#define CDM  1024
#define CW   1024   // W_REC = M + L
#define NBH  64     // B*H
#define NROWS 4096  // B*L
#define SCW  1536   // W + S  (joint softmax width)

static __device__ __constant__ const float TAUI = 0.08838834764831845f; // 1/sqrt(128)

// ---------------------------------------------------------------------------
// Scratch (static device allocations; no runtime alloc)
// ---------------------------------------------------------------------------
__device__ float g_xt   [(size_t)NROWS * CDM];        // LN(input)
__device__ float g_qraw [(size_t)NROWS * CDM];        // x_t @ W_q
__device__ float g_kvg  [(size_t)NROWS * 3072];       // x_t @ W_kvg
__device__ float g_qu   [(size_t)NBH * CL * CDK];     // LN(q)+x_u  (B,H,L,DK)
__device__ float g_qvb  [(size_t)NBH * CL * CDK];     // LN(q)+x_v
__device__ float g_kl   [(size_t)NBH * CL * CDK];     // LN(k)
__device__ float g_vv   [(size_t)NBH * CL * CDV];     // v          (B,H,L,DV)
__device__ float g_gate [(size_t)NROWS * CDM];        // silu(g)    (B,L,H*DV)
__device__ float g_rbd  [(size_t)NBH * CL * CW];      // qv @ xl_r^T / TAU
__device__ float g_scores[(size_t)NBH * CL * SCW];    // joint scores / probs
__device__ float g_wvg  [(size_t)NROWS * CDM];        // (wv * g)   (B,L,H*DV)
__device__ unsigned long long g_zpk[NBH * CL];        // packed (d2,idx) argmin
__device__ float g_csq  [CH * CS];                    // |codebook|^2

// ---------------------------------------------------------------------------
// Packed f32x2 helpers (sm_103a)
// ---------------------------------------------------------------------------
__device__ __forceinline__ void ffma2(unsigned long long& acc,
                                      unsigned long long a,
                                      unsigned long long b) {
    asm("fma.rn.f32x2 %0, %1, %2, %0;" : "+l"(acc) : "l"(a), "l"(b));
}
__device__ __forceinline__ unsigned long long packdup(float x) {
    unsigned long long r;
    unsigned u = __float_as_uint(x);
    asm("mov.b64 %0, {%1, %2};" : "=l"(r) : "r"(u), "r"(u));
    return r;
}
__device__ __forceinline__ void unpack2(unsigned long long v, float& lo, float& hi) {
    unsigned a, b;
    asm("mov.b64 {%0, %1}, %2;" : "=r"(a), "=r"(b) : "l"(v));
    lo = __uint_as_float(a);
    hi = __uint_as_float(b);
}

// Shared inner-product over one 16-deep smem tile using packed FFMA2.
// acc2[ip][j]: lane0 = local row 2*ip, lane1 = local row 2*ip+1 (of the 8-row micro tile).
__device__ __forceinline__ void mm_tile(const float (*As)[128], const float (*Bs)[128],
                                        int tr, int tc, unsigned long long acc2[4][8]) {
    #pragma unroll
    for (int k = 0; k < 16; ++k) {
        unsigned long long a2[4];
        #pragma unroll
        for (int ip = 0; ip < 4; ++ip)
            a2[ip] = *(const unsigned long long*)&As[k][tr + 2 * ip];
        float bb[8];
        *(float4*)(bb)     = *(const float4*)&Bs[k][tc];
        *(float4*)(bb + 4) = *(const float4*)&Bs[k][tc + 4];
        unsigned long long b2[8];
        #pragma unroll
        for (int j = 0; j < 8; ++j) b2[j] = packdup(bb[j]);
        #pragma unroll
        for (int ip = 0; ip < 4; ++ip)
            #pragma unroll
            for (int j = 0; j < 8; ++j)
                ffma2(acc2[ip][j], a2[ip], b2[j]);
    }
}

__device__ __forceinline__ void unpack_acc(const unsigned long long acc2[4][8],
                                           float accf[8][8]) {
    #pragma unroll
    for (int ip = 0; ip < 4; ++ip)
        #pragma unroll
        for (int j = 0; j < 8; ++j)
            unpack2(acc2[ip][j], accf[2 * ip][j], accf[2 * ip + 1][j]);
}

// ---------------------------------------------------------------------------
// Block reductions
// ---------------------------------------------------------------------------
__device__ __forceinline__ float block_sum(float v) {
    __shared__ float sb_[8];
    int tid = threadIdx.x;
    int nw  = blockDim.x >> 5;
    #pragma unroll
    for (int o = 16; o; o >>= 1) v += __shfl_down_sync(0xffffffffu, v, o);
    __syncthreads();                       // protect sb_ reuse (WAR)
    if ((tid & 31) == 0) sb_[tid >> 5] = v;
    __syncthreads();
    float r = 0.f;
    for (int i = 0; i < nw; ++i) r += sb_[i];
    return r;
}

// ---------------------------------------------------------------------------
// LayerNorm over DM=1024 (input features). 256 threads, 4 elems/thread.
// ---------------------------------------------------------------------------
__global__ void __launch_bounds__(256) ln_rows_kernel(const float* __restrict__ x,
                                                      float* __restrict__ y) {
    int row = blockIdx.x;
    const float* xr = x + (size_t)row * CDM;
    float*       yr = y + (size_t)row * CDM;
    int tid = threadIdx.x;
    float v[4]; float s = 0.f;
    #pragma unroll
    for (int i = 0; i < 4; ++i) { v[i] = xr[tid + i * 256]; s += v[i]; }
    float mu = block_sum(s) * (1.f / 1024.f);
    float s2 = 0.f;
    #pragma unroll
    for (int i = 0; i < 4; ++i) { v[i] -= mu; s2 += v[i] * v[i]; }
    float rstd = rsqrtf(block_sum(s2) * (1.f / 1024.f) + 1e-6f);
    #pragma unroll
    for (int i = 0; i < 4; ++i) yr[tid + i * 256] = v[i] * rstd;
}

// ---------------------------------------------------------------------------
// Generic SGEMM (FFMA2 + register prefetch): C(MxN) = A(MxK) @ B(KxN)
// ---------------------------------------------------------------------------
__global__ void __launch_bounds__(256, 2) sgemm_kernel(const float* __restrict__ A,
                                                       const float* __restrict__ B,
                                                       float* __restrict__ C,
                                                       int M, int N, int K) {
    __shared__ float As[16][128];
    __shared__ float Bs[16][128];
    int bm = blockIdx.y * 128;
    int bn = blockIdx.x * 128;
    int tid = threadIdx.x;
    int tr = (tid >> 4) << 3;
    int tc = (tid & 15) << 3;

    int ar[2], ac[2], br[2], bc[2];
    float4 va[2], vb[2];
    #pragma unroll
    for (int i = 0; i < 2; ++i) {
        int p = tid * 2 + i;
        ar[i] = p >> 2;        ac[i] = (p & 3) << 2;
        br[i] = p >> 5;        bc[i] = (p & 31) << 2;
        va[i] = *(const float4*)(A + (size_t)(bm + ar[i]) * K + ac[i]);
        vb[i] = *(const float4*)(B + (size_t)br[i] * N + bn + bc[i]);
    }

    unsigned long long acc2[4][8] = {};
    for (int k0 = 0; k0 < K; k0 += 16) {
        #pragma unroll
        for (int i = 0; i < 2; ++i) {
            As[ac[i] + 0][ar[i]] = va[i].x; As[ac[i] + 1][ar[i]] = va[i].y;
            As[ac[i] + 2][ar[i]] = va[i].z; As[ac[i] + 3][ar[i]] = va[i].w;
            *(float4*)&Bs[br[i]][bc[i]] = vb[i];
        }
        __syncthreads();
        if (k0 + 16 < K) {
            #pragma unroll
            for (int i = 0; i < 2; ++i) {
                va[i] = *(const float4*)(A + (size_t)(bm + ar[i]) * K + k0 + 16 + ac[i]);
                vb[i] = *(const float4*)(B + (size_t)(k0 + 16 + br[i]) * N + bn + bc[i]);
            }
        }
        mm_tile(As, Bs, tr, tc, acc2);
        __syncthreads();
    }

    float accf[8][8];
    unpack_acc(acc2, accf);
    #pragma unroll
    for (int i = 0; i < 8; ++i) {
        float* crow = C + (size_t)(bm + tr + i) * N + bn + tc;
        #pragma unroll
        for (int j = 0; j < 8; j += 4) {
            float4 v4 = make_float4(accf[i][j], accf[i][j + 1], accf[i][j + 2], accf[i][j + 3]);
            *(float4*)(crow + j) = v4;
        }
    }
}

// ---------------------------------------------------------------------------
// Per-(b,l,h): LN(q)->qu/qv, LN(k)->kl, copy v, silu(g). 128 threads.
// ---------------------------------------------------------------------------
__global__ void __launch_bounds__(128) transform_kernel(const float* __restrict__ qraw,
                                                        const float* __restrict__ kvg,
                                                        const float* __restrict__ x_u,
                                                        const float* __restrict__ x_v,
                                                        float* __restrict__ qu,
                                                        float* __restrict__ qv,
                                                        float* __restrict__ kl,
                                                        float* __restrict__ vv,
                                                        float* __restrict__ gate) {
    int idx = blockIdx.x;        // (b*L+l)*H + h
    int h  = idx & 7;
    int bl = idx >> 3;
    int b = bl >> 9, l = bl & 511;
    int d = threadIdx.x;

    float q  = qraw[(size_t)bl * CDM + h * CDK + d];
    float mu = block_sum(q) * (1.f / 128.f);
    float qc = q - mu;
    float var = block_sum(qc * qc) * (1.f / 128.f);
    float qn  = qc * rsqrtf(var + 1e-6f);
    size_t o = (((size_t)b * CH + h) * CL + l) * CDK + d;
    qu[o] = qn + x_u[h * CDK + d];
    qv[o] = qn + x_v[h * CDK + d];

    float k   = kvg[(size_t)bl * 3072 + h * CDK + d];
    float kmu = block_sum(k) * (1.f / 128.f);
    float kc  = k - kmu;
    float kvar = block_sum(kc * kc) * (1.f / 128.f);
    kl[o] = kc * rsqrtf(kvar + 1e-6f);

    vv[o] = kvg[(size_t)bl * 3072 + 1024 + h * CDK + d];

    float gg = kvg[(size_t)bl * 3072 + 2048 + h * CDK + d];
    gate[(size_t)bl * CDM + h * CDK + d] = gg / (1.f + __expf(-gg));
}

// ---------------------------------------------------------------------------
// |codebook row|^2
// ---------------------------------------------------------------------------
__global__ void __launch_bounds__(128) csq_kernel(const float* __restrict__ cb,
                                                  float* __restrict__ csq) {
    int row = blockIdx.x;  // H*S
    float v = cb[(size_t)row * CDK + threadIdx.x];
    v = block_sum(v * v);
    if (threadIdx.x == 0) csq[row] = v;
}

__global__ void zinit_kernel(unsigned long long* zpk) {
    zpk[blockIdx.x * 512 + threadIdx.x] = ~0ull;
}

// ---------------------------------------------------------------------------
// Batched attention GEMM: C = A(bh) @ Brows^T, K=128, 128x128 tile.
// Modes: 0=BD (xl_r), 1=RECENT (xl_k_hat | codebook[z], +rbd shift +mask),
//        2=CACHE (codebook, +log bias), 3=VQ (argmin epilogue).
// ---------------------------------------------------------------------------
template <int MODE>
__global__ void __launch_bounds__(256, 2) battn_kernel(
    const float* __restrict__ Abase,
    const float* __restrict__ xl_k_hat,
    const float* __restrict__ codebook,
    const float* __restrict__ xl_r,
    const float* __restrict__ agg_lower,
    const float* __restrict__ csq,
    const unsigned long long* __restrict__ zpk_in,
    unsigned long long* zpk_out,
    const float* __restrict__ rbd_in,
    float* __restrict__ outp) {
    int bh = blockIdx.z;
    int h  = bh & 7;
    int bm = blockIdx.y * 128;
    int bn = blockIdx.x * 128;
    const float* A = Abase + (size_t)bh * CL * CDK;

    __shared__ float As[16][128];
    __shared__ float Bs[16][128];
    int tid = threadIdx.x;
    int tr = (tid >> 4) << 3;
    int tc = (tid & 15) << 3;

    // Resolve row pointers once (gather is k-invariant)
    int ar[2], ac[2];
    const float* bptr[2];
    float4 va[2], vb[2];
    #pragma unroll
    for (int i = 0; i < 2; ++i) {
        int p = tid * 2 + i;
        ar[i] = p >> 2;
        ac[i] = (p & 3) << 2;
        int n = bn + ar[i];
        if constexpr (MODE == 0) {
            bptr[i] = xl_r + ((size_t)h * CW + n) * CDK;
        } else if constexpr (MODE == 1) {
            if (n < CM) bptr[i] = xl_k_hat + ((size_t)bh * CM + n) * CDK;
            else {
                unsigned zi = (unsigned)(zpk_in[(size_t)bh * CL + (n - CM)] & 0xffffffffull);
                bptr[i] = codebook + ((size_t)h * CS + zi) * CDK;
            }
        } else {
            bptr[i] = codebook + ((size_t)h * CS + n) * CDK;
        }
        va[i] = *(const float4*)(A + (size_t)(bm + ar[i]) * CDK + ac[i]);
        vb[i] = *(const float4*)(bptr[i] + ac[i]);
    }

    unsigned long long acc2[4][8] = {};
    #pragma unroll 1
    for (int k0 = 0; k0 < 128; k0 += 16) {
        #pragma unroll
        for (int i = 0; i < 2; ++i) {
            As[ac[i] + 0][ar[i]] = va[i].x; As[ac[i] + 1][ar[i]] = va[i].y;
            As[ac[i] + 2][ar[i]] = va[i].z; As[ac[i] + 3][ar[i]] = va[i].w;
            Bs[ac[i] + 0][ar[i]] = vb[i].x; Bs[ac[i] + 1][ar[i]] = vb[i].y;
            Bs[ac[i] + 2][ar[i]] = vb[i].z; Bs[ac[i] + 3][ar[i]] = vb[i].w;
        }
        __syncthreads();
        if (k0 + 16 < 128) {
            #pragma unroll
            for (int i = 0; i < 2; ++i) {
                va[i] = *(const float4*)(A + (size_t)(bm + ar[i]) * CDK + k0 + 16 + ac[i]);
                vb[i] = *(const float4*)(bptr[i] + k0 + 16 + ac[i]);
            }
        }
        mm_tile(As, Bs, tr, tc, acc2);
        __syncthreads();
    }

    float accf[8][8];
    unpack_acc(acc2, accf);

    if constexpr (MODE == 0) {           // Rbd = qv @ xl_r^T / TAU
        #pragma unroll
        for (int i = 0; i < 8; ++i) {
            int l = bm + tr + i;
            float* orow = outp + ((size_t)bh * CL + l) * CW + bn + tc;
            #pragma unroll
            for (int j = 0; j < 8; j += 4) {
                float4 v4 = make_float4(accf[i][j] * TAUI, accf[i][j + 1] * TAUI,
                                        accf[i][j + 2] * TAUI, accf[i][j + 3] * TAUI);
                *(float4*)(orow + j) = v4;
            }
        }
    } else if constexpr (MODE == 1) {    // recent scores (+rel_shift bias, +mask)
        #pragma unroll
        for (int i = 0; i < 8; ++i) {
            int l = bm + tr + i;
            const float* rrow = rbd_in + ((size_t)bh * CL + l) * CW;
            float* orow = outp + ((size_t)bh * CL + l) * SCW;
            #pragma unroll
            for (int j = 0; j < 8; ++j) {
                int w = bn + tc + j;
                float sc = -1e30f;
                if (w <= l + CM) sc = accf[i][j] * TAUI + rrow[w + (CL - 1) - l];
                orow[w] = sc;
            }
        }
    } else if constexpr (MODE == 2) {    // cache scores (+log bias)
        #pragma unroll
        for (int i = 0; i < 8; ++i) {
            int l = bm + tr + i;
            float* orow = outp + ((size_t)bh * CL + l) * SCW + CW;
            #pragma unroll
            for (int j = 0; j < 8; ++j) {
                int s = bn + tc + j;
                float al = agg_lower[(size_t)bh * CS + s];
                float bias = (al > 0.f) ? logf(fmaxf(al, 1e-30f)) : -1e30f;
                orow[s] = accf[i][j] * TAUI + bias;
            }
        }
    } else {                              // VQ argmin over codes
        __shared__ unsigned long long rkey[128][17];
        #pragma unroll
        for (int i = 0; i < 8; ++i) {
            unsigned long long bk = ~0ull;
            #pragma unroll
            for (int j = 0; j < 8; ++j) {
                int s = bn + tc + j;
                float val = csq[h * CS + s] - 2.f * accf[i][j];
                unsigned u = __float_as_uint(val);
                u = (u & 0x80000000u) ? ~u : (u | 0x80000000u);
                unsigned long long key = ((unsigned long long)u << 32) | (unsigned)s;
                if (key < bk) bk = key;
            }
            rkey[tr + i][tid & 15] = bk;
        }
        __syncthreads();
        if (tid < 128) {
            unsigned long long bk = rkey[tid][0];
            #pragma unroll
            for (int t = 1; t < 16; ++t) {
                unsigned long long k2 = rkey[tid][t];
                if (k2 < bk) bk = k2;
            }
            atomicMin(&zpk_out[(size_t)bh * CL + bm + tid], bk);
        }
    }
}

// ---------------------------------------------------------------------------
// Joint softmax over 1536 keys; writes normalized probabilities in place.
// ---------------------------------------------------------------------------
__global__ void __launch_bounds__(256) softmax_kernel(float* __restrict__ scores) {
    float* row = scores + (size_t)blockIdx.x * SCW;
    int tid = threadIdx.x;
    __shared__ float sb[8];
    float v[6];
    float m = -3.4e38f;
    #pragma unroll
    for (int i = 0; i < 6; ++i) { v[i] = row[tid + i * 256]; m = fmaxf(m, v[i]); }
    #pragma unroll
    for (int o = 16; o; o >>= 1) m = fmaxf(m, __shfl_down_sync(0xffffffffu, m, o));
    if ((tid & 31) == 0) sb[tid >> 5] = m;
    __syncthreads();
    m = sb[0];
    #pragma unroll
    for (int i = 1; i < 8; ++i) m = fmaxf(m, sb[i]);
    __syncthreads();
    float s = 0.f;
    #pragma unroll
    for (int i = 0; i < 6; ++i) { v[i] = __expf(v[i] - m); s += v[i]; }
    #pragma unroll
    for (int o = 16; o; o >>= 1) s += __shfl_down_sync(0xffffffffu, s, o);
    if ((tid & 31) == 0) sb[tid >> 5] = s;
    __syncthreads();
    float tot = sb[0];
    #pragma unroll
    for (int i = 1; i < 8; ++i) tot += sb[i];
    float inv = 1.f / tot;
    #pragma unroll
    for (int i = 0; i < 6; ++i) row[tid + i * 256] = v[i] * inv;
}

// ---------------------------------------------------------------------------
// wv = P(512x1536) @ Vgather(1536x128), fused *gate, write (B,L,H*DV)
// ---------------------------------------------------------------------------
__global__ void __launch_bounds__(256, 2) wv_kernel(const float* __restrict__ P,
                                                    const float* __restrict__ xl_v,
                                                    const float* __restrict__ vcur,
                                                    const float* __restrict__ aggu,
                                                    const float* __restrict__ gate,
                                                    float* __restrict__ wvg) {
    int bh = blockIdx.z;
    int b = bh >> 3, h = bh & 7;
    int bm = blockIdx.y * 128;
    const float* A = P + (size_t)bh * CL * SCW;
    __shared__ float As[16][128];
    __shared__ float Bs[16][128];
    int tid = threadIdx.x;
    int tr = (tid >> 4) << 3;
    int tc = (tid & 15) << 3;

    int ar[2], ac[2], br[2], bc[2];
    #pragma unroll
    for (int i = 0; i < 2; ++i) {
        int p = tid * 2 + i;
        ar[i] = p >> 2;  ac[i] = (p & 3) << 2;
        br[i] = p >> 5;  bc[i] = (p & 31) << 2;
    }
    auto bsrc = [&](int j) -> const float* {
        if (j < CM)       return xl_v + ((size_t)bh * CM + j) * CDV;
        else if (j < CW)  return vcur + ((size_t)bh * CL + (j - CM)) * CDV;
        else              return aggu + ((size_t)bh * CS + (j - CW)) * CDV;
    };
    float4 va[2], vb[2];
    #pragma unroll
    for (int i = 0; i < 2; ++i) {
        va[i] = *(const float4*)(A + (size_t)(bm + ar[i]) * SCW + ac[i]);
        vb[i] = *(const float4*)(bsrc(br[i]) + bc[i]);
    }

    unsigned long long acc2[4][8] = {};
    #pragma unroll 1
    for (int k0 = 0; k0 < SCW; k0 += 16) {
        #pragma unroll
        for (int i = 0; i < 2; ++i) {
            As[ac[i] + 0][ar[i]] = va[i].x; As[ac[i] + 1][ar[i]] = va[i].y;
            As[ac[i] + 2][ar[i]] = va[i].z; As[ac[i] + 3][ar[i]] = va[i].w;
            *(float4*)&Bs[br[i]][bc[i]] = vb[i];
        }
        __syncthreads();
        if (k0 + 16 < SCW) {
            #pragma unroll
            for (int i = 0; i < 2; ++i) {
                va[i] = *(const float4*)(A + (size_t)(bm + ar[i]) * SCW + k0 + 16 + ac[i]);
                vb[i] = *(const float4*)(bsrc(k0 + 16 + br[i]) + bc[i]);
            }
        }
        mm_tile(As, Bs, tr, tc, acc2);
        __syncthreads();
    }

    float accf[8][8];
    unpack_acc(acc2, accf);
    #pragma unroll
    for (int i = 0; i < 8; ++i) {
        int l = bm + tr + i;
        size_t base = ((size_t)b * CL + l) * CDM + h * CDV + tc;
        #pragma unroll
        for (int j = 0; j < 8; ++j)
            wvg[base + j] = accf[i][j] * gate[base + j];
    }
}

// ---------------------------------------------------------------------------
// Host launcher (graph-capturable: kernel launches only)
// ---------------------------------------------------------------------------
extern "C" void kernel_launch(void* const* d_in, const int* in_sizes, int n_in,
                              void* d_out, int out_size) {
    const float* input     = (const float*)d_in[0];
    const float* xl_k_hat  = (const float*)d_in[2];
    const float* xl_v      = (const float*)d_in[3];
    const float* agg_upper = (const float*)d_in[4];
    const float* agg_lower = (const float*)d_in[5];
    const float* W_q       = (const float*)d_in[6];
    const float* W_kvg     = (const float*)d_in[7];
    const float* W_res     = (const float*)d_in[8];
    const float* x_u       = (const float*)d_in[9];
    const float* x_v       = (const float*)d_in[10];
    const float* xl_r      = (const float*)d_in[11];
    const float* codebook  = (const float*)d_in[12];
    float* out = (float*)d_out;

    float *xt, *qraw, *kvg, *qu, *qv, *kl, *vv, *gate, *rbd, *scores, *wvg, *csq;
    unsigned long long* zpk;
    cudaGetSymbolAddress((void**)&xt, g_xt);
    cudaGetSymbolAddress((void**)&qraw, g_qraw);
    cudaGetSymbolAddress((void**)&kvg, g_kvg);
    cudaGetSymbolAddress((void**)&qu, g_qu);
    cudaGetSymbolAddress((void**)&qv, g_qvb);
    cudaGetSymbolAddress((void**)&kl, g_kl);
    cudaGetSymbolAddress((void**)&vv, g_vv);
    cudaGetSymbolAddress((void**)&gate, g_gate);
    cudaGetSymbolAddress((void**)&rbd, g_rbd);
    cudaGetSymbolAddress((void**)&scores, g_scores);
    cudaGetSymbolAddress((void**)&wvg, g_wvg);
    cudaGetSymbolAddress((void**)&zpk, g_zpk);
    cudaGetSymbolAddress((void**)&csq, g_csq);

    // 1. LN(input) -> x_t
    ln_rows_kernel<<<NROWS, 256>>>(input, xt);
    // 2. projections
    sgemm_kernel<<<dim3(1024 / 128, 4096 / 128), 256>>>(xt, W_q, qraw, 4096, 1024, 1024);
    sgemm_kernel<<<dim3(3072 / 128, 4096 / 128), 256>>>(xt, W_kvg, kvg, 4096, 3072, 1024);
    // 3. per-head LN, biases, silu
    transform_kernel<<<NROWS * CH, 128>>>(qraw, kvg, x_u, x_v, qu, qv, kl, vv, gate);
    // 4. VQ
    csq_kernel<<<CH * CS, 128>>>(codebook, csq);
    zinit_kernel<<<NBH, 512>>>(zpk);
    battn_kernel<3><<<dim3(4, 4, NBH), 256>>>(kl, xl_k_hat, codebook, xl_r, agg_lower,
                                              csq, zpk, zpk, rbd, rbd);
    // 5. scores
    battn_kernel<0><<<dim3(8, 4, NBH), 256>>>(qv, xl_k_hat, codebook, xl_r, agg_lower,
                                              csq, zpk, zpk, rbd, rbd);
    battn_kernel<1><<<dim3(8, 4, NBH), 256>>>(qu, xl_k_hat, codebook, xl_r, agg_lower,
                                              csq, zpk, zpk, rbd, scores);
    battn_kernel<2><<<dim3(4, 4, NBH), 256>>>(qu, xl_k_hat, codebook, xl_r, agg_lower,
                                              csq, zpk, zpk, rbd, scores);
    // 6. joint softmax
    softmax_kernel<<<NBH * CL, 256>>>(scores);
    // 7. weighted values (fused * gate)
    wv_kernel<<<dim3(1, 4, NBH), 256>>>(scores, xl_v, vv, agg_upper, gate, wvg);
    // 8. output projection
    sgemm_kernel<<<dim3(1024 / 128, 4096 / 128), 256>>>(wvg, W_res, out, 4096, 1024, 1024);
}

// round 3
// speedup vs baseline: 1.6397x; 1.5645x over previous
#include <cuda_runtime.h>
#include <cuda_bf16.h>
#include <cstdint>

// ---------------------------------------------------------------------------
// Problem constants
// ---------------------------------------------------------------------------
#define CB   8
#define CL   512
#define CM   512
#define CH   8
#define CDK  128
#define CDV  128
#define CS   512
#define CDM  1024
#define CW   1024   // W_REC
#define NBH  64
#define NROWS 4096
#define SCW  1536   // W + S

static __device__ __constant__ const float TAUI = 0.08838834764831845f; // 1/sqrt(128)

// ---------------------------------------------------------------------------
// Scratch
// ---------------------------------------------------------------------------
__device__ float g_xt    [(size_t)NROWS * CDM];
__device__ float g_qraw  [(size_t)NROWS * CDM];
__device__ float g_kvg   [(size_t)NROWS * 3072];
__device__ float g_qu    [(size_t)NBH * CL * CDK];
__device__ float g_qvb   [(size_t)NBH * CL * CDK];
__device__ float g_kl    [(size_t)NBH * CL * CDK];
__device__ float g_vv    [(size_t)NBH * CL * CDV];
__device__ float g_gate  [(size_t)NROWS * CDM];
__device__ float g_rbd   [(size_t)NBH * CL * CW];
__device__ float g_scores[(size_t)NBH * CL * SCW];
__device__ float g_wvg   [(size_t)NROWS * CDM];
__device__ unsigned long long g_zpk[NBH * CL];
__device__ float g_csq   [CH * CS];
__device__ float g_wqt   [(size_t)1024 * 1024];   // W_q^T   [N][K]
__device__ float g_wkvgt [(size_t)3072 * 1024];   // W_kvg^T [N][K]
__device__ float g_wrest [(size_t)1024 * 1024];   // W_res^T [N][K]
__device__ float g_vt    [(size_t)NBH * CDV * SCW]; // V gather transposed [bh][v][w]

// ---------------------------------------------------------------------------
// mma / ldmatrix primitives
// ---------------------------------------------------------------------------
__device__ __forceinline__ uint32_t cvta_s(const void* p) {
    return (uint32_t)__cvta_generic_to_shared(p);
}
__device__ __forceinline__ void ldmx4(uint32_t addr, uint32_t& r0, uint32_t& r1,
                                      uint32_t& r2, uint32_t& r3) {
    asm volatile("ldmatrix.sync.aligned.m8n8.x4.shared.b16 {%0,%1,%2,%3}, [%4];"
                 : "=r"(r0), "=r"(r1), "=r"(r2), "=r"(r3) : "r"(addr));
}
__device__ __forceinline__ void mma16816(float c[4], const uint32_t a[4], const uint32_t b[2]) {
    asm volatile(
        "mma.sync.aligned.m16n8k16.row.col.f32.bf16.bf16.f32 "
        "{%0,%1,%2,%3}, {%4,%5,%6,%7}, {%8,%9}, {%0,%1,%2,%3};"
        : "+f"(c[0]), "+f"(c[1]), "+f"(c[2]), "+f"(c[3])
        : "r"(a[0]), "r"(a[1]), "r"(a[2]), "r"(a[3]), "r"(b[0]), "r"(b[1]));
}

// fp32 float4 -> bf16 hi + bf16 lo (residual) written to smem (8B each)
__device__ __forceinline__ void split4(float4 v, __nv_bfloat16* hp, __nv_bfloat16* lp) {
    __nv_bfloat162 h0 = __floats2bfloat162_rn(v.x, v.y);
    __nv_bfloat162 h1 = __floats2bfloat162_rn(v.z, v.w);
    float2 f0 = __bfloat1622float2(h0);
    float2 f1 = __bfloat1622float2(h1);
    __nv_bfloat162 l0 = __floats2bfloat162_rn(v.x - f0.x, v.y - f0.y);
    __nv_bfloat162 l1 = __floats2bfloat162_rn(v.z - f1.x, v.w - f1.y);
    uint2 hv, lv;
    hv.x = *(uint32_t*)&h0; hv.y = *(uint32_t*)&h1;
    lv.x = *(uint32_t*)&l0; lv.y = *(uint32_t*)&l1;
    *(uint2*)hp = hv;
    *(uint2*)lp = lv;
}

// ---------------------------------------------------------------------------
// Block reductions (elementwise kernels)
// ---------------------------------------------------------------------------
__device__ __forceinline__ float block_sum(float v) {
    __shared__ float sb_[8];
    int tid = threadIdx.x;
    int nw  = blockDim.x >> 5;
    #pragma unroll
    for (int o = 16; o; o >>= 1) v += __shfl_down_sync(0xffffffffu, v, o);
    __syncthreads();
    if ((tid & 31) == 0) sb_[tid >> 5] = v;
    __syncthreads();
    float r = 0.f;
    for (int i = 0; i < nw; ++i) r += sb_[i];
    return r;
}

// ---------------------------------------------------------------------------
// LayerNorm over DM=1024
// ---------------------------------------------------------------------------
__global__ void __launch_bounds__(256) ln_rows_kernel(const float* __restrict__ x,
                                                      float* __restrict__ y) {
    int row = blockIdx.x;
    const float* xr = x + (size_t)row * CDM;
    float*       yr = y + (size_t)row * CDM;
    int tid = threadIdx.x;
    float v[4]; float s = 0.f;
    #pragma unroll
    for (int i = 0; i < 4; ++i) { v[i] = xr[tid + i * 256]; s += v[i]; }
    float mu = block_sum(s) * (1.f / 1024.f);
    float s2 = 0.f;
    #pragma unroll
    for (int i = 0; i < 4; ++i) { v[i] -= mu; s2 += v[i] * v[i]; }
    float rstd = rsqrtf(block_sum(s2) * (1.f / 1024.f) + 1e-6f);
    #pragma unroll
    for (int i = 0; i < 4; ++i) yr[tid + i * 256] = v[i] * rstd;
}

// ---------------------------------------------------------------------------
// Tiled transpose: dst[c][r] = src[r][c]   (R, C multiples of 32)
// ---------------------------------------------------------------------------
__global__ void __launch_bounds__(256) transpose_kernel(const float* __restrict__ src,
                                                        float* __restrict__ dst,
                                                        int R, int C) {
    __shared__ float tile[32][33];
    int c0 = blockIdx.x * 32, r0 = blockIdx.y * 32;
    int x = threadIdx.x & 31, y = (threadIdx.x >> 5) * 4;
    #pragma unroll
    for (int i = 0; i < 4; ++i)
        tile[y + i][x] = src[(size_t)(r0 + y + i) * C + c0 + x];
    __syncthreads();
    #pragma unroll
    for (int i = 0; i < 4; ++i)
        dst[(size_t)(c0 + y + i) * R + r0 + x] = tile[x][y + i];
}

// ---------------------------------------------------------------------------
// Build Vt[bh][v][w] from gathered V rows (xl_v | vv | agg_upper)
// ---------------------------------------------------------------------------
__global__ void __launch_bounds__(256) vt_kernel(const float* __restrict__ xl_v,
                                                 const float* __restrict__ vv,
                                                 const float* __restrict__ aggu,
                                                 float* __restrict__ vt) {
    __shared__ float tile[32][33];
    int bh = blockIdx.z;
    int w0 = blockIdx.x * 32, v0 = blockIdx.y * 32;
    int x = threadIdx.x & 31, y = (threadIdx.x >> 5) * 4;
    #pragma unroll
    for (int i = 0; i < 4; ++i) {
        int w = w0 + y + i;
        const float* srcrow;
        if (w < CM)      srcrow = xl_v + ((size_t)bh * CM + w) * CDV;
        else if (w < CW) srcrow = vv   + ((size_t)bh * CL + (w - CM)) * CDV;
        else             srcrow = aggu + ((size_t)bh * CS + (w - CW)) * CDV;
        tile[y + i][x] = srcrow[v0 + x];
    }
    __syncthreads();
    #pragma unroll
    for (int i = 0; i < 4; ++i)
        vt[((size_t)bh * CDV + v0 + y + i) * SCW + w0 + x] = tile[x][y + i];
}

// ---------------------------------------------------------------------------
// Per-(b,l,h): LN(q)->qu/qv, LN(k)->kl, copy v, silu(g)
// ---------------------------------------------------------------------------
__global__ void __launch_bounds__(128) transform_kernel(const float* __restrict__ qraw,
                                                        const float* __restrict__ kvg,
                                                        const float* __restrict__ x_u,
                                                        const float* __restrict__ x_v,
                                                        float* __restrict__ qu,
                                                        float* __restrict__ qv,
                                                        float* __restrict__ kl,
                                                        float* __restrict__ vv,
                                                        float* __restrict__ gate) {
    int idx = blockIdx.x;
    int h  = idx & 7;
    int bl = idx >> 3;
    int b = bl >> 9, l = bl & 511;
    int d = threadIdx.x;

    float q  = qraw[(size_t)bl * CDM + h * CDK + d];
    float mu = block_sum(q) * (1.f / 128.f);
    float qc = q - mu;
    float var = block_sum(qc * qc) * (1.f / 128.f);
    float qn  = qc * rsqrtf(var + 1e-6f);
    size_t o = (((size_t)b * CH + h) * CL + l) * CDK + d;
    qu[o] = qn + x_u[h * CDK + d];
    qv[o] = qn + x_v[h * CDK + d];

    float k   = kvg[(size_t)bl * 3072 + h * CDK + d];
    float kmu = block_sum(k) * (1.f / 128.f);
    float kc  = k - kmu;
    float kvar = block_sum(kc * kc) * (1.f / 128.f);
    kl[o] = kc * rsqrtf(kvar + 1e-6f);

    vv[o] = kvg[(size_t)bl * 3072 + 1024 + h * CDK + d];

    float gg = kvg[(size_t)bl * 3072 + 2048 + h * CDK + d];
    gate[(size_t)bl * CDM + h * CDK + d] = gg / (1.f + __expf(-gg));
}

__global__ void __launch_bounds__(128) csq_kernel(const float* __restrict__ cb,
                                                  float* __restrict__ csq) {
    int row = blockIdx.x;
    float v = cb[(size_t)row * CDK + threadIdx.x];
    v = block_sum(v * v);
    if (threadIdx.x == 0) csq[row] = v;
}

__global__ void zinit_kernel(unsigned long long* zpk) {
    zpk[blockIdx.x * 512 + threadIdx.x] = ~0ull;
}

// ---------------------------------------------------------------------------
// Universal NT tensor-core GEMM (bf16x3): C[128x128 tile] = A[M,K] x B[N,K]^T
// MODE: 0=BD, 1=REC, 2=CACHE, 3=VQ, 4=PROJ, 5=WV
// ---------------------------------------------------------------------------
template <int MODE>
__global__ void __launch_bounds__(256) mma_gemm_kernel(
    const float* __restrict__ Abase,
    const float* __restrict__ Bbase,
    const float* __restrict__ xl_k_hat,
    const float* __restrict__ codebook,
    const float* __restrict__ agg_lower,
    const float* __restrict__ csq,
    const unsigned long long* __restrict__ zpk_in,
    unsigned long long* zpk_out,
    const float* __restrict__ rbd_in,
    const float* __restrict__ gate,
    float* __restrict__ outp,
    int N, int K, int lda) {

    __shared__ __nv_bfloat16 As[2][128][40];
    __shared__ __nv_bfloat16 Bs[2][128][40];

    int tid  = threadIdx.x;
    int lane = tid & 31, warp = tid >> 5;
    int wm = warp >> 2, wn = warp & 3;
    int bm = blockIdx.y * 128;
    int bn = blockIdx.x * 128;
    int bh = blockIdx.z;
    int h  = bh & 7;

    // REC: fully-masked tile -> fill and exit
    if (MODE == 1 && bn >= bm + CM + 128) {
        for (int i = tid; i < 128 * 128; i += 256) {
            int r = i >> 7, c = i & 127;
            outp[((size_t)bh * CL + bm + r) * SCW + bn + c] = -1e30f;
        }
        return;
    }

    const float* A;
    if (MODE == 4)      A = Abase;
    else if (MODE == 5) A = Abase + (size_t)bh * CL * SCW;
    else                A = Abase + (size_t)bh * CL * CDK;

    // ---- staging assignment: thread -> (row = tid>>1, k-offset = (tid&1)*16)
    int srow = tid >> 1;
    int skc  = (tid & 1) * 16;
    const float* arow = A + (size_t)(bm + srow) * lda + skc;
    const float* brow;
    {
        int n = bn + srow;
        if (MODE == 0)      brow = Bbase + ((size_t)h * CW + n) * CDK;
        else if (MODE == 1) {
            if (n < CM) brow = xl_k_hat + ((size_t)bh * CM + n) * CDK;
            else {
                unsigned zi = (unsigned)(zpk_in[(size_t)bh * CL + (n - CM)] & 0xffffffffull);
                brow = codebook + ((size_t)h * CS + zi) * CDK;
            }
        }
        else if (MODE == 2 || MODE == 3) brow = codebook + ((size_t)h * CS + n) * CDK;
        else if (MODE == 4) brow = Bbase + (size_t)n * K;
        else                brow = Bbase + ((size_t)bh * CDV + n) * SCW;
        brow += skc;
    }

    float4 va[4], vb[4];
    #pragma unroll
    for (int i = 0; i < 4; ++i) {
        va[i] = *(const float4*)(arow + 4 * i);
        vb[i] = *(const float4*)(brow + 4 * i);
    }

    // ---- fragment smem offsets (elements)
    uint32_t as_h = cvta_s(&As[0][0][0]);
    uint32_t as_l = cvta_s(&As[1][0][0]);
    uint32_t bs_h = cvta_s(&Bs[0][0][0]);
    uint32_t bs_l = cvta_s(&Bs[1][0][0]);
    int a_off = (wm * 64 + (lane & 15)) * 40 + ((lane >> 4) << 3);
    int b_off = (wn * 32 + ((lane >> 4) << 3) + (lane & 7)) * 40 + (((lane >> 3) & 1) << 3);

    float acc[4][4][4] = {};

    #pragma unroll 1
    for (int k0 = 0; k0 < K; k0 += 32) {
        #pragma unroll
        for (int i = 0; i < 4; ++i) {
            split4(va[i], &As[0][srow][skc + 4 * i], &As[1][srow][skc + 4 * i]);
            split4(vb[i], &Bs[0][srow][skc + 4 * i], &Bs[1][srow][skc + 4 * i]);
        }
        __syncthreads();
        if (k0 + 32 < K) {
            #pragma unroll
            for (int i = 0; i < 4; ++i) {
                va[i] = *(const float4*)(arow + k0 + 32 + 4 * i);
                vb[i] = *(const float4*)(brow + k0 + 32 + 4 * i);
            }
        }
        #pragma unroll
        for (int kk = 0; kk < 32; kk += 16) {
            uint32_t ah[4][4], al[4][4], bh2[4][2], bl2[4][2];
            #pragma unroll
            for (int t = 0; t < 4; ++t) {
                ldmx4(as_h + (uint32_t)(a_off + t * 640 + kk) * 2,
                      ah[t][0], ah[t][1], ah[t][2], ah[t][3]);
                ldmx4(as_l + (uint32_t)(a_off + t * 640 + kk) * 2,
                      al[t][0], al[t][1], al[t][2], al[t][3]);
            }
            #pragma unroll
            for (int u2 = 0; u2 < 2; ++u2) {
                uint32_t r0, r1, r2, r3;
                ldmx4(bs_h + (uint32_t)(b_off + u2 * 640 + kk) * 2, r0, r1, r2, r3);
                bh2[2 * u2][0] = r0; bh2[2 * u2][1] = r1;
                bh2[2 * u2 + 1][0] = r2; bh2[2 * u2 + 1][1] = r3;
                ldmx4(bs_l + (uint32_t)(b_off + u2 * 640 + kk) * 2, r0, r1, r2, r3);
                bl2[2 * u2][0] = r0; bl2[2 * u2][1] = r1;
                bl2[2 * u2 + 1][0] = r2; bl2[2 * u2 + 1][1] = r3;
            }
            #pragma unroll
            for (int t = 0; t < 4; ++t)
                #pragma unroll
                for (int u = 0; u < 4; ++u) {
                    mma16816(acc[t][u], ah[t], bh2[u]);
                    mma16816(acc[t][u], ah[t], bl2[u]);
                    mma16816(acc[t][u], al[t], bh2[u]);
                }
        }
        __syncthreads();
    }

    // ---- epilogues ------------------------------------------------------
    int g  = lane >> 2;
    int qd = lane & 3;

    if constexpr (MODE == 4) {                       // plain C write
        #pragma unroll
        for (int t = 0; t < 4; ++t) {
            int r = bm + wm * 64 + t * 16 + g;
            #pragma unroll
            for (int u = 0; u < 4; ++u) {
                int c = bn + wn * 32 + u * 8 + qd * 2;
                *(float2*)(outp + (size_t)r * N + c) =
                    make_float2(acc[t][u][0], acc[t][u][1]);
                *(float2*)(outp + (size_t)(r + 8) * N + c) =
                    make_float2(acc[t][u][2], acc[t][u][3]);
            }
        }
    } else if constexpr (MODE == 0) {                // Rbd write (scaled)
        #pragma unroll
        for (int t = 0; t < 4; ++t) {
            int l = bm + wm * 64 + t * 16 + g;
            #pragma unroll
            for (int u = 0; u < 4; ++u) {
                int c = bn + wn * 32 + u * 8 + qd * 2;
                *(float2*)(outp + ((size_t)bh * CL + l) * CW + c) =
                    make_float2(acc[t][u][0] * TAUI, acc[t][u][1] * TAUI);
                *(float2*)(outp + ((size_t)bh * CL + l + 8) * CW + c) =
                    make_float2(acc[t][u][2] * TAUI, acc[t][u][3] * TAUI);
            }
        }
    } else if constexpr (MODE == 1) {                // recent scores
        #pragma unroll
        for (int t = 0; t < 4; ++t) {
            int l0 = bm + wm * 64 + t * 16 + g;
            int l1 = l0 + 8;
            const float* rr0 = rbd_in + ((size_t)bh * CL + l0) * CW + (CL - 1) - l0;
            const float* rr1 = rbd_in + ((size_t)bh * CL + l1) * CW + (CL - 1) - l1;
            #pragma unroll
            for (int u = 0; u < 4; ++u) {
                int w = bn + wn * 32 + u * 8 + qd * 2;
                float2 o0, o1;
                o0.x = (w     <= l0 + CM) ? acc[t][u][0] * TAUI + rr0[w]     : -1e30f;
                o0.y = (w + 1 <= l0 + CM) ? acc[t][u][1] * TAUI + rr0[w + 1] : -1e30f;
                o1.x = (w     <= l1 + CM) ? acc[t][u][2] * TAUI + rr1[w]     : -1e30f;
                o1.y = (w + 1 <= l1 + CM) ? acc[t][u][3] * TAUI + rr1[w + 1] : -1e30f;
                *(float2*)(outp + ((size_t)bh * CL + l0) * SCW + w) = o0;
                *(float2*)(outp + ((size_t)bh * CL + l1) * SCW + w) = o1;
            }
        }
    } else if constexpr (MODE == 2) {                // cache scores
        #pragma unroll
        for (int t = 0; t < 4; ++t) {
            int l0 = bm + wm * 64 + t * 16 + g;
            #pragma unroll
            for (int u = 0; u < 4; ++u) {
                int s = bn + wn * 32 + u * 8 + qd * 2;
                float a0 = agg_lower[(size_t)bh * CS + s];
                float a1 = agg_lower[(size_t)bh * CS + s + 1];
                float b0 = (a0 > 0.f) ? logf(fmaxf(a0, 1e-30f)) : -1e30f;
                float b1 = (a1 > 0.f) ? logf(fmaxf(a1, 1e-30f)) : -1e30f;
                *(float2*)(outp + ((size_t)bh * CL + l0) * SCW + CW + s) =
                    make_float2(acc[t][u][0] * TAUI + b0, acc[t][u][1] * TAUI + b1);
                *(float2*)(outp + ((size_t)bh * CL + l0 + 8) * SCW + CW + s) =
                    make_float2(acc[t][u][2] * TAUI + b0, acc[t][u][3] * TAUI + b1);
            }
        }
    } else if constexpr (MODE == 3) {                // VQ argmin
        __shared__ unsigned long long zmin[128];
        if (tid < 128) zmin[tid] = ~0ull;
        __syncthreads();
        #pragma unroll
        for (int t = 0; t < 4; ++t) {
            unsigned long long b0 = ~0ull, b1 = ~0ull;
            #pragma unroll
            for (int u = 0; u < 4; ++u) {
                #pragma unroll
                for (int p = 0; p < 2; ++p) {
                    int s = bn + wn * 32 + u * 8 + qd * 2 + p;
                    float cs = csq[h * CS + s];
                    {
                        float val = cs - 2.f * acc[t][u][p];
                        unsigned uu = __float_as_uint(val);
                        uu = (uu & 0x80000000u) ? ~uu : (uu | 0x80000000u);
                        unsigned long long key = ((unsigned long long)uu << 32) | (unsigned)s;
                        if (key < b0) b0 = key;
                    }
                    {
                        float val = cs - 2.f * acc[t][u][2 + p];
                        unsigned uu = __float_as_uint(val);
                        uu = (uu & 0x80000000u) ? ~uu : (uu | 0x80000000u);
                        unsigned long long key = ((unsigned long long)uu << 32) | (unsigned)s;
                        if (key < b1) b1 = key;
                    }
                }
            }
            unsigned long long o;
            o = __shfl_xor_sync(0xffffffffu, b0, 1); if (o < b0) b0 = o;
            o = __shfl_xor_sync(0xffffffffu, b0, 2); if (o < b0) b0 = o;
            o = __shfl_xor_sync(0xffffffffu, b1, 1); if (o < b1) b1 = o;
            o = __shfl_xor_sync(0xffffffffu, b1, 2); if (o < b1) b1 = o;
            if (qd == 0) {
                atomicMin(&zmin[wm * 64 + t * 16 + g], b0);
                atomicMin(&zmin[wm * 64 + t * 16 + g + 8], b1);
            }
        }
        __syncthreads();
        if (tid < 128)
            atomicMin(&zpk_out[(size_t)bh * CL + bm + tid], zmin[tid]);
    } else {                                          // MODE 5: wv * gate
        int b = bh >> 3;
        #pragma unroll
        for (int t = 0; t < 4; ++t) {
            int l = bm + wm * 64 + t * 16 + g;
            #pragma unroll
            for (int u = 0; u < 4; ++u) {
                int c = wn * 32 + u * 8 + qd * 2;
                size_t o0 = ((size_t)b * CL + l) * CDM + h * CDV + c;
                size_t o1 = ((size_t)b * CL + l + 8) * CDM + h * CDV + c;
                float2 g0 = *(const float2*)(gate + o0);
                float2 g1 = *(const float2*)(gate + o1);
                *(float2*)(outp + o0) = make_float2(acc[t][u][0] * g0.x, acc[t][u][1] * g0.y);
                *(float2*)(outp + o1) = make_float2(acc[t][u][2] * g1.x, acc[t][u][3] * g1.y);
            }
        }
    }
}

// ---------------------------------------------------------------------------
// Joint softmax over 1536 keys
// ---------------------------------------------------------------------------
__global__ void __launch_bounds__(256) softmax_kernel(float* __restrict__ scores) {
    float* row = scores + (size_t)blockIdx.x * SCW;
    int tid = threadIdx.x;
    __shared__ float sb[8];
    float v[6];
    float m = -3.4e38f;
    #pragma unroll
    for (int i = 0; i < 6; ++i) { v[i] = row[tid + i * 256]; m = fmaxf(m, v[i]); }
    #pragma unroll
    for (int o = 16; o; o >>= 1) m = fmaxf(m, __shfl_down_sync(0xffffffffu, m, o));
    if ((tid & 31) == 0) sb[tid >> 5] = m;
    __syncthreads();
    m = sb[0];
    #pragma unroll
    for (int i = 1; i < 8; ++i) m = fmaxf(m, sb[i]);
    __syncthreads();
    float s = 0.f;
    #pragma unroll
    for (int i = 0; i < 6; ++i) { v[i] = __expf(v[i] - m); s += v[i]; }
    #pragma unroll
    for (int o = 16; o; o >>= 1) s += __shfl_down_sync(0xffffffffu, s, o);
    if ((tid & 31) == 0) sb[tid >> 5] = s;
    __syncthreads();
    float tot = sb[0];
    #pragma unroll
    for (int i = 1; i < 8; ++i) tot += sb[i];
    float inv = 1.f / tot;
    #pragma unroll
    for (int i = 0; i < 6; ++i) row[tid + i * 256] = v[i] * inv;
}

// ---------------------------------------------------------------------------
// Host launcher
// ---------------------------------------------------------------------------
extern "C" void kernel_launch(void* const* d_in, const int* in_sizes, int n_in,
                              void* d_out, int out_size) {
    const float* input     = (const float*)d_in[0];
    const float* xl_k_hat  = (const float*)d_in[2];
    const float* xl_v      = (const float*)d_in[3];
    const float* agg_upper = (const float*)d_in[4];
    const float* agg_lower = (const float*)d_in[5];
    const float* W_q       = (const float*)d_in[6];
    const float* W_kvg     = (const float*)d_in[7];
    const float* W_res     = (const float*)d_in[8];
    const float* x_u       = (const float*)d_in[9];
    const float* x_v       = (const float*)d_in[10];
    const float* xl_r      = (const float*)d_in[11];
    const float* codebook  = (const float*)d_in[12];
    float* out = (float*)d_out;

    float *xt, *qraw, *kvg, *qu, *qv, *kl, *vv, *gate, *rbd, *scores, *wvg, *csq;
    float *wqt, *wkvgt, *wrest, *vt;
    unsigned long long* zpk;
    cudaGetSymbolAddress((void**)&xt, g_xt);
    cudaGetSymbolAddress((void**)&qraw, g_qraw);
    cudaGetSymbolAddress((void**)&kvg, g_kvg);
    cudaGetSymbolAddress((void**)&qu, g_qu);
    cudaGetSymbolAddress((void**)&qv, g_qvb);
    cudaGetSymbolAddress((void**)&kl, g_kl);
    cudaGetSymbolAddress((void**)&vv, g_vv);
    cudaGetSymbolAddress((void**)&gate, g_gate);
    cudaGetSymbolAddress((void**)&rbd, g_rbd);
    cudaGetSymbolAddress((void**)&scores, g_scores);
    cudaGetSymbolAddress((void**)&wvg, g_wvg);
    cudaGetSymbolAddress((void**)&zpk, g_zpk);
    cudaGetSymbolAddress((void**)&csq, g_csq);
    cudaGetSymbolAddress((void**)&wqt, g_wqt);
    cudaGetSymbolAddress((void**)&wkvgt, g_wkvgt);
    cudaGetSymbolAddress((void**)&wrest, g_wrest);
    cudaGetSymbolAddress((void**)&vt, g_vt);

    // transposes (weights)
    transpose_kernel<<<dim3(1024 / 32, 1024 / 32), 256>>>(W_q, wqt, 1024, 1024);
    transpose_kernel<<<dim3(3072 / 32, 1024 / 32), 256>>>(W_kvg, wkvgt, 1024, 3072);
    transpose_kernel<<<dim3(1024 / 32, 1024 / 32), 256>>>(W_res, wrest, 1024, 1024);

    // 1. LN(input)
    ln_rows_kernel<<<NROWS, 256>>>(input, xt);

    // 2. projections: qraw = xt @ Wq, kvg = xt @ Wkvg   (NT vs transposed weights)
    mma_gemm_kernel<4><<<dim3(8, 32, 1), 256>>>(xt, wqt, nullptr, nullptr, nullptr,
                                                nullptr, nullptr, nullptr, nullptr,
                                                nullptr, qraw, 1024, 1024, 1024);
    mma_gemm_kernel<4><<<dim3(24, 32, 1), 256>>>(xt, wkvgt, nullptr, nullptr, nullptr,
                                                 nullptr, nullptr, nullptr, nullptr,
                                                 nullptr, kvg, 3072, 1024, 1024);

    // 3. per-head LN, biases, silu
    transform_kernel<<<NROWS * CH, 128>>>(qraw, kvg, x_u, x_v, qu, qv, kl, vv, gate);

    // 4. V gather-transpose (needs vv)
    vt_kernel<<<dim3(SCW / 32, CDV / 32, NBH), 256>>>(xl_v, vv, agg_upper, vt);

    // 5. VQ
    csq_kernel<<<CH * CS, 128>>>(codebook, csq);
    zinit_kernel<<<NBH, 512>>>(zpk);
    mma_gemm_kernel<3><<<dim3(4, 4, NBH), 256>>>(kl, nullptr, xl_k_hat, codebook,
                                                 agg_lower, csq, zpk, zpk, rbd,
                                                 nullptr, nullptr, 512, 128, 128);

    // 6. scores
    mma_gemm_kernel<0><<<dim3(8, 4, NBH), 256>>>(qv, xl_r, xl_k_hat, codebook,
                                                 agg_lower, csq, zpk, zpk, rbd,
                                                 nullptr, rbd, 1024, 128, 128);
    mma_gemm_kernel<1><<<dim3(8, 4, NBH), 256>>>(qu, nullptr, xl_k_hat, codebook,
                                                 agg_lower, csq, zpk, zpk, rbd,
                                                 nullptr, scores, 1024, 128, 128);
    mma_gemm_kernel<2><<<dim3(4, 4, NBH), 256>>>(qu, nullptr, xl_k_hat, codebook,
                                                 agg_lower, csq, zpk, zpk, rbd,
                                                 nullptr, scores, 512, 128, 128);

    // 7. joint softmax
    softmax_kernel<<<NBH * CL, 256>>>(scores);

    // 8. weighted values (fused * gate)
    mma_gemm_kernel<5><<<dim3(1, 4, NBH), 256>>>(scores, vt, xl_k_hat, codebook,
                                                 agg_lower, csq, zpk, zpk, rbd,
                                                 gate, wvg, 128, 1536, SCW);

    // 9. output projection
    mma_gemm_kernel<4><<<dim3(8, 32, 1), 256>>>(wvg, wrest, nullptr, nullptr, nullptr,
                                                nullptr, nullptr, nullptr, nullptr,
                                                nullptr, out, 1024, 1024, 1024);
}

// round 4
// speedup vs baseline: 2.0820x; 1.2697x over previous
#include <cuda_runtime.h>
#include <cuda_bf16.h>
#include <cstdint>

// ---------------------------------------------------------------------------
// Problem constants
// ---------------------------------------------------------------------------
#define CB   8
#define CL   512
#define CM   512
#define CH   8
#define CDK  128
#define CDV  128
#define CS   512
#define CDM  1024
#define CW   1024   // W_REC
#define NBH  64
#define NROWS 4096
#define SCW  1536   // W + S

static __device__ __constant__ const float TAUI = 0.08838834764831845f; // 1/sqrt(128)

typedef __nv_bfloat16 bf16;

// ---------------------------------------------------------------------------
// Scratch
// ---------------------------------------------------------------------------
__device__ float g_qraw  [(size_t)NROWS * CDM];
__device__ float g_kvg   [(size_t)NROWS * 3072];
__device__ float g_vv    [(size_t)NBH * CL * CDV];
__device__ float g_gate  [(size_t)NROWS * CDM];
__device__ float g_rbd   [(size_t)NBH * CL * CW];
__device__ float g_scores[(size_t)NBH * CL * SCW];
__device__ unsigned long long g_zpk[NBH * CL];
__device__ float g_csq   [CH * CS];

// pre-split bf16 hi/lo operand buffers
__device__ bf16 g_xt_h   [(size_t)NROWS * CDM];
__device__ bf16 g_xt_l   [(size_t)NROWS * CDM];
__device__ bf16 g_wqt_h  [(size_t)1024 * 1024];
__device__ bf16 g_wqt_l  [(size_t)1024 * 1024];
__device__ bf16 g_wkvgt_h[(size_t)3072 * 1024];
__device__ bf16 g_wkvgt_l[(size_t)3072 * 1024];
__device__ bf16 g_wrest_h[(size_t)1024 * 1024];
__device__ bf16 g_wrest_l[(size_t)1024 * 1024];
__device__ bf16 g_qu_h   [(size_t)NBH * CL * CDK];
__device__ bf16 g_qu_l   [(size_t)NBH * CL * CDK];
__device__ bf16 g_qv_h   [(size_t)NBH * CL * CDK];
__device__ bf16 g_qv_l   [(size_t)NBH * CL * CDK];
__device__ bf16 g_kl_h   [(size_t)NBH * CL * CDK];
__device__ bf16 g_kl_l   [(size_t)NBH * CL * CDK];
__device__ bf16 g_khat_h [(size_t)NBH * CM * CDK];
__device__ bf16 g_khat_l [(size_t)NBH * CM * CDK];
__device__ bf16 g_cb_h   [(size_t)CH * CS * CDK];
__device__ bf16 g_cb_l   [(size_t)CH * CS * CDK];
__device__ bf16 g_xlr_h  [(size_t)CH * CW * CDK];
__device__ bf16 g_xlr_l  [(size_t)CH * CW * CDK];
__device__ bf16 g_vt_h   [(size_t)NBH * CDV * SCW];
__device__ bf16 g_vt_l   [(size_t)NBH * CDV * SCW];
__device__ bf16 g_p_h    [(size_t)NBH * CL * SCW];
__device__ bf16 g_p_l    [(size_t)NBH * CL * SCW];
__device__ bf16 g_wvg_h  [(size_t)NROWS * CDM];
__device__ bf16 g_wvg_l  [(size_t)NROWS * CDM];

// ---------------------------------------------------------------------------
// primitives
// ---------------------------------------------------------------------------
__device__ __forceinline__ uint32_t cvta_s(const void* p) {
    return (uint32_t)__cvta_generic_to_shared(p);
}
__device__ __forceinline__ void ldmx4(uint32_t addr, uint32_t& r0, uint32_t& r1,
                                      uint32_t& r2, uint32_t& r3) {
    asm volatile("ldmatrix.sync.aligned.m8n8.x4.shared.b16 {%0,%1,%2,%3}, [%4];"
                 : "=r"(r0), "=r"(r1), "=r"(r2), "=r"(r3) : "r"(addr));
}
__device__ __forceinline__ void mma16816(float c[4], const uint32_t a[4], const uint32_t b[2]) {
    asm volatile(
        "mma.sync.aligned.m16n8k16.row.col.f32.bf16.bf16.f32 "
        "{%0,%1,%2,%3}, {%4,%5,%6,%7}, {%8,%9}, {%0,%1,%2,%3};"
        : "+f"(c[0]), "+f"(c[1]), "+f"(c[2]), "+f"(c[3])
        : "r"(a[0]), "r"(a[1]), "r"(a[2]), "r"(a[3]), "r"(b[0]), "r"(b[1]));
}
__device__ __forceinline__ void cpa16(uint32_t d, const void* s) {
    asm volatile("cp.async.ca.shared.global [%0], [%1], 16;" :: "r"(d), "l"(s));
}
__device__ __forceinline__ void cpa_commit() {
    asm volatile("cp.async.commit_group;");
}
template <int NN>
__device__ __forceinline__ void cpa_wait() {
    asm volatile("cp.async.wait_group %0;" :: "n"(NN));
}

// fp32 -> bf16 hi + lo residual
__device__ __forceinline__ void splitw(float x, bf16* h, bf16* l) {
    bf16 hh = __float2bfloat16_rn(x);
    *h = hh;
    *l = __float2bfloat16_rn(x - __bfloat162float(hh));
}
__device__ __forceinline__ void split4(float4 v, bf16* hp, bf16* lp) {
    __nv_bfloat162 h0 = __floats2bfloat162_rn(v.x, v.y);
    __nv_bfloat162 h1 = __floats2bfloat162_rn(v.z, v.w);
    float2 f0 = __bfloat1622float2(h0);
    float2 f1 = __bfloat1622float2(h1);
    __nv_bfloat162 l0 = __floats2bfloat162_rn(v.x - f0.x, v.y - f0.y);
    __nv_bfloat162 l1 = __floats2bfloat162_rn(v.z - f1.x, v.w - f1.y);
    uint2 hv, lv;
    hv.x = *(uint32_t*)&h0; hv.y = *(uint32_t*)&h1;
    lv.x = *(uint32_t*)&l0; lv.y = *(uint32_t*)&l1;
    *(uint2*)hp = hv;
    *(uint2*)lp = lv;
}

// ---------------------------------------------------------------------------
// Block reductions
// ---------------------------------------------------------------------------
__device__ __forceinline__ float block_sum(float v) {
    __shared__ float sb_[8];
    int tid = threadIdx.x;
    int nw  = blockDim.x >> 5;
    #pragma unroll
    for (int o = 16; o; o >>= 1) v += __shfl_down_sync(0xffffffffu, v, o);
    __syncthreads();
    if ((tid & 31) == 0) sb_[tid >> 5] = v;
    __syncthreads();
    float r = 0.f;
    for (int i = 0; i < nw; ++i) r += sb_[i];
    return r;
}

// ---------------------------------------------------------------------------
// LayerNorm over DM=1024 -> bf16 hi/lo
// ---------------------------------------------------------------------------
__global__ void __launch_bounds__(256) ln_rows_kernel(const float* __restrict__ x,
                                                      bf16* __restrict__ yh,
                                                      bf16* __restrict__ yl) {
    int row = blockIdx.x;
    const float* xr = x + (size_t)row * CDM;
    int tid = threadIdx.x;
    float4 v = *(const float4*)(xr + tid * 4);
    float s = v.x + v.y + v.z + v.w;
    float mu = block_sum(s) * (1.f / 1024.f);
    v.x -= mu; v.y -= mu; v.z -= mu; v.w -= mu;
    float s2 = v.x * v.x + v.y * v.y + v.z * v.z + v.w * v.w;
    float rstd = rsqrtf(block_sum(s2) * (1.f / 1024.f) + 1e-6f);
    v.x *= rstd; v.y *= rstd; v.z *= rstd; v.w *= rstd;
    split4(v, yh + (size_t)row * CDM + tid * 4, yl + (size_t)row * CDM + tid * 4);
}

// ---------------------------------------------------------------------------
// fp32 -> bf16 hi/lo convert (n multiple of 1024)
// ---------------------------------------------------------------------------
__global__ void __launch_bounds__(256) convert_hl_kernel(const float* __restrict__ src,
                                                         bf16* __restrict__ h,
                                                         bf16* __restrict__ l) {
    size_t idx = (size_t)blockIdx.x * 256 + threadIdx.x;
    float4 v = ((const float4*)src)[idx];
    split4(v, h + idx * 4, l + idx * 4);
}

// ---------------------------------------------------------------------------
// Transpose + split: dst[c][r] = src[r][c]
// ---------------------------------------------------------------------------
__global__ void __launch_bounds__(256) transpose_kernel(const float* __restrict__ src,
                                                        bf16* __restrict__ dsth,
                                                        bf16* __restrict__ dstl,
                                                        int R, int C) {
    __shared__ float tile[32][33];
    int c0 = blockIdx.x * 32, r0 = blockIdx.y * 32;
    int x = threadIdx.x & 31, y = (threadIdx.x >> 5) * 4;
    #pragma unroll
    for (int i = 0; i < 4; ++i)
        tile[y + i][x] = src[(size_t)(r0 + y + i) * C + c0 + x];
    __syncthreads();
    #pragma unroll
    for (int i = 0; i < 4; ++i) {
        size_t o = (size_t)(c0 + y + i) * R + r0 + x;
        splitw(tile[x][y + i], dsth + o, dstl + o);
    }
}

// ---------------------------------------------------------------------------
// Vt[bh][v][w] from gathered V rows, split
// ---------------------------------------------------------------------------
__global__ void __launch_bounds__(256) vt_kernel(const float* __restrict__ xl_v,
                                                 const float* __restrict__ vv,
                                                 const float* __restrict__ aggu,
                                                 bf16* __restrict__ vth,
                                                 bf16* __restrict__ vtl) {
    __shared__ float tile[32][33];
    int bh = blockIdx.z;
    int w0 = blockIdx.x * 32, v0 = blockIdx.y * 32;
    int x = threadIdx.x & 31, y = (threadIdx.x >> 5) * 4;
    #pragma unroll
    for (int i = 0; i < 4; ++i) {
        int w = w0 + y + i;
        const float* srcrow;
        if (w < CM)      srcrow = xl_v + ((size_t)bh * CM + w) * CDV;
        else if (w < CW) srcrow = vv   + ((size_t)bh * CL + (w - CM)) * CDV;
        else             srcrow = aggu + ((size_t)bh * CS + (w - CW)) * CDV;
        tile[y + i][x] = srcrow[v0 + x];
    }
    __syncthreads();
    #pragma unroll
    for (int i = 0; i < 4; ++i) {
        size_t o = ((size_t)bh * CDV + v0 + y + i) * SCW + w0 + x;
        splitw(tile[x][y + i], vth + o, vtl + o);
    }
}

// ---------------------------------------------------------------------------
// Per-(b,l,h): LN(q)->qu/qv, LN(k)->kl (split), copy v, silu(g)
// ---------------------------------------------------------------------------
__global__ void __launch_bounds__(128) transform_kernel(const float* __restrict__ qraw,
                                                        const float* __restrict__ kvg,
                                                        const float* __restrict__ x_u,
                                                        const float* __restrict__ x_v,
                                                        bf16* __restrict__ quh, bf16* __restrict__ qul,
                                                        bf16* __restrict__ qvh, bf16* __restrict__ qvl,
                                                        bf16* __restrict__ klh, bf16* __restrict__ kll,
                                                        float* __restrict__ vv,
                                                        float* __restrict__ gate) {
    int idx = blockIdx.x;
    int h  = idx & 7;
    int bl = idx >> 3;
    int b = bl >> 9, l = bl & 511;
    int d = threadIdx.x;

    float q  = qraw[(size_t)bl * CDM + h * CDK + d];
    float mu = block_sum(q) * (1.f / 128.f);
    float qc = q - mu;
    float var = block_sum(qc * qc) * (1.f / 128.f);
    float qn  = qc * rsqrtf(var + 1e-6f);
    size_t o = (((size_t)b * CH + h) * CL + l) * CDK + d;
    splitw(qn + x_u[h * CDK + d], quh + o, qul + o);
    splitw(qn + x_v[h * CDK + d], qvh + o, qvl + o);

    float k   = kvg[(size_t)bl * 3072 + h * CDK + d];
    float kmu = block_sum(k) * (1.f / 128.f);
    float kc  = k - kmu;
    float kvar = block_sum(kc * kc) * (1.f / 128.f);
    splitw(kc * rsqrtf(kvar + 1e-6f), klh + o, kll + o);

    vv[o] = kvg[(size_t)bl * 3072 + 1024 + h * CDK + d];

    float gg = kvg[(size_t)bl * 3072 + 2048 + h * CDK + d];
    gate[(size_t)bl * CDM + h * CDK + d] = gg / (1.f + __expf(-gg));
}

__global__ void __launch_bounds__(128) csq_kernel(const float* __restrict__ cb,
                                                  float* __restrict__ csq) {
    int row = blockIdx.x;
    float v = cb[(size_t)row * CDK + threadIdx.x];
    v = block_sum(v * v);
    if (threadIdx.x == 0) csq[row] = v;
}

__global__ void zinit_kernel(unsigned long long* zpk) {
    zpk[blockIdx.x * 512 + threadIdx.x] = ~0ull;
}

// ---------------------------------------------------------------------------
// NT tensor-core GEMM (bf16x3, pre-split operands, cp.async 2-stage pipeline)
// MODE: 0=BD, 1=REC, 2=CACHE, 3=VQ, 4=PROJ(fp32 out), 5=WV(bf16 out * gate)
// smem: [stage][hi/lo][row128][pitch24] -> exactly 48KB total
// ---------------------------------------------------------------------------
#define STG_B 12288   // stage stride bytes (2*128*24*2)
#define CMP_B 6144    // hi->lo stride bytes
template <int MODE>
__global__ void __launch_bounds__(256) mma_gemm_kernel(
    const bf16* __restrict__ Ah, const bf16* __restrict__ Al,
    const bf16* __restrict__ Bh, const bf16* __restrict__ Bl,
    const bf16* __restrict__ cbh, const bf16* __restrict__ cbl,
    const float* __restrict__ agg_lower, const float* __restrict__ csq,
    const unsigned long long* __restrict__ zpk_in, unsigned long long* zpk_out,
    const float* __restrict__ rbd_in, const float* __restrict__ gate,
    float* __restrict__ outp, bf16* __restrict__ outh, bf16* __restrict__ outl,
    int N, int K, int lda) {

    __shared__ __align__(16) bf16 SA[2][2][128][24];
    __shared__ __align__(16) bf16 SB[2][2][128][24];

    int tid  = threadIdx.x;
    int lane = tid & 31, warp = tid >> 5;
    int wm = warp >> 2, wn = warp & 3;
    int bm = blockIdx.y * 128;
    int bn = blockIdx.x * 128;
    int bh = blockIdx.z;
    int h  = bh & 7;

    if (MODE == 1 && bn >= bm + CM + 128) {     // fully masked tile
        for (int i = tid; i < 128 * 128; i += 256) {
            int r = i >> 7, c = i & 127;
            outp[((size_t)bh * CL + bm + r) * SCW + bn + c] = -1e30f;
        }
        return;
    }

    size_t aoff;
    if (MODE == 4)      aoff = 0;
    else if (MODE == 5) aoff = (size_t)bh * CL * SCW;
    else                aoff = (size_t)bh * CL * CDK;

    int srow = tid >> 1;
    int sc8  = (tid & 1) * 8;
    const bf16* a_h = Ah + aoff + (size_t)(bm + srow) * lda + sc8;
    const bf16* a_l = Al + aoff + (size_t)(bm + srow) * lda + sc8;
    const bf16 *b_h, *b_l;
    {
        int n = bn + srow;
        size_t boff;
        if (MODE == 0)      { boff = ((size_t)h * CW + n) * CDK; b_h = Bh + boff; b_l = Bl + boff; }
        else if (MODE == 1) {
            if (n < CM) { boff = ((size_t)bh * CM + n) * CDK; b_h = Bh + boff; b_l = Bl + boff; }
            else {
                unsigned zi = (unsigned)(zpk_in[(size_t)bh * CL + (n - CM)] & 0xffffffffull);
                boff = ((size_t)h * CS + zi) * CDK; b_h = cbh + boff; b_l = cbl + boff;
            }
        }
        else if (MODE == 2 || MODE == 3) { boff = ((size_t)h * CS + n) * CDK; b_h = Bh + boff; b_l = Bl + boff; }
        else if (MODE == 4) { boff = (size_t)n * K; b_h = Bh + boff; b_l = Bl + boff; }
        else                { boff = ((size_t)bh * CDV + n) * SCW; b_h = Bh + boff; b_l = Bl + boff; }
        b_h += sc8; b_l += sc8;
    }

    uint32_t sA = cvta_s(&SA[0][0][0][0]);
    uint32_t sB = cvta_s(&SB[0][0][0][0]);
    uint32_t dA = sA + (uint32_t)(srow * 24 + sc8) * 2;
    uint32_t dB = sB + (uint32_t)(srow * 24 + sc8) * 2;

    int a_off = (wm * 64 + (lane & 15)) * 24 + ((lane >> 4) << 3);
    int b_off = (wn * 32 + ((lane >> 4) << 3) + (lane & 7)) * 24 + (((lane >> 3) & 1) << 3);

    float acc[4][4][4] = {};
    int T = K >> 4;

    // stage 0 prefetch
    cpa16(dA,         a_h);  cpa16(dA + CMP_B, a_l);
    cpa16(dB,         b_h);  cpa16(dB + CMP_B, b_l);
    cpa_commit();

    #pragma unroll 1
    for (int kt = 0; kt < T; ++kt) {
        if (kt + 1 < T) {
            int st = (kt + 1) & 1, k0 = (kt + 1) * 16;
            cpa16(dA + st * STG_B,         a_h + k0);
            cpa16(dA + st * STG_B + CMP_B, a_l + k0);
            cpa16(dB + st * STG_B,         b_h + k0);
            cpa16(dB + st * STG_B + CMP_B, b_l + k0);
            cpa_commit();
            cpa_wait<1>();
        } else {
            cpa_wait<0>();
        }
        __syncthreads();

        uint32_t aH = sA + (kt & 1) * STG_B + (uint32_t)a_off * 2;
        uint32_t bH = sB + (kt & 1) * STG_B + (uint32_t)b_off * 2;
        uint32_t ah[4][4], al[4][4], bhf[4][2], blf[4][2];
        #pragma unroll
        for (int t = 0; t < 4; ++t) {
            ldmx4(aH + t * 768,         ah[t][0], ah[t][1], ah[t][2], ah[t][3]);
            ldmx4(aH + CMP_B + t * 768, al[t][0], al[t][1], al[t][2], al[t][3]);
        }
        #pragma unroll
        for (int u2 = 0; u2 < 2; ++u2) {
            uint32_t r0, r1, r2, r3;
            ldmx4(bH + u2 * 768, r0, r1, r2, r3);
            bhf[2 * u2][0] = r0; bhf[2 * u2][1] = r1;
            bhf[2 * u2 + 1][0] = r2; bhf[2 * u2 + 1][1] = r3;
            ldmx4(bH + CMP_B + u2 * 768, r0, r1, r2, r3);
            blf[2 * u2][0] = r0; blf[2 * u2][1] = r1;
            blf[2 * u2 + 1][0] = r2; blf[2 * u2 + 1][1] = r3;
        }
        #pragma unroll
        for (int t = 0; t < 4; ++t)
            #pragma unroll
            for (int u = 0; u < 4; ++u) {
                mma16816(acc[t][u], ah[t], bhf[u]);
                mma16816(acc[t][u], ah[t], blf[u]);
                mma16816(acc[t][u], al[t], bhf[u]);
            }
        __syncthreads();
    }

    // ---- epilogues ------------------------------------------------------
    int g  = lane >> 2;
    int qd = lane & 3;

    if constexpr (MODE == 4) {
        #pragma unroll
        for (int t = 0; t < 4; ++t) {
            int r = bm + wm * 64 + t * 16 + g;
            #pragma unroll
            for (int u = 0; u < 4; ++u) {
                int c = bn + wn * 32 + u * 8 + qd * 2;
                *(float2*)(outp + (size_t)r * N + c) =
                    make_float2(acc[t][u][0], acc[t][u][1]);
                *(float2*)(outp + (size_t)(r + 8) * N + c) =
                    make_float2(acc[t][u][2], acc[t][u][3]);
            }
        }
    } else if constexpr (MODE == 0) {
        #pragma unroll
        for (int t = 0; t < 4; ++t) {
            int l = bm + wm * 64 + t * 16 + g;
            #pragma unroll
            for (int u = 0; u < 4; ++u) {
                int c = bn + wn * 32 + u * 8 + qd * 2;
                *(float2*)(outp + ((size_t)bh * CL + l) * CW + c) =
                    make_float2(acc[t][u][0] * TAUI, acc[t][u][1] * TAUI);
                *(float2*)(outp + ((size_t)bh * CL + l + 8) * CW + c) =
                    make_float2(acc[t][u][2] * TAUI, acc[t][u][3] * TAUI);
            }
        }
    } else if constexpr (MODE == 1) {
        #pragma unroll
        for (int t = 0; t < 4; ++t) {
            int l0 = bm + wm * 64 + t * 16 + g;
            int l1 = l0 + 8;
            const float* rr0 = rbd_in + ((size_t)bh * CL + l0) * CW + (CL - 1) - l0;
            const float* rr1 = rbd_in + ((size_t)bh * CL + l1) * CW + (CL - 1) - l1;
            #pragma unroll
            for (int u = 0; u < 4; ++u) {
                int w = bn + wn * 32 + u * 8 + qd * 2;
                float2 o0, o1;
                o0.x = (w     <= l0 + CM) ? acc[t][u][0] * TAUI + rr0[w]     : -1e30f;
                o0.y = (w + 1 <= l0 + CM) ? acc[t][u][1] * TAUI + rr0[w + 1] : -1e30f;
                o1.x = (w     <= l1 + CM) ? acc[t][u][2] * TAUI + rr1[w]     : -1e30f;
                o1.y = (w + 1 <= l1 + CM) ? acc[t][u][3] * TAUI + rr1[w + 1] : -1e30f;
                *(float2*)(outp + ((size_t)bh * CL + l0) * SCW + w) = o0;
                *(float2*)(outp + ((size_t)bh * CL + l1) * SCW + w) = o1;
            }
        }
    } else if constexpr (MODE == 2) {
        #pragma unroll
        for (int t = 0; t < 4; ++t) {
            int l0 = bm + wm * 64 + t * 16 + g;
            #pragma unroll
            for (int u = 0; u < 4; ++u) {
                int s = bn + wn * 32 + u * 8 + qd * 2;
                float a0 = agg_lower[(size_t)bh * CS + s];
                float a1 = agg_lower[(size_t)bh * CS + s + 1];
                float b0 = (a0 > 0.f) ? logf(fmaxf(a0, 1e-30f)) : -1e30f;
                float b1 = (a1 > 0.f) ? logf(fmaxf(a1, 1e-30f)) : -1e30f;
                *(float2*)(outp + ((size_t)bh * CL + l0) * SCW + CW + s) =
                    make_float2(acc[t][u][0] * TAUI + b0, acc[t][u][1] * TAUI + b1);
                *(float2*)(outp + ((size_t)bh * CL + l0 + 8) * SCW + CW + s) =
                    make_float2(acc[t][u][2] * TAUI + b0, acc[t][u][3] * TAUI + b1);
            }
        }
    } else if constexpr (MODE == 3) {
        unsigned long long* zmin = reinterpret_cast<unsigned long long*>(&SA[0][0][0][0]);
        if (tid < 128) zmin[tid] = ~0ull;
        __syncthreads();
        #pragma unroll
        for (int t = 0; t < 4; ++t) {
            unsigned long long b0 = ~0ull, b1 = ~0ull;
            #pragma unroll
            for (int u = 0; u < 4; ++u) {
                #pragma unroll
                for (int p = 0; p < 2; ++p) {
                    int s = bn + wn * 32 + u * 8 + qd * 2 + p;
                    float cs = csq[h * CS + s];
                    {
                        float val = cs - 2.f * acc[t][u][p];
                        unsigned uu = __float_as_uint(val);
                        uu = (uu & 0x80000000u) ? ~uu : (uu | 0x80000000u);
                        unsigned long long key = ((unsigned long long)uu << 32) | (unsigned)s;
                        if (key < b0) b0 = key;
                    }
                    {
                        float val = cs - 2.f * acc[t][u][2 + p];
                        unsigned uu = __float_as_uint(val);
                        uu = (uu & 0x80000000u) ? ~uu : (uu | 0x80000000u);
                        unsigned long long key = ((unsigned long long)uu << 32) | (unsigned)s;
                        if (key < b1) b1 = key;
                    }
                }
            }
            unsigned long long o;
            o = __shfl_xor_sync(0xffffffffu, b0, 1); if (o < b0) b0 = o;
            o = __shfl_xor_sync(0xffffffffu, b0, 2); if (o < b0) b0 = o;
            o = __shfl_xor_sync(0xffffffffu, b1, 1); if (o < b1) b1 = o;
            o = __shfl_xor_sync(0xffffffffu, b1, 2); if (o < b1) b1 = o;
            if (qd == 0) {
                atomicMin(&zmin[wm * 64 + t * 16 + g], b0);
                atomicMin(&zmin[wm * 64 + t * 16 + g + 8], b1);
            }
        }
        __syncthreads();
        if (tid < 128)
            atomicMin(&zpk_out[(size_t)bh * CL + bm + tid], zmin[tid]);
    } else {                                          // MODE 5: wv * gate -> bf16 hi/lo
        int b = bh >> 3;
        #pragma unroll
        for (int t = 0; t < 4; ++t) {
            int l = bm + wm * 64 + t * 16 + g;
            #pragma unroll
            for (int u = 0; u < 4; ++u) {
                int c = wn * 32 + u * 8 + qd * 2;
                size_t o0 = ((size_t)b * CL + l) * CDM + h * CDV + c;
                size_t o1 = ((size_t)b * CL + l + 8) * CDM + h * CDV + c;
                float2 g0 = *(const float2*)(gate + o0);
                float2 g1 = *(const float2*)(gate + o1);
                splitw(acc[t][u][0] * g0.x, outh + o0,     outl + o0);
                splitw(acc[t][u][1] * g0.y, outh + o0 + 1, outl + o0 + 1);
                splitw(acc[t][u][2] * g1.x, outh + o1,     outl + o1);
                splitw(acc[t][u][3] * g1.y, outh + o1 + 1, outl + o1 + 1);
            }
        }
    }
}

// ---------------------------------------------------------------------------
// Joint softmax over 1536 keys -> bf16 hi/lo probabilities
// ---------------------------------------------------------------------------
__global__ void __launch_bounds__(256) softmax_kernel(const float* __restrict__ scores,
                                                      bf16* __restrict__ ph,
                                                      bf16* __restrict__ pl) {
    const float* row = scores + (size_t)blockIdx.x * SCW;
    size_t ob = (size_t)blockIdx.x * SCW;
    int tid = threadIdx.x;
    __shared__ float sb[8];
    float v[6];
    float m = -3.4e38f;
    #pragma unroll
    for (int i = 0; i < 6; ++i) { v[i] = row[tid + i * 256]; m = fmaxf(m, v[i]); }
    #pragma unroll
    for (int o = 16; o; o >>= 1) m = fmaxf(m, __shfl_down_sync(0xffffffffu, m, o));
    if ((tid & 31) == 0) sb[tid >> 5] = m;
    __syncthreads();
    m = sb[0];
    #pragma unroll
    for (int i = 1; i < 8; ++i) m = fmaxf(m, sb[i]);
    __syncthreads();
    float s = 0.f;
    #pragma unroll
    for (int i = 0; i < 6; ++i) { v[i] = __expf(v[i] - m); s += v[i]; }
    #pragma unroll
    for (int o = 16; o; o >>= 1) s += __shfl_down_sync(0xffffffffu, s, o);
    if ((tid & 31) == 0) sb[tid >> 5] = s;
    __syncthreads();
    float tot = sb[0];
    #pragma unroll
    for (int i = 1; i < 8; ++i) tot += sb[i];
    float inv = 1.f / tot;
    #pragma unroll
    for (int i = 0; i < 6; ++i)
        splitw(v[i] * inv, ph + ob + tid + i * 256, pl + ob + tid + i * 256);
}

// ---------------------------------------------------------------------------
// Host launcher
// ---------------------------------------------------------------------------
extern "C" void kernel_launch(void* const* d_in, const int* in_sizes, int n_in,
                              void* d_out, int out_size) {
    const float* input     = (const float*)d_in[0];
    const float* xl_k_hat  = (const float*)d_in[2];
    const float* xl_v      = (const float*)d_in[3];
    const float* agg_upper = (const float*)d_in[4];
    const float* agg_lower = (const float*)d_in[5];
    const float* W_q       = (const float*)d_in[6];
    const float* W_kvg     = (const float*)d_in[7];
    const float* W_res     = (const float*)d_in[8];
    const float* x_u       = (const float*)d_in[9];
    const float* x_v       = (const float*)d_in[10];
    const float* xl_r      = (const float*)d_in[11];
    const float* codebook  = (const float*)d_in[12];
    float* out = (float*)d_out;

    float *qraw, *kvg, *vv, *gate, *rbd, *scores, *csq;
    unsigned long long* zpk;
    bf16 *xt_h, *xt_l, *wqt_h, *wqt_l, *wkvgt_h, *wkvgt_l, *wrest_h, *wrest_l;
    bf16 *qu_h, *qu_l, *qv_h, *qv_l, *kl_h, *kl_l, *khat_h, *khat_l;
    bf16 *cb_h, *cb_l, *xlr_h, *xlr_l, *vt_h, *vt_l, *p_h, *p_l, *wvg_h, *wvg_l;

    cudaGetSymbolAddress((void**)&qraw, g_qraw);
    cudaGetSymbolAddress((void**)&kvg, g_kvg);
    cudaGetSymbolAddress((void**)&vv, g_vv);
    cudaGetSymbolAddress((void**)&gate, g_gate);
    cudaGetSymbolAddress((void**)&rbd, g_rbd);
    cudaGetSymbolAddress((void**)&scores, g_scores);
    cudaGetSymbolAddress((void**)&csq, g_csq);
    cudaGetSymbolAddress((void**)&zpk, g_zpk);
    cudaGetSymbolAddress((void**)&xt_h, g_xt_h);   cudaGetSymbolAddress((void**)&xt_l, g_xt_l);
    cudaGetSymbolAddress((void**)&wqt_h, g_wqt_h); cudaGetSymbolAddress((void**)&wqt_l, g_wqt_l);
    cudaGetSymbolAddress((void**)&wkvgt_h, g_wkvgt_h); cudaGetSymbolAddress((void**)&wkvgt_l, g_wkvgt_l);
    cudaGetSymbolAddress((void**)&wrest_h, g_wrest_h); cudaGetSymbolAddress((void**)&wrest_l, g_wrest_l);
    cudaGetSymbolAddress((void**)&qu_h, g_qu_h);   cudaGetSymbolAddress((void**)&qu_l, g_qu_l);
    cudaGetSymbolAddress((void**)&qv_h, g_qv_h);   cudaGetSymbolAddress((void**)&qv_l, g_qv_l);
    cudaGetSymbolAddress((void**)&kl_h, g_kl_h);   cudaGetSymbolAddress((void**)&kl_l, g_kl_l);
    cudaGetSymbolAddress((void**)&khat_h, g_khat_h); cudaGetSymbolAddress((void**)&khat_l, g_khat_l);
    cudaGetSymbolAddress((void**)&cb_h, g_cb_h);   cudaGetSymbolAddress((void**)&cb_l, g_cb_l);
    cudaGetSymbolAddress((void**)&xlr_h, g_xlr_h); cudaGetSymbolAddress((void**)&xlr_l, g_xlr_l);
    cudaGetSymbolAddress((void**)&vt_h, g_vt_h);   cudaGetSymbolAddress((void**)&vt_l, g_vt_l);
    cudaGetSymbolAddress((void**)&p_h, g_p_h);     cudaGetSymbolAddress((void**)&p_l, g_p_l);
    cudaGetSymbolAddress((void**)&wvg_h, g_wvg_h); cudaGetSymbolAddress((void**)&wvg_l, g_wvg_l);

    // input converts / transposes
    transpose_kernel<<<dim3(32, 32), 256>>>(W_q, wqt_h, wqt_l, 1024, 1024);
    transpose_kernel<<<dim3(96, 32), 256>>>(W_kvg, wkvgt_h, wkvgt_l, 1024, 3072);
    transpose_kernel<<<dim3(32, 32), 256>>>(W_res, wrest_h, wrest_l, 1024, 1024);
    convert_hl_kernel<<<(NBH * CM * CDK) / 1024, 256>>>(xl_k_hat, khat_h, khat_l);
    convert_hl_kernel<<<(CH * CS * CDK) / 1024, 256>>>(codebook, cb_h, cb_l);
    convert_hl_kernel<<<(CH * CW * CDK) / 1024, 256>>>(xl_r, xlr_h, xlr_l);
    csq_kernel<<<CH * CS, 128>>>(codebook, csq);
    zinit_kernel<<<NBH, 512>>>(zpk);

    // 1. LN(input)
    ln_rows_kernel<<<NROWS, 256>>>(input, xt_h, xt_l);

    // 2. projections
    mma_gemm_kernel<4><<<dim3(8, 32, 1), 256>>>(xt_h, xt_l, wqt_h, wqt_l, nullptr, nullptr,
        nullptr, nullptr, nullptr, nullptr, nullptr, nullptr, qraw, nullptr, nullptr,
        1024, 1024, 1024);
    mma_gemm_kernel<4><<<dim3(24, 32, 1), 256>>>(xt_h, xt_l, wkvgt_h, wkvgt_l, nullptr, nullptr,
        nullptr, nullptr, nullptr, nullptr, nullptr, nullptr, kvg, nullptr, nullptr,
        3072, 1024, 1024);

    // 3. per-head LN, biases, silu
    transform_kernel<<<NROWS * CH, 128>>>(qraw, kvg, x_u, x_v,
                                          qu_h, qu_l, qv_h, qv_l, kl_h, kl_l, vv, gate);

    // 4. V gather-transpose
    vt_kernel<<<dim3(SCW / 32, CDV / 32, NBH), 256>>>(xl_v, vv, agg_upper, vt_h, vt_l);

    // 5. VQ argmin
    mma_gemm_kernel<3><<<dim3(4, 4, NBH), 256>>>(kl_h, kl_l, cb_h, cb_l, cb_h, cb_l,
        agg_lower, csq, zpk, zpk, nullptr, nullptr, nullptr, nullptr, nullptr,
        512, 128, 128);

    // 6. scores
    mma_gemm_kernel<0><<<dim3(8, 4, NBH), 256>>>(qv_h, qv_l, xlr_h, xlr_l, nullptr, nullptr,
        nullptr, nullptr, nullptr, nullptr, nullptr, nullptr, rbd, nullptr, nullptr,
        1024, 128, 128);
    mma_gemm_kernel<1><<<dim3(8, 4, NBH), 256>>>(qu_h, qu_l, khat_h, khat_l, cb_h, cb_l,
        nullptr, nullptr, zpk, nullptr, rbd, nullptr, scores, nullptr, nullptr,
        1024, 128, 128);
    mma_gemm_kernel<2><<<dim3(4, 4, NBH), 256>>>(qu_h, qu_l, cb_h, cb_l, nullptr, nullptr,
        agg_lower, nullptr, nullptr, nullptr, nullptr, nullptr, scores, nullptr, nullptr,
        512, 128, 128);

    // 7. joint softmax -> bf16 probs
    softmax_kernel<<<NBH * CL, 256>>>(scores, p_h, p_l);

    // 8. weighted values (fused * gate) -> bf16 hi/lo
    mma_gemm_kernel<5><<<dim3(1, 4, NBH), 256>>>(p_h, p_l, vt_h, vt_l, nullptr, nullptr,
        nullptr, nullptr, nullptr, nullptr, nullptr, gate, nullptr, wvg_h, wvg_l,
        128, 1536, 1536);

    // 9. output projection
    mma_gemm_kernel<4><<<dim3(8, 32, 1), 256>>>(wvg_h, wvg_l, wrest_h, wrest_l, nullptr, nullptr,
        nullptr, nullptr, nullptr, nullptr, nullptr, nullptr, out, nullptr, nullptr,
        1024, 1024, 1024);
}

// round 7
// speedup vs baseline: 2.2664x; 1.0885x over previous
#include <cuda_runtime.h>
#include <cuda_bf16.h>
#include <cstdint>

// ---------------------------------------------------------------------------
// Problem constants
// ---------------------------------------------------------------------------
#define CB   8
#define CL   512
#define CM   512
#define CH   8
#define CDK  128
#define CDV  128
#define CS   512
#define CDM  1024
#define CW   1024   // W_REC
#define NBH  64
#define NROWS 4096
#define SCW  1536   // W + S

static __device__ __constant__ const float TAUI = 0.08838834764831845f; // 1/sqrt(128)

typedef __nv_bfloat16 bf16;

// ---------------------------------------------------------------------------
// Scratch
// ---------------------------------------------------------------------------
__device__ float g_qraw  [(size_t)NROWS * CDM];
__device__ float g_kvg   [(size_t)NROWS * 3072];
__device__ float g_vv    [(size_t)NBH * CL * CDV];
__device__ float g_gate  [(size_t)NROWS * CDM];
__device__ float g_rbd   [(size_t)NBH * CL * CW];
__device__ float g_scores[(size_t)NBH * CL * SCW];
__device__ unsigned long long g_zpk[NBH * CL];
__device__ float g_csq   [CH * CS];

// pre-split bf16 hi/lo operand buffers
__device__ bf16 g_xt_h   [(size_t)NROWS * CDM];
__device__ bf16 g_xt_l   [(size_t)NROWS * CDM];
__device__ bf16 g_wqt_h  [(size_t)1024 * 1024];
__device__ bf16 g_wqt_l  [(size_t)1024 * 1024];
__device__ bf16 g_wkvgt_h[(size_t)3072 * 1024];
__device__ bf16 g_wkvgt_l[(size_t)3072 * 1024];
__device__ bf16 g_wrest_h[(size_t)1024 * 1024];
__device__ bf16 g_wrest_l[(size_t)1024 * 1024];
__device__ bf16 g_qu_h   [(size_t)NBH * CL * CDK];
__device__ bf16 g_qu_l   [(size_t)NBH * CL * CDK];
__device__ bf16 g_qv_h   [(size_t)NBH * CL * CDK];
__device__ bf16 g_qv_l   [(size_t)NBH * CL * CDK];
__device__ bf16 g_kl_h   [(size_t)NBH * CL * CDK];
__device__ bf16 g_kl_l   [(size_t)NBH * CL * CDK];
__device__ bf16 g_khat_h [(size_t)NBH * CM * CDK];
__device__ bf16 g_khat_l [(size_t)NBH * CM * CDK];
__device__ bf16 g_cb_h   [(size_t)CH * CS * CDK];
__device__ bf16 g_cb_l   [(size_t)CH * CS * CDK];
__device__ bf16 g_xlr_h  [(size_t)CH * CW * CDK];
__device__ bf16 g_xlr_l  [(size_t)CH * CW * CDK];
__device__ bf16 g_vt_h   [(size_t)NBH * CDV * SCW];
__device__ bf16 g_vt_l   [(size_t)NBH * CDV * SCW];
__device__ bf16 g_p_h    [(size_t)NBH * CL * SCW];
__device__ bf16 g_p_l    [(size_t)NBH * CL * SCW];
__device__ bf16 g_wvg_h  [(size_t)NROWS * CDM];
__device__ bf16 g_wvg_l  [(size_t)NROWS * CDM];

// ---------------------------------------------------------------------------
// primitives
// ---------------------------------------------------------------------------
__device__ __forceinline__ uint32_t cvta_s(const void* p) {
    return (uint32_t)__cvta_generic_to_shared(p);
}
__device__ __forceinline__ void ldmx4(uint32_t addr, uint32_t& r0, uint32_t& r1,
                                      uint32_t& r2, uint32_t& r3) {
    asm volatile("ldmatrix.sync.aligned.m8n8.x4.shared.b16 {%0,%1,%2,%3}, [%4];"
                 : "=r"(r0), "=r"(r1), "=r"(r2), "=r"(r3) : "r"(addr));
}
__device__ __forceinline__ void mma16816(float c[4], const uint32_t a[4], const uint32_t b[2]) {
    asm volatile(
        "mma.sync.aligned.m16n8k16.row.col.f32.bf16.bf16.f32 "
        "{%0,%1,%2,%3}, {%4,%5,%6,%7}, {%8,%9}, {%0,%1,%2,%3};"
        : "+f"(c[0]), "+f"(c[1]), "+f"(c[2]), "+f"(c[3])
        : "r"(a[0]), "r"(a[1]), "r"(a[2]), "r"(a[3]), "r"(b[0]), "r"(b[1]));
}
__device__ __forceinline__ void cpa16(uint32_t d, const void* s) {
    asm volatile("cp.async.ca.shared.global [%0], [%1], 16;" :: "r"(d), "l"(s));
}
__device__ __forceinline__ void cpa_commit() {
    asm volatile("cp.async.commit_group;");
}
template <int NN>
__device__ __forceinline__ void cpa_wait() {
    asm volatile("cp.async.wait_group %0;" :: "n"(NN));
}

// fp32 -> bf16 hi + lo residual
__device__ __forceinline__ void splitw(float x, bf16* h, bf16* l) {
    bf16 hh = __float2bfloat16_rn(x);
    *h = hh;
    *l = __float2bfloat16_rn(x - __bfloat162float(hh));
}
__device__ __forceinline__ void split4(float4 v, bf16* hp, bf16* lp) {
    __nv_bfloat162 h0 = __floats2bfloat162_rn(v.x, v.y);
    __nv_bfloat162 h1 = __floats2bfloat162_rn(v.z, v.w);
    float2 f0 = __bfloat1622float2(h0);
    float2 f1 = __bfloat1622float2(h1);
    __nv_bfloat162 l0 = __floats2bfloat162_rn(v.x - f0.x, v.y - f0.y);
    __nv_bfloat162 l1 = __floats2bfloat162_rn(v.z - f1.x, v.w - f1.y);
    uint2 hv, lv;
    hv.x = *(uint32_t*)&h0; hv.y = *(uint32_t*)&h1;
    lv.x = *(uint32_t*)&l0; lv.y = *(uint32_t*)&l1;
    *(uint2*)hp = hv;
    *(uint2*)lp = lv;
}

// ---------------------------------------------------------------------------
// reductions
// ---------------------------------------------------------------------------
__device__ __forceinline__ float block_sum(float v) {
    __shared__ float sb_[8];
    int tid = threadIdx.x;
    int nw  = blockDim.x >> 5;
    #pragma unroll
    for (int o = 16; o; o >>= 1) v += __shfl_down_sync(0xffffffffu, v, o);
    __syncthreads();
    if ((tid & 31) == 0) sb_[tid >> 5] = v;
    __syncthreads();
    float r = 0.f;
    for (int i = 0; i < nw; ++i) r += sb_[i];
    return r;
}
__device__ __forceinline__ float warp_sum(float v) {
    #pragma unroll
    for (int o = 16; o; o >>= 1) v += __shfl_xor_sync(0xffffffffu, v, o);
    return v;
}

// ---------------------------------------------------------------------------
// LayerNorm over DM=1024 -> bf16 hi/lo
// ---------------------------------------------------------------------------
__global__ void __launch_bounds__(256) ln_rows_kernel(const float* __restrict__ x,
                                                      bf16* __restrict__ yh,
                                                      bf16* __restrict__ yl) {
    int row = blockIdx.x;
    const float* xr = x + (size_t)row * CDM;
    int tid = threadIdx.x;
    float4 v = *(const float4*)(xr + tid * 4);
    float s = v.x + v.y + v.z + v.w;
    float mu = block_sum(s) * (1.f / 1024.f);
    v.x -= mu; v.y -= mu; v.z -= mu; v.w -= mu;
    float s2 = v.x * v.x + v.y * v.y + v.z * v.z + v.w * v.w;
    float rstd = rsqrtf(block_sum(s2) * (1.f / 1024.f) + 1e-6f);
    v.x *= rstd; v.y *= rstd; v.z *= rstd; v.w *= rstd;
    split4(v, yh + (size_t)row * CDM + tid * 4, yl + (size_t)row * CDM + tid * 4);
}

// ---------------------------------------------------------------------------
// fp32 -> bf16 hi/lo convert
// ---------------------------------------------------------------------------
__global__ void __launch_bounds__(256) convert_hl_kernel(const float* __restrict__ src,
                                                         bf16* __restrict__ h,
                                                         bf16* __restrict__ l) {
    size_t idx = (size_t)blockIdx.x * 256 + threadIdx.x;
    float4 v = ((const float4*)src)[idx];
    split4(v, h + idx * 4, l + idx * 4);
}

// ---------------------------------------------------------------------------
// Transpose + split: dst[c][r] = src[r][c]
// ---------------------------------------------------------------------------
__global__ void __launch_bounds__(256) transpose_kernel(const float* __restrict__ src,
                                                        bf16* __restrict__ dsth,
                                                        bf16* __restrict__ dstl,
                                                        int R, int C) {
    __shared__ float tile[32][33];
    int c0 = blockIdx.x * 32, r0 = blockIdx.y * 32;
    int x = threadIdx.x & 31, y = (threadIdx.x >> 5) * 4;
    #pragma unroll
    for (int i = 0; i < 4; ++i)
        tile[y + i][x] = src[(size_t)(r0 + y + i) * C + c0 + x];
    __syncthreads();
    #pragma unroll
    for (int i = 0; i < 4; ++i) {
        size_t o = (size_t)(c0 + y + i) * R + r0 + x;
        splitw(tile[x][y + i], dsth + o, dstl + o);
    }
}

// ---------------------------------------------------------------------------
// Vt[bh][v][w] from gathered V rows, split
// ---------------------------------------------------------------------------
__global__ void __launch_bounds__(256) vt_kernel(const float* __restrict__ xl_v,
                                                 const float* __restrict__ vv,
                                                 const float* __restrict__ aggu,
                                                 bf16* __restrict__ vth,
                                                 bf16* __restrict__ vtl) {
    __shared__ float tile[32][33];
    int zb = blockIdx.z;
    int w0 = blockIdx.x * 32, v0 = blockIdx.y * 32;
    int x = threadIdx.x & 31, y = (threadIdx.x >> 5) * 4;
    #pragma unroll
    for (int i = 0; i < 4; ++i) {
        int w = w0 + y + i;
        const float* srcrow;
        if (w < CM)      srcrow = xl_v + ((size_t)zb * CM + w) * CDV;
        else if (w < CW) srcrow = vv   + ((size_t)zb * CL + (w - CM)) * CDV;
        else             srcrow = aggu + ((size_t)zb * CS + (w - CW)) * CDV;
        tile[y + i][x] = srcrow[v0 + x];
    }
    __syncthreads();
    #pragma unroll
    for (int i = 0; i < 4; ++i) {
        size_t o = ((size_t)zb * CDV + v0 + y + i) * SCW + w0 + x;
        splitw(tile[x][y + i], vth + o, vtl + o);
    }
}

// ---------------------------------------------------------------------------
// Per-(b,l,h): warp-per-row LN(q)->qu/qv, LN(k)->kl (split), copy v, silu(g)
// ---------------------------------------------------------------------------
__global__ void __launch_bounds__(256) transform_kernel(const float* __restrict__ qraw,
                                                        const float* __restrict__ kvg,
                                                        const float* __restrict__ x_u,
                                                        const float* __restrict__ x_v,
                                                        bf16* __restrict__ quh, bf16* __restrict__ qul,
                                                        bf16* __restrict__ qvh, bf16* __restrict__ qvl,
                                                        bf16* __restrict__ klh, bf16* __restrict__ kll,
                                                        float* __restrict__ vv,
                                                        float* __restrict__ gate) {
    int wid  = threadIdx.x >> 5;
    int lane = threadIdx.x & 31;
    int idx = blockIdx.x * 8 + wid;      // (b*L+l)*H + h
    int h  = idx & 7;
    int bl = idx >> 3;
    int b = bl >> 9, l = bl & 511;
    int d0 = lane * 4;

    float4 q = *(const float4*)(qraw + (size_t)bl * CDM + h * CDK + d0);
    float mu = warp_sum(q.x + q.y + q.z + q.w) * (1.f / 128.f);
    q.x -= mu; q.y -= mu; q.z -= mu; q.w -= mu;
    float var = warp_sum(q.x * q.x + q.y * q.y + q.z * q.z + q.w * q.w) * (1.f / 128.f);
    float rs = rsqrtf(var + 1e-6f);
    float4 xu = *(const float4*)(x_u + h * CDK + d0);
    float4 xv = *(const float4*)(x_v + h * CDK + d0);
    size_t o = (((size_t)b * CH + h) * CL + l) * CDK + d0;
    split4(make_float4(q.x * rs + xu.x, q.y * rs + xu.y, q.z * rs + xu.z, q.w * rs + xu.w),
           quh + o, qul + o);
    split4(make_float4(q.x * rs + xv.x, q.y * rs + xv.y, q.z * rs + xv.z, q.w * rs + xv.w),
           qvh + o, qvl + o);

    float4 k = *(const float4*)(kvg + (size_t)bl * 3072 + h * CDK + d0);
    float kmu = warp_sum(k.x + k.y + k.z + k.w) * (1.f / 128.f);
    k.x -= kmu; k.y -= kmu; k.z -= kmu; k.w -= kmu;
    float kvar = warp_sum(k.x * k.x + k.y * k.y + k.z * k.z + k.w * k.w) * (1.f / 128.f);
    float krs = rsqrtf(kvar + 1e-6f);
    split4(make_float4(k.x * krs, k.y * krs, k.z * krs, k.w * krs), klh + o, kll + o);

    *(float4*)(vv + o) = *(const float4*)(kvg + (size_t)bl * 3072 + 1024 + h * CDK + d0);

    float4 gg = *(const float4*)(kvg + (size_t)bl * 3072 + 2048 + h * CDK + d0);
    float4 gs;
    gs.x = gg.x / (1.f + __expf(-gg.x));
    gs.y = gg.y / (1.f + __expf(-gg.y));
    gs.z = gg.z / (1.f + __expf(-gg.z));
    gs.w = gg.w / (1.f + __expf(-gg.w));
    *(float4*)(gate + (size_t)bl * CDM + h * CDK + d0) = gs;
}

__global__ void __launch_bounds__(128) csq_kernel(const float* __restrict__ cb,
                                                  float* __restrict__ csq) {
    int row = blockIdx.x;
    float v = cb[(size_t)row * CDK + threadIdx.x];
    v = block_sum(v * v);
    if (threadIdx.x == 0) csq[row] = v;
}

__global__ void zinit_kernel(unsigned long long* zpk) {
    zpk[blockIdx.x * 512 + threadIdx.x] = ~0ull;
}

// ---------------------------------------------------------------------------
// NT tensor-core GEMM (bf16x3, pre-split operands, cp.async 3-stage pipeline,
// ONE barrier per k-tile).
// MODE: 0=BD, 1=REC, 2=CACHE, 3=VQ, 4=PROJ(fp32 out), 5=WV(bf16 out * gate)
// smem: [stage3][hi/lo][row128][pitch24]
// ---------------------------------------------------------------------------
#define STG_B 12288   // stage stride bytes (2*128*24*2)
#define CMP_B 6144    // hi->lo stride bytes
template <int MODE>
__global__ void __launch_bounds__(256) mma_gemm_kernel(
    const bf16* __restrict__ Ah, const bf16* __restrict__ Al,
    const bf16* __restrict__ Bh, const bf16* __restrict__ Bl,
    const bf16* __restrict__ cbh, const bf16* __restrict__ cbl,
    const float* __restrict__ agg_lower, const float* __restrict__ csq,
    const unsigned long long* __restrict__ zpk_in, unsigned long long* zpk_out,
    const float* __restrict__ rbd_in, const float* __restrict__ gate,
    float* __restrict__ outp, bf16* __restrict__ outh, bf16* __restrict__ outl,
    int N, int K, int lda) {

    __shared__ __align__(16) bf16 SA[3][2][128][24];
    __shared__ __align__(16) bf16 SB[3][2][128][24];

    int tid  = threadIdx.x;
    int lane = tid & 31, warp = tid >> 5;
    int wm = warp >> 2, wn = warp & 3;
    int bm = blockIdx.y * 128;
    int bn = blockIdx.x * 128;
    int bh = blockIdx.z;
    int h  = bh & 7;

    if (MODE == 1 && bn >= bm + CM + 128) {     // fully masked tile
        for (int i = tid; i < 128 * 128; i += 256) {
            int r = i >> 7, c = i & 127;
            outp[((size_t)bh * CL + bm + r) * SCW + bn + c] = -1e30f;
        }
        return;
    }

    size_t aoff;
    if (MODE == 4)      aoff = 0;
    else if (MODE == 5) aoff = (size_t)bh * CL * SCW;
    else                aoff = (size_t)bh * CL * CDK;

    int srow = tid >> 1;
    int sc8  = (tid & 1) * 8;
    const bf16* a_h = Ah + aoff + (size_t)(bm + srow) * lda + sc8;
    const bf16* a_l = Al + aoff + (size_t)(bm + srow) * lda + sc8;
    const bf16 *b_h, *b_l;
    {
        int n = bn + srow;
        size_t boff;
        if (MODE == 0)      { boff = ((size_t)h * CW + n) * CDK; b_h = Bh + boff; b_l = Bl + boff; }
        else if (MODE == 1) {
            if (n < CM) { boff = ((size_t)bh * CM + n) * CDK; b_h = Bh + boff; b_l = Bl + boff; }
            else {
                unsigned zi = (unsigned)(zpk_in[(size_t)bh * CL + (n - CM)] & 0xffffffffull);
                boff = ((size_t)h * CS + zi) * CDK; b_h = cbh + boff; b_l = cbl + boff;
            }
        }
        else if (MODE == 2 || MODE == 3) { boff = ((size_t)h * CS + n) * CDK; b_h = Bh + boff; b_l = Bl + boff; }
        else if (MODE == 4) { boff = (size_t)n * K; b_h = Bh + boff; b_l = Bl + boff; }
        else                { boff = ((size_t)bh * CDV + n) * SCW; b_h = Bh + boff; b_l = Bl + boff; }
        b_h += sc8; b_l += sc8;
    }

    uint32_t sA = cvta_s(&SA[0][0][0][0]);
    uint32_t sB = cvta_s(&SB[0][0][0][0]);
    uint32_t dA = sA + (uint32_t)(srow * 24 + sc8) * 2;
    uint32_t dB = sB + (uint32_t)(srow * 24 + sc8) * 2;

    int a_off = (wm * 64 + (lane & 15)) * 24 + ((lane >> 4) << 3);
    int b_off = (wn * 32 + ((lane >> 4) << 3) + (lane & 7)) * 24 + (((lane >> 3) & 1) << 3);

    float acc[4][4][4] = {};
    int T = K >> 4;

    // stage 0 prefetch
    cpa16(dA,         a_h);  cpa16(dA + CMP_B, a_l);
    cpa16(dB,         b_h);  cpa16(dB + CMP_B, b_l);
    cpa_commit();

    #pragma unroll 1
    for (int kt = 0; kt < T; ++kt) {
        if (kt + 1 < T) {
            int st = (kt + 1) % 3;
            int k0 = (kt + 1) * 16;
            cpa16(dA + st * STG_B,         a_h + k0);
            cpa16(dA + st * STG_B + CMP_B, a_l + k0);
            cpa16(dB + st * STG_B,         b_h + k0);
            cpa16(dB + st * STG_B + CMP_B, b_l + k0);
            cpa_commit();
            cpa_wait<1>();
        } else {
            cpa_wait<0>();
        }
        __syncthreads();

        int cs = kt % 3;
        uint32_t aH = sA + cs * STG_B + (uint32_t)a_off * 2;
        uint32_t bH = sB + cs * STG_B + (uint32_t)b_off * 2;
        uint32_t ah[4][4], al[4][4], bhf[4][2], blf[4][2];
        #pragma unroll
        for (int t = 0; t < 4; ++t) {
            ldmx4(aH + t * 768,         ah[t][0], ah[t][1], ah[t][2], ah[t][3]);
            ldmx4(aH + CMP_B + t * 768, al[t][0], al[t][1], al[t][2], al[t][3]);
        }
        #pragma unroll
        for (int u2 = 0; u2 < 2; ++u2) {
            uint32_t r0, r1, r2, r3;
            ldmx4(bH + u2 * 768, r0, r1, r2, r3);
            bhf[2 * u2][0] = r0; bhf[2 * u2][1] = r1;
            bhf[2 * u2 + 1][0] = r2; bhf[2 * u2 + 1][1] = r3;
            ldmx4(bH + CMP_B + u2 * 768, r0, r1, r2, r3);
            blf[2 * u2][0] = r0; blf[2 * u2][1] = r1;
            blf[2 * u2 + 1][0] = r2; blf[2 * u2 + 1][1] = r3;
        }
        #pragma unroll
        for (int t = 0; t < 4; ++t)
            #pragma unroll
            for (int u = 0; u < 4; ++u) {
                mma16816(acc[t][u], ah[t], bhf[u]);
                mma16816(acc[t][u], ah[t], blf[u]);
                mma16816(acc[t][u], al[t], bhf[u]);
            }
        // NOTE: no trailing barrier — 3-stage ring makes the top barrier sufficient
    }

    // ---- epilogues ------------------------------------------------------
    int g  = lane >> 2;
    int qd = lane & 3;

    if constexpr (MODE == 4) {
        #pragma unroll
        for (int t = 0; t < 4; ++t) {
            int r = bm + wm * 64 + t * 16 + g;
            #pragma unroll
            for (int u = 0; u < 4; ++u) {
                int c = bn + wn * 32 + u * 8 + qd * 2;
                *(float2*)(outp + (size_t)r * N + c) =
                    make_float2(acc[t][u][0], acc[t][u][1]);
                *(float2*)(outp + (size_t)(r + 8) * N + c) =
                    make_float2(acc[t][u][2], acc[t][u][3]);
            }
        }
    } else if constexpr (MODE == 0) {
        #pragma unroll
        for (int t = 0; t < 4; ++t) {
            int l = bm + wm * 64 + t * 16 + g;
            #pragma unroll
            for (int u = 0; u < 4; ++u) {
                int c = bn + wn * 32 + u * 8 + qd * 2;
                *(float2*)(outp + ((size_t)bh * CL + l) * CW + c) =
                    make_float2(acc[t][u][0] * TAUI, acc[t][u][1] * TAUI);
                *(float2*)(outp + ((size_t)bh * CL + l + 8) * CW + c) =
                    make_float2(acc[t][u][2] * TAUI, acc[t][u][3] * TAUI);
            }
        }
    } else if constexpr (MODE == 1) {
        #pragma unroll
        for (int t = 0; t < 4; ++t) {
            int l0 = bm + wm * 64 + t * 16 + g;
            int l1 = l0 + 8;
            const float* rr0 = rbd_in + ((size_t)bh * CL + l0) * CW + (CL - 1) - l0;
            const float* rr1 = rbd_in + ((size_t)bh * CL + l1) * CW + (CL - 1) - l1;
            #pragma unroll
            for (int u = 0; u < 4; ++u) {
                int w = bn + wn * 32 + u * 8 + qd * 2;
                float2 o0, o1;
                o0.x = (w     <= l0 + CM) ? acc[t][u][0] * TAUI + rr0[w]     : -1e30f;
                o0.y = (w + 1 <= l0 + CM) ? acc[t][u][1] * TAUI + rr0[w + 1] : -1e30f;
                o1.x = (w     <= l1 + CM) ? acc[t][u][2] * TAUI + rr1[w]     : -1e30f;
                o1.y = (w + 1 <= l1 + CM) ? acc[t][u][3] * TAUI + rr1[w + 1] : -1e30f;
                *(float2*)(outp + ((size_t)bh * CL + l0) * SCW + w) = o0;
                *(float2*)(outp + ((size_t)bh * CL + l1) * SCW + w) = o1;
            }
        }
    } else if constexpr (MODE == 2) {
        #pragma unroll
        for (int t = 0; t < 4; ++t) {
            int l0 = bm + wm * 64 + t * 16 + g;
            #pragma unroll
            for (int u = 0; u < 4; ++u) {
                int s = bn + wn * 32 + u * 8 + qd * 2;
                float a0 = agg_lower[(size_t)bh * CS + s];
                float a1 = agg_lower[(size_t)bh * CS + s + 1];
                float b0 = (a0 > 0.f) ? logf(fmaxf(a0, 1e-30f)) : -1e30f;
                float b1 = (a1 > 0.f) ? logf(fmaxf(a1, 1e-30f)) : -1e30f;
                *(float2*)(outp + ((size_t)bh * CL + l0) * SCW + CW + s) =
                    make_float2(acc[t][u][0] * TAUI + b0, acc[t][u][1] * TAUI + b1);
                *(float2*)(outp + ((size_t)bh * CL + l0 + 8) * SCW + CW + s) =
                    make_float2(acc[t][u][2] * TAUI + b0, acc[t][u][3] * TAUI + b1);
            }
        }
    } else if constexpr (MODE == 3) {
        unsigned long long* zmin = reinterpret_cast<unsigned long long*>(&SA[0][0][0][0]);
        __syncthreads();                      // all warps past final ldmatrix
        if (tid < 128) zmin[tid] = ~0ull;
        __syncthreads();
        #pragma unroll
        for (int t = 0; t < 4; ++t) {
            unsigned long long b0 = ~0ull, b1 = ~0ull;
            #pragma unroll
            for (int u = 0; u < 4; ++u) {
                #pragma unroll
                for (int p = 0; p < 2; ++p) {
                    int s = bn + wn * 32 + u * 8 + qd * 2 + p;
                    float cs = csq[h * CS + s];
                    {
                        float val = cs - 2.f * acc[t][u][p];
                        unsigned uu = __float_as_uint(val);
                        uu = (uu & 0x80000000u) ? ~uu : (uu | 0x80000000u);
                        unsigned long long key = ((unsigned long long)uu << 32) | (unsigned)s;
                        if (key < b0) b0 = key;
                    }
                    {
                        float val = cs - 2.f * acc[t][u][2 + p];
                        unsigned uu = __float_as_uint(val);
                        uu = (uu & 0x80000000u) ? ~uu : (uu | 0x80000000u);
                        unsigned long long key = ((unsigned long long)uu << 32) | (unsigned)s;
                        if (key < b1) b1 = key;
                    }
                }
            }
            unsigned long long o;
            o = __shfl_xor_sync(0xffffffffu, b0, 1); if (o < b0) b0 = o;
            o = __shfl_xor_sync(0xffffffffu, b0, 2); if (o < b0) b0 = o;
            o = __shfl_xor_sync(0xffffffffu, b1, 1); if (o < b1) b1 = o;
            o = __shfl_xor_sync(0xffffffffu, b1, 2); if (o < b1) b1 = o;
            if (qd == 0) {
                atomicMin(&zmin[wm * 64 + t * 16 + g], b0);
                atomicMin(&zmin[wm * 64 + t * 16 + g + 8], b1);
            }
        }
        __syncthreads();
        if (tid < 128)
            atomicMin(&zpk_out[(size_t)bh * CL + bm + tid], zmin[tid]);
    } else {                                          // MODE 5: wv * gate -> bf16 hi/lo
        int b = bh >> 3;
        #pragma unroll
        for (int t = 0; t < 4; ++t) {
            int l = bm + wm * 64 + t * 16 + g;
            #pragma unroll
            for (int u = 0; u < 4; ++u) {
                int c = wn * 32 + u * 8 + qd * 2;
                size_t o0 = ((size_t)b * CL + l) * CDM + h * CDV + c;
                size_t o1 = ((size_t)b * CL + l + 8) * CDM + h * CDV + c;
                float2 g0 = *(const float2*)(gate + o0);
                float2 g1 = *(const float2*)(gate + o1);
                splitw(acc[t][u][0] * g0.x, outh + o0,     outl + o0);
                splitw(acc[t][u][1] * g0.y, outh + o0 + 1, outl + o0 + 1);
                splitw(acc[t][u][2] * g1.x, outh + o1,     outl + o1);
                splitw(acc[t][u][3] * g1.y, outh + o1 + 1, outl + o1 + 1);
            }
        }
    }
}

// ---------------------------------------------------------------------------
// Joint softmax over 1536 keys -> bf16 hi/lo probabilities
// ---------------------------------------------------------------------------
__global__ void __launch_bounds__(256) softmax_kernel(const float* __restrict__ scores,
                                                      bf16* __restrict__ ph,
                                                      bf16* __restrict__ pl) {
    const float* row = scores + (size_t)blockIdx.x * SCW;
    size_t ob = (size_t)blockIdx.x * SCW;
    int tid = threadIdx.x;
    __shared__ float sb[8];
    float v[6];
    float m = -3.4e38f;
    #pragma unroll
    for (int i = 0; i < 6; ++i) { v[i] = row[tid + i * 256]; m = fmaxf(m, v[i]); }
    #pragma unroll
    for (int o = 16; o; o >>= 1) m = fmaxf(m, __shfl_down_sync(0xffffffffu, m, o));
    if ((tid & 31) == 0) sb[tid >> 5] = m;
    __syncthreads();
    m = sb[0];
    #pragma unroll
    for (int i = 1; i < 8; ++i) m = fmaxf(m, sb[i]);
    __syncthreads();
    float s = 0.f;
    #pragma unroll
    for (int i = 0; i < 6; ++i) { v[i] = __expf(v[i] - m); s += v[i]; }
    #pragma unroll
    for (int o = 16; o; o >>= 1) s += __shfl_down_sync(0xffffffffu, s, o);
    if ((tid & 31) == 0) sb[tid >> 5] = s;
    __syncthreads();
    float tot = sb[0];
    #pragma unroll
    for (int i = 1; i < 8; ++i) tot += sb[i];
    float inv = 1.f / tot;
    #pragma unroll
    for (int i = 0; i < 6; ++i)
        splitw(v[i] * inv, ph + ob + tid + i * 256, pl + ob + tid + i * 256);
}

// ---------------------------------------------------------------------------
// Host launcher
// ---------------------------------------------------------------------------
extern "C" void kernel_launch(void* const* d_in, const int* in_sizes, int n_in,
                              void* d_out, int out_size) {
    const float* input     = (const float*)d_in[0];
    const float* xl_k_hat  = (const float*)d_in[2];
    const float* xl_v      = (const float*)d_in[3];
    const float* agg_upper = (const float*)d_in[4];
    const float* agg_lower = (const float*)d_in[5];
    const float* W_q       = (const float*)d_in[6];
    const float* W_kvg     = (const float*)d_in[7];
    const float* W_res     = (const float*)d_in[8];
    const float* x_u       = (const float*)d_in[9];
    const float* x_v       = (const float*)d_in[10];
    const float* xl_r      = (const float*)d_in[11];
    const float* codebook  = (const float*)d_in[12];
    float* out = (float*)d_out;

    float *qraw, *kvg, *vv, *gate, *rbd, *scores, *csq;
    unsigned long long* zpk;
    bf16 *xt_h, *xt_l, *wqt_h, *wqt_l, *wkvgt_h, *wkvgt_l, *wrest_h, *wrest_l;
    bf16 *qu_h, *qu_l, *qv_h, *qv_l, *kl_h, *kl_l, *khat_h, *khat_l;
    bf16 *cb_h, *cb_l, *xlr_h, *xlr_l, *vt_h, *vt_l, *p_h, *p_l, *wvg_h, *wvg_l;

    cudaGetSymbolAddress((void**)&qraw, g_qraw);
    cudaGetSymbolAddress((void**)&kvg, g_kvg);
    cudaGetSymbolAddress((void**)&vv, g_vv);
    cudaGetSymbolAddress((void**)&gate, g_gate);
    cudaGetSymbolAddress((void**)&rbd, g_rbd);
    cudaGetSymbolAddress((void**)&scores, g_scores);
    cudaGetSymbolAddress((void**)&csq, g_csq);
    cudaGetSymbolAddress((void**)&zpk, g_zpk);
    cudaGetSymbolAddress((void**)&xt_h, g_xt_h);   cudaGetSymbolAddress((void**)&xt_l, g_xt_l);
    cudaGetSymbolAddress((void**)&wqt_h, g_wqt_h); cudaGetSymbolAddress((void**)&wqt_l, g_wqt_l);
    cudaGetSymbolAddress((void**)&wkvgt_h, g_wkvgt_h); cudaGetSymbolAddress((void**)&wkvgt_l, g_wkvgt_l);
    cudaGetSymbolAddress((void**)&wrest_h, g_wrest_h); cudaGetSymbolAddress((void**)&wrest_l, g_wrest_l);
    cudaGetSymbolAddress((void**)&qu_h, g_qu_h);   cudaGetSymbolAddress((void**)&qu_l, g_qu_l);
    cudaGetSymbolAddress((void**)&qv_h, g_qv_h);   cudaGetSymbolAddress((void**)&qv_l, g_qv_l);
    cudaGetSymbolAddress((void**)&kl_h, g_kl_h);   cudaGetSymbolAddress((void**)&kl_l, g_kl_l);
    cudaGetSymbolAddress((void**)&khat_h, g_khat_h); cudaGetSymbolAddress((void**)&khat_l, g_khat_l);
    cudaGetSymbolAddress((void**)&cb_h, g_cb_h);   cudaGetSymbolAddress((void**)&cb_l, g_cb_l);
    cudaGetSymbolAddress((void**)&xlr_h, g_xlr_h); cudaGetSymbolAddress((void**)&xlr_l, g_xlr_l);
    cudaGetSymbolAddress((void**)&vt_h, g_vt_h);   cudaGetSymbolAddress((void**)&vt_l, g_vt_l);
    cudaGetSymbolAddress((void**)&p_h, g_p_h);     cudaGetSymbolAddress((void**)&p_l, g_p_l);
    cudaGetSymbolAddress((void**)&wvg_h, g_wvg_h); cudaGetSymbolAddress((void**)&wvg_l, g_wvg_l);

    // input converts / transposes
    transpose_kernel<<<dim3(32, 32), 256>>>(W_q, wqt_h, wqt_l, 1024, 1024);
    transpose_kernel<<<dim3(96, 32), 256>>>(W_kvg, wkvgt_h, wkvgt_l, 1024, 3072);
    transpose_kernel<<<dim3(32, 32), 256>>>(W_res, wrest_h, wrest_l, 1024, 1024);
    convert_hl_kernel<<<(NBH * CM * CDK) / 1024, 256>>>(xl_k_hat, khat_h, khat_l);
    convert_hl_kernel<<<(CH * CS * CDK) / 1024, 256>>>(codebook, cb_h, cb_l);
    convert_hl_kernel<<<(CH * CW * CDK) / 1024, 256>>>(xl_r, xlr_h, xlr_l);
    csq_kernel<<<CH * CS, 128>>>(codebook, csq);
    zinit_kernel<<<NBH, 512>>>(zpk);

    // 1. LN(input)
    ln_rows_kernel<<<NROWS, 256>>>(input, xt_h, xt_l);

    // 2. projections
    mma_gemm_kernel<4><<<dim3(8, 32, 1), 256>>>(xt_h, xt_l, wqt_h, wqt_l, nullptr, nullptr,
        nullptr, nullptr, nullptr, nullptr, nullptr, nullptr, qraw, nullptr, nullptr,
        1024, 1024, 1024);
    mma_gemm_kernel<4><<<dim3(24, 32, 1), 256>>>(xt_h, xt_l, wkvgt_h, wkvgt_l, nullptr, nullptr,
        nullptr, nullptr, nullptr, nullptr, nullptr, nullptr, kvg, nullptr, nullptr,
        3072, 1024, 1024);

    // 3. per-head LN, biases, silu (warp-per-row)
    transform_kernel<<<NROWS * CH / 8, 256>>>(qraw, kvg, x_u, x_v,
                                              qu_h, qu_l, qv_h, qv_l, kl_h, kl_l, vv, gate);

    // 4. V gather-transpose
    vt_kernel<<<dim3(SCW / 32, CDV / 32, NBH), 256>>>(xl_v, vv, agg_upper, vt_h, vt_l);

    // 5. VQ argmin
    mma_gemm_kernel<3><<<dim3(4, 4, NBH), 256>>>(kl_h, kl_l, cb_h, cb_l, cb_h, cb_l,
        nullptr, csq, nullptr, zpk, nullptr, nullptr, nullptr, nullptr, nullptr,
        512, 128, 128);

    // 6. scores
    mma_gemm_kernel<0><<<dim3(8, 4, NBH), 256>>>(qv_h, qv_l, xlr_h, xlr_l, nullptr, nullptr,
        nullptr, nullptr, nullptr, nullptr, nullptr, nullptr, rbd, nullptr, nullptr,
        1024, 128, 128);
    mma_gemm_kernel<1><<<dim3(8, 4, NBH), 256>>>(qu_h, qu_l, khat_h, khat_l, cb_h, cb_l,
        nullptr, nullptr, zpk, nullptr, rbd, nullptr, scores, nullptr, nullptr,
        1024, 128, 128);
    mma_gemm_kernel<2><<<dim3(4, 4, NBH), 256>>>(qu_h, qu_l, cb_h, cb_l, nullptr, nullptr,
        agg_lower, nullptr, nullptr, nullptr, nullptr, nullptr, scores, nullptr, nullptr,
        512, 128, 128);

    // 7. joint softmax -> bf16 probs
    softmax_kernel<<<NBH * CL, 256>>>(scores, p_h, p_l);

    // 8. weighted values (fused * gate) -> bf16 hi/lo
    mma_gemm_kernel<5><<<dim3(1, 4, NBH), 256>>>(p_h, p_l, vt_h, vt_l, nullptr, nullptr,
        nullptr, nullptr, nullptr, nullptr, nullptr, gate, nullptr, wvg_h, wvg_l,
        128, 1536, 1536);

    // 9. output projection
    mma_gemm_kernel<4><<<dim3(8, 32, 1), 256>>>(wvg_h, wvg_l, wrest_h, wrest_l, nullptr, nullptr,
        nullptr, nullptr, nullptr, nullptr, nullptr, nullptr, out, nullptr, nullptr,
        1024, 1024, 1024);
}

// round 8
// speedup vs baseline: 2.2823x; 1.0070x over previous
#include <cuda_runtime.h>
#include <cuda_bf16.h>
#include <cstdint>

// ---------------------------------------------------------------------------
// Problem constants
// ---------------------------------------------------------------------------
#define CB   8
#define CL   512
#define CM   512
#define CH   8
#define CDK  128
#define CDV  128
#define CS   512
#define CDM  1024
#define CW   1024   // W_REC
#define NBH  64
#define NROWS 4096
#define SCW  1536   // W + S

static __device__ __constant__ const float TAUI = 0.08838834764831845f; // 1/sqrt(128)

typedef __nv_bfloat16 bf16;

// ---------------------------------------------------------------------------
// Scratch
// ---------------------------------------------------------------------------
__device__ float g_qraw  [(size_t)NROWS * CDM];
__device__ float g_kvg   [(size_t)NROWS * 3072];
__device__ float g_vv    [(size_t)NBH * CL * CDV];
__device__ float g_gate  [(size_t)NROWS * CDM];
__device__ float g_rbd   [(size_t)NBH * CL * CW];
__device__ unsigned long long g_zpk[NBH * CL];
__device__ float g_csq   [CH * CS];

__device__ bf16 g_xt_h   [(size_t)NROWS * CDM];
__device__ bf16 g_xt_l   [(size_t)NROWS * CDM];
__device__ bf16 g_wqt_h  [(size_t)1024 * 1024];
__device__ bf16 g_wqt_l  [(size_t)1024 * 1024];
__device__ bf16 g_wkvgt_h[(size_t)3072 * 1024];
__device__ bf16 g_wkvgt_l[(size_t)3072 * 1024];
__device__ bf16 g_wrest_h[(size_t)1024 * 1024];
__device__ bf16 g_wrest_l[(size_t)1024 * 1024];
__device__ bf16 g_qu_h   [(size_t)NBH * CL * CDK];
__device__ bf16 g_qu_l   [(size_t)NBH * CL * CDK];
__device__ bf16 g_qv_h   [(size_t)NBH * CL * CDK];
__device__ bf16 g_qv_l   [(size_t)NBH * CL * CDK];
__device__ bf16 g_kl_h   [(size_t)NBH * CL * CDK];
__device__ bf16 g_kl_l   [(size_t)NBH * CL * CDK];
__device__ bf16 g_khat_h [(size_t)NBH * CM * CDK];
__device__ bf16 g_khat_l [(size_t)NBH * CM * CDK];
__device__ bf16 g_cb_h   [(size_t)CH * CS * CDK];
__device__ bf16 g_cb_l   [(size_t)CH * CS * CDK];
__device__ bf16 g_xlr_h  [(size_t)CH * CW * CDK];
__device__ bf16 g_xlr_l  [(size_t)CH * CW * CDK];
__device__ bf16 g_vt_h   [(size_t)NBH * CDV * SCW];
__device__ bf16 g_vt_l   [(size_t)NBH * CDV * SCW];
__device__ bf16 g_wvg_h  [(size_t)NROWS * CDM];
__device__ bf16 g_wvg_l  [(size_t)NROWS * CDM];

// ---------------------------------------------------------------------------
// primitives
// ---------------------------------------------------------------------------
__device__ __forceinline__ uint32_t cvta_s(const void* p) {
    return (uint32_t)__cvta_generic_to_shared(p);
}
__device__ __forceinline__ void ldmx4(uint32_t addr, uint32_t& r0, uint32_t& r1,
                                      uint32_t& r2, uint32_t& r3) {
    asm volatile("ldmatrix.sync.aligned.m8n8.x4.shared.b16 {%0,%1,%2,%3}, [%4];"
                 : "=r"(r0), "=r"(r1), "=r"(r2), "=r"(r3) : "r"(addr));
}
__device__ __forceinline__ void mma16816(float c[4], const uint32_t a[4], const uint32_t b[2]) {
    asm volatile(
        "mma.sync.aligned.m16n8k16.row.col.f32.bf16.bf16.f32 "
        "{%0,%1,%2,%3}, {%4,%5,%6,%7}, {%8,%9}, {%0,%1,%2,%3};"
        : "+f"(c[0]), "+f"(c[1]), "+f"(c[2]), "+f"(c[3])
        : "r"(a[0]), "r"(a[1]), "r"(a[2]), "r"(a[3]), "r"(b[0]), "r"(b[1]));
}
__device__ __forceinline__ void cpa16(uint32_t d, const void* s) {
    asm volatile("cp.async.ca.shared.global [%0], [%1], 16;" :: "r"(d), "l"(s));
}
__device__ __forceinline__ void cpa_commit() {
    asm volatile("cp.async.commit_group;");
}
template <int NN>
__device__ __forceinline__ void cpa_wait() {
    asm volatile("cp.async.wait_group %0;" :: "n"(NN));
}

__device__ __forceinline__ void splitw(float x, bf16* h, bf16* l) {
    bf16 hh = __float2bfloat16_rn(x);
    *h = hh;
    *l = __float2bfloat16_rn(x - __bfloat162float(hh));
}
__device__ __forceinline__ void split4(float4 v, bf16* hp, bf16* lp) {
    __nv_bfloat162 h0 = __floats2bfloat162_rn(v.x, v.y);
    __nv_bfloat162 h1 = __floats2bfloat162_rn(v.z, v.w);
    float2 f0 = __bfloat1622float2(h0);
    float2 f1 = __bfloat1622float2(h1);
    __nv_bfloat162 l0 = __floats2bfloat162_rn(v.x - f0.x, v.y - f0.y);
    __nv_bfloat162 l1 = __floats2bfloat162_rn(v.z - f1.x, v.w - f1.y);
    uint2 hv, lv;
    hv.x = *(uint32_t*)&h0; hv.y = *(uint32_t*)&h1;
    lv.x = *(uint32_t*)&l0; lv.y = *(uint32_t*)&l1;
    *(uint2*)hp = hv;
    *(uint2*)lp = lv;
}
__device__ __forceinline__ uint32_t packbf(float x, float y) {
    __nv_bfloat162 t = __floats2bfloat162_rn(x, y);
    return *(uint32_t*)&t;
}
__device__ __forceinline__ uint32_t packbf_res(float x, float y, uint32_t hp) {
    __nv_bfloat162 hv = *(__nv_bfloat162*)&hp;
    float2 f = __bfloat1622float2(hv);
    return packbf(x - f.x, y - f.y);
}

// ---------------------------------------------------------------------------
// reductions
// ---------------------------------------------------------------------------
__device__ __forceinline__ float block_sum(float v) {
    __shared__ float sb_[8];
    int tid = threadIdx.x;
    int nw  = blockDim.x >> 5;
    #pragma unroll
    for (int o = 16; o; o >>= 1) v += __shfl_down_sync(0xffffffffu, v, o);
    __syncthreads();
    if ((tid & 31) == 0) sb_[tid >> 5] = v;
    __syncthreads();
    float r = 0.f;
    for (int i = 0; i < nw; ++i) r += sb_[i];
    return r;
}
__device__ __forceinline__ float warp_sum(float v) {
    #pragma unroll
    for (int o = 16; o; o >>= 1) v += __shfl_xor_sync(0xffffffffu, v, o);
    return v;
}

// ---------------------------------------------------------------------------
// LayerNorm over DM=1024 -> bf16 hi/lo
// ---------------------------------------------------------------------------
__global__ void __launch_bounds__(256) ln_rows_kernel(const float* __restrict__ x,
                                                      bf16* __restrict__ yh,
                                                      bf16* __restrict__ yl) {
    int row = blockIdx.x;
    const float* xr = x + (size_t)row * CDM;
    int tid = threadIdx.x;
    float4 v = *(const float4*)(xr + tid * 4);
    float s = v.x + v.y + v.z + v.w;
    float mu = block_sum(s) * (1.f / 1024.f);
    v.x -= mu; v.y -= mu; v.z -= mu; v.w -= mu;
    float s2 = v.x * v.x + v.y * v.y + v.z * v.z + v.w * v.w;
    float rstd = rsqrtf(block_sum(s2) * (1.f / 1024.f) + 1e-6f);
    v.x *= rstd; v.y *= rstd; v.z *= rstd; v.w *= rstd;
    split4(v, yh + (size_t)row * CDM + tid * 4, yl + (size_t)row * CDM + tid * 4);
}

__global__ void __launch_bounds__(256) convert_hl_kernel(const float* __restrict__ src,
                                                         bf16* __restrict__ h,
                                                         bf16* __restrict__ l) {
    size_t idx = (size_t)blockIdx.x * 256 + threadIdx.x;
    float4 v = ((const float4*)src)[idx];
    split4(v, h + idx * 4, l + idx * 4);
}

__global__ void __launch_bounds__(256) transpose_kernel(const float* __restrict__ src,
                                                        bf16* __restrict__ dsth,
                                                        bf16* __restrict__ dstl,
                                                        int R, int C) {
    __shared__ float tile[32][33];
    int c0 = blockIdx.x * 32, r0 = blockIdx.y * 32;
    int x = threadIdx.x & 31, y = (threadIdx.x >> 5) * 4;
    #pragma unroll
    for (int i = 0; i < 4; ++i)
        tile[y + i][x] = src[(size_t)(r0 + y + i) * C + c0 + x];
    __syncthreads();
    #pragma unroll
    for (int i = 0; i < 4; ++i) {
        size_t o = (size_t)(c0 + y + i) * R + r0 + x;
        splitw(tile[x][y + i], dsth + o, dstl + o);
    }
}

__global__ void __launch_bounds__(256) vt_kernel(const float* __restrict__ xl_v,
                                                 const float* __restrict__ vv,
                                                 const float* __restrict__ aggu,
                                                 bf16* __restrict__ vth,
                                                 bf16* __restrict__ vtl) {
    __shared__ float tile[32][33];
    int zb = blockIdx.z;
    int w0 = blockIdx.x * 32, v0 = blockIdx.y * 32;
    int x = threadIdx.x & 31, y = (threadIdx.x >> 5) * 4;
    #pragma unroll
    for (int i = 0; i < 4; ++i) {
        int w = w0 + y + i;
        const float* srcrow;
        if (w < CM)      srcrow = xl_v + ((size_t)zb * CM + w) * CDV;
        else if (w < CW) srcrow = vv   + ((size_t)zb * CL + (w - CM)) * CDV;
        else             srcrow = aggu + ((size_t)zb * CS + (w - CW)) * CDV;
        tile[y + i][x] = srcrow[v0 + x];
    }
    __syncthreads();
    #pragma unroll
    for (int i = 0; i < 4; ++i) {
        size_t o = ((size_t)zb * CDV + v0 + y + i) * SCW + w0 + x;
        splitw(tile[x][y + i], vth + o, vtl + o);
    }
}

__global__ void __launch_bounds__(256) transform_kernel(const float* __restrict__ qraw,
                                                        const float* __restrict__ kvg,
                                                        const float* __restrict__ x_u,
                                                        const float* __restrict__ x_v,
                                                        bf16* __restrict__ quh, bf16* __restrict__ qul,
                                                        bf16* __restrict__ qvh, bf16* __restrict__ qvl,
                                                        bf16* __restrict__ klh, bf16* __restrict__ kll,
                                                        float* __restrict__ vv,
                                                        float* __restrict__ gate) {
    int wid  = threadIdx.x >> 5;
    int lane = threadIdx.x & 31;
    int idx = blockIdx.x * 8 + wid;
    int h  = idx & 7;
    int bl = idx >> 3;
    int b = bl >> 9, l = bl & 511;
    int d0 = lane * 4;

    float4 q = *(const float4*)(qraw + (size_t)bl * CDM + h * CDK + d0);
    float mu = warp_sum(q.x + q.y + q.z + q.w) * (1.f / 128.f);
    q.x -= mu; q.y -= mu; q.z -= mu; q.w -= mu;
    float var = warp_sum(q.x * q.x + q.y * q.y + q.z * q.z + q.w * q.w) * (1.f / 128.f);
    float rs = rsqrtf(var + 1e-6f);
    float4 xu = *(const float4*)(x_u + h * CDK + d0);
    float4 xv = *(const float4*)(x_v + h * CDK + d0);
    size_t o = (((size_t)b * CH + h) * CL + l) * CDK + d0;
    split4(make_float4(q.x * rs + xu.x, q.y * rs + xu.y, q.z * rs + xu.z, q.w * rs + xu.w),
           quh + o, qul + o);
    split4(make_float4(q.x * rs + xv.x, q.y * rs + xv.y, q.z * rs + xv.z, q.w * rs + xv.w),
           qvh + o, qvl + o);

    float4 k = *(const float4*)(kvg + (size_t)bl * 3072 + h * CDK + d0);
    float kmu = warp_sum(k.x + k.y + k.z + k.w) * (1.f / 128.f);
    k.x -= kmu; k.y -= kmu; k.z -= kmu; k.w -= kmu;
    float kvar = warp_sum(k.x * k.x + k.y * k.y + k.z * k.z + k.w * k.w) * (1.f / 128.f);
    float krs = rsqrtf(kvar + 1e-6f);
    split4(make_float4(k.x * krs, k.y * krs, k.z * krs, k.w * krs), klh + o, kll + o);

    *(float4*)(vv + o) = *(const float4*)(kvg + (size_t)bl * 3072 + 1024 + h * CDK + d0);

    float4 gg = *(const float4*)(kvg + (size_t)bl * 3072 + 2048 + h * CDK + d0);
    float4 gs;
    gs.x = gg.x / (1.f + __expf(-gg.x));
    gs.y = gg.y / (1.f + __expf(-gg.y));
    gs.z = gg.z / (1.f + __expf(-gg.z));
    gs.w = gg.w / (1.f + __expf(-gg.w));
    *(float4*)(gate + (size_t)bl * CDM + h * CDK + d0) = gs;
}

__global__ void __launch_bounds__(128) csq_kernel(const float* __restrict__ cb,
                                                  float* __restrict__ csq) {
    int row = blockIdx.x;
    float v = cb[(size_t)row * CDK + threadIdx.x];
    v = block_sum(v * v);
    if (threadIdx.x == 0) csq[row] = v;
}

__global__ void zinit_kernel(unsigned long long* zpk) {
    zpk[blockIdx.x * 512 + threadIdx.x] = ~0ull;
}

// ---------------------------------------------------------------------------
// NT tensor-core GEMM (bf16x3, 3-stage cp.async). MODE: 0=BD, 3=VQ, 4=PROJ
// ---------------------------------------------------------------------------
#define STG_B 12288
#define CMP_B 6144
template <int MODE>
__global__ void __launch_bounds__(256) mma_gemm_kernel(
    const bf16* __restrict__ Ah, const bf16* __restrict__ Al,
    const bf16* __restrict__ Bh, const bf16* __restrict__ Bl,
    const float* __restrict__ csq,
    unsigned long long* zpk_out,
    float* __restrict__ outp,
    int N, int K, int lda) {

    __shared__ __align__(16) bf16 SA[3][2][128][24];
    __shared__ __align__(16) bf16 SB[3][2][128][24];

    int tid  = threadIdx.x;
    int lane = tid & 31, warp = tid >> 5;
    int wm = warp >> 2, wn = warp & 3;
    int bm = blockIdx.y * 128;
    int bn = blockIdx.x * 128;
    int bh = blockIdx.z;
    int h  = bh & 7;

    size_t aoff = (MODE == 4) ? 0 : (size_t)bh * CL * CDK;

    int srow = tid >> 1;
    int sc8  = (tid & 1) * 8;
    const bf16* a_h = Ah + aoff + (size_t)(bm + srow) * lda + sc8;
    const bf16* a_l = Al + aoff + (size_t)(bm + srow) * lda + sc8;
    const bf16 *b_h, *b_l;
    {
        int n = bn + srow;
        size_t boff;
        if (MODE == 0)      boff = ((size_t)h * CW + n) * CDK;
        else if (MODE == 3) boff = ((size_t)h * CS + n) * CDK;
        else                boff = (size_t)n * K;
        b_h = Bh + boff + sc8; b_l = Bl + boff + sc8;
    }

    uint32_t sA = cvta_s(&SA[0][0][0][0]);
    uint32_t sB = cvta_s(&SB[0][0][0][0]);
    uint32_t dA = sA + (uint32_t)(srow * 24 + sc8) * 2;
    uint32_t dB = sB + (uint32_t)(srow * 24 + sc8) * 2;

    int a_off = (wm * 64 + (lane & 15)) * 24 + ((lane >> 4) << 3);
    int b_off = (wn * 32 + ((lane >> 4) << 3) + (lane & 7)) * 24 + (((lane >> 3) & 1) << 3);

    float acc[4][4][4] = {};
    int T = K >> 4;

    cpa16(dA,         a_h);  cpa16(dA + CMP_B, a_l);
    cpa16(dB,         b_h);  cpa16(dB + CMP_B, b_l);
    cpa_commit();

    #pragma unroll 1
    for (int kt = 0; kt < T; ++kt) {
        if (kt + 1 < T) {
            int st = (kt + 1) % 3;
            int k0 = (kt + 1) * 16;
            cpa16(dA + st * STG_B,         a_h + k0);
            cpa16(dA + st * STG_B + CMP_B, a_l + k0);
            cpa16(dB + st * STG_B,         b_h + k0);
            cpa16(dB + st * STG_B + CMP_B, b_l + k0);
            cpa_commit();
            cpa_wait<1>();
        } else {
            cpa_wait<0>();
        }
        __syncthreads();

        int cs = kt % 3;
        uint32_t aH = sA + cs * STG_B + (uint32_t)a_off * 2;
        uint32_t bH = sB + cs * STG_B + (uint32_t)b_off * 2;
        uint32_t ah[4][4], al[4][4], bhf[4][2], blf[4][2];
        #pragma unroll
        for (int t = 0; t < 4; ++t) {
            ldmx4(aH + t * 768,         ah[t][0], ah[t][1], ah[t][2], ah[t][3]);
            ldmx4(aH + CMP_B + t * 768, al[t][0], al[t][1], al[t][2], al[t][3]);
        }
        #pragma unroll
        for (int u2 = 0; u2 < 2; ++u2) {
            uint32_t r0, r1, r2, r3;
            ldmx4(bH + u2 * 768, r0, r1, r2, r3);
            bhf[2 * u2][0] = r0; bhf[2 * u2][1] = r1;
            bhf[2 * u2 + 1][0] = r2; bhf[2 * u2 + 1][1] = r3;
            ldmx4(bH + CMP_B + u2 * 768, r0, r1, r2, r3);
            blf[2 * u2][0] = r0; blf[2 * u2][1] = r1;
            blf[2 * u2 + 1][0] = r2; blf[2 * u2 + 1][1] = r3;
        }
        #pragma unroll
        for (int t = 0; t < 4; ++t)
            #pragma unroll
            for (int u = 0; u < 4; ++u) {
                mma16816(acc[t][u], ah[t], bhf[u]);
                mma16816(acc[t][u], ah[t], blf[u]);
                mma16816(acc[t][u], al[t], bhf[u]);
            }
    }

    int g  = lane >> 2;
    int qd = lane & 3;

    if constexpr (MODE == 4) {
        #pragma unroll
        for (int t = 0; t < 4; ++t) {
            int r = bm + wm * 64 + t * 16 + g;
            #pragma unroll
            for (int u = 0; u < 4; ++u) {
                int c = bn + wn * 32 + u * 8 + qd * 2;
                *(float2*)(outp + (size_t)r * N + c) =
                    make_float2(acc[t][u][0], acc[t][u][1]);
                *(float2*)(outp + (size_t)(r + 8) * N + c) =
                    make_float2(acc[t][u][2], acc[t][u][3]);
            }
        }
    } else if constexpr (MODE == 0) {
        #pragma unroll
        for (int t = 0; t < 4; ++t) {
            int l = bm + wm * 64 + t * 16 + g;
            #pragma unroll
            for (int u = 0; u < 4; ++u) {
                int c = bn + wn * 32 + u * 8 + qd * 2;
                *(float2*)(outp + ((size_t)bh * CL + l) * CW + c) =
                    make_float2(acc[t][u][0] * TAUI, acc[t][u][1] * TAUI);
                *(float2*)(outp + ((size_t)bh * CL + l + 8) * CW + c) =
                    make_float2(acc[t][u][2] * TAUI, acc[t][u][3] * TAUI);
            }
        }
    } else {   // MODE 3: VQ argmin
        unsigned long long* zmin = reinterpret_cast<unsigned long long*>(&SA[0][0][0][0]);
        __syncthreads();
        if (tid < 128) zmin[tid] = ~0ull;
        __syncthreads();
        #pragma unroll
        for (int t = 0; t < 4; ++t) {
            unsigned long long b0 = ~0ull, b1 = ~0ull;
            #pragma unroll
            for (int u = 0; u < 4; ++u) {
                #pragma unroll
                for (int p = 0; p < 2; ++p) {
                    int s = bn + wn * 32 + u * 8 + qd * 2 + p;
                    float cs = csq[h * CS + s];
                    {
                        float val = cs - 2.f * acc[t][u][p];
                        unsigned uu = __float_as_uint(val);
                        uu = (uu & 0x80000000u) ? ~uu : (uu | 0x80000000u);
                        unsigned long long key = ((unsigned long long)uu << 32) | (unsigned)s;
                        if (key < b0) b0 = key;
                    }
                    {
                        float val = cs - 2.f * acc[t][u][2 + p];
                        unsigned uu = __float_as_uint(val);
                        uu = (uu & 0x80000000u) ? ~uu : (uu | 0x80000000u);
                        unsigned long long key = ((unsigned long long)uu << 32) | (unsigned)s;
                        if (key < b1) b1 = key;
                    }
                }
            }
            unsigned long long o;
            o = __shfl_xor_sync(0xffffffffu, b0, 1); if (o < b0) b0 = o;
            o = __shfl_xor_sync(0xffffffffu, b0, 2); if (o < b0) b0 = o;
            o = __shfl_xor_sync(0xffffffffu, b1, 1); if (o < b1) b1 = o;
            o = __shfl_xor_sync(0xffffffffu, b1, 2); if (o < b1) b1 = o;
            if (qd == 0) {
                atomicMin(&zmin[wm * 64 + t * 16 + g], b0);
                atomicMin(&zmin[wm * 64 + t * 16 + g + 8], b1);
            }
        }
        __syncthreads();
        if (tid < 128)
            atomicMin(&zpk_out[(size_t)bh * CL + bm + tid], zmin[tid]);
    }
}

// ---------------------------------------------------------------------------
// Fused attention: scores (recent+cache) + online softmax + P@V + gate
// CTA = (bm 128 q-rows, bh). Warp tile = 16 rows x full 128-key tile.
// smem: QU | KT | VT, each = hi plane + lo plane, 128 rows x pitch 136 bf16.
// ---------------------------------------------------------------------------
#define APITCH 272      // row pitch bytes (136 bf16)
#define APLANE 34816    // 128 * 272
#define ABUF   69632    // hi + lo
__global__ void __launch_bounds__(256) attn_kernel(
    const bf16* __restrict__ quh, const bf16* __restrict__ qul,
    const bf16* __restrict__ khat_h, const bf16* __restrict__ khat_l,
    const bf16* __restrict__ cb_h, const bf16* __restrict__ cb_l,
    const bf16* __restrict__ vt_h, const bf16* __restrict__ vt_l,
    const unsigned long long* __restrict__ zpk,
    const float* __restrict__ rbd,
    const float* __restrict__ agg_lower,
    const float* __restrict__ gate,
    bf16* __restrict__ outh, bf16* __restrict__ outl) {

    extern __shared__ __align__(16) char smem_raw[];
    uint32_t sQU = cvta_s(smem_raw);
    uint32_t sKT = sQU + ABUF;
    uint32_t sVT = sQU + 2 * ABUF;

    int tid  = threadIdx.x;
    int lane = tid & 31, warp = tid >> 5;
    int g = lane >> 2, qd = lane & 3;
    int bm = blockIdx.x * 128;
    int bh = blockIdx.y;
    int h  = bh & 7;
    int b  = bh >> 3;

    // key tile schedule (skip fully-masked recent tiles)
    int tiles[12]; int nt = 0;
    #pragma unroll
    for (int j = 0; j < 12; ++j)
        if (!(j < 8 && j * 128 >= bm + CM + 128)) tiles[nt++] = j;

    // ---- loaders (each thread stages 8 rows x 16B per plane) --------------
    auto load_qu = [&]() {
        size_t qoff = (size_t)bh * CL * CDK;
        #pragma unroll
        for (int i = 0; i < 8; ++i) {
            int id = tid + i * 256;
            int r = id >> 4, c = id & 15;
            uint32_t d = sQU + r * APITCH + c * 16;
            cpa16(d,          quh + qoff + (size_t)(bm + r) * CDK + c * 8);
            cpa16(d + APLANE, qul + qoff + (size_t)(bm + r) * CDK + c * 8);
        }
    };
    auto load_kt = [&](int j) {
        #pragma unroll
        for (int i = 0; i < 8; ++i) {
            int id = tid + i * 256;
            int r = id >> 4, c = id & 15;
            int n = j * 128 + r;
            const bf16 *sh, *sl;
            if (j < 4) {
                size_t o = ((size_t)bh * CM + n) * CDK;
                sh = khat_h + o; sl = khat_l + o;
            } else if (j < 8) {
                unsigned zi = (unsigned)(zpk[(size_t)bh * CL + (n - CM)] & 0xffffffffull);
                size_t o = ((size_t)h * CS + zi) * CDK;
                sh = cb_h + o; sl = cb_l + o;
            } else {
                size_t o = ((size_t)h * CS + (n - CW)) * CDK;
                sh = cb_h + o; sl = cb_l + o;
            }
            uint32_t d = sKT + r * APITCH + c * 16;
            cpa16(d,          sh + c * 8);
            cpa16(d + APLANE, sl + c * 8);
        }
    };
    auto load_vt = [&](int j) {
        #pragma unroll
        for (int i = 0; i < 8; ++i) {
            int id = tid + i * 256;
            int r = id >> 4, c = id & 15;
            size_t o = ((size_t)bh * CDV + r) * SCW + j * 128 + c * 8;
            uint32_t d = sVT + r * APITCH + c * 16;
            cpa16(d,          vt_h + o);
            cpa16(d + APLANE, vt_l + o);
        }
    };

    // fragment base addresses
    uint32_t quB = sQU + (uint32_t)(warp * 16 + (lane & 15)) * APITCH + ((lane >> 4) << 4);
    uint32_t bB  = (uint32_t)((((lane >> 4) << 3) + (lane & 7)) * APITCH) + (((lane >> 3) & 1) << 4);

    int l0 = bm + warp * 16 + g;
    int l1 = l0 + 8;

    float O[16][4] = {};
    float m0 = -3.4e38f, m1 = -3.4e38f, d0 = 0.f, d1 = 0.f;

    load_qu();
    load_kt(tiles[0]);
    cpa_commit();

    #pragma unroll 1
    for (int ti = 0; ti < nt; ++ti) {
        int j = tiles[ti];
        cpa_wait<0>();
        __syncthreads();                    // Kt_j (and qu) ready; Vt region free
        load_vt(j);
        cpa_commit();

        // ---- S = qu @ Kt^T (bf16x3) ---------------------------------------
        float S[16][4] = {};
        #pragma unroll
        for (int kg = 0; kg < 8; ++kg) {
            uint32_t ah[4], al[4];
            ldmx4(quB + kg * 32,          ah[0], ah[1], ah[2], ah[3]);
            ldmx4(quB + APLANE + kg * 32, al[0], al[1], al[2], al[3]);
            #pragma unroll
            for (int nf = 0; nf < 8; ++nf) {
                uint32_t base = sKT + bB + nf * (16 * APITCH) + kg * 32;
                uint32_t p0, p1, p2, p3, q0, q1, q2, q3;
                ldmx4(base,          p0, p1, p2, p3);
                ldmx4(base + APLANE, q0, q1, q2, q3);
                uint32_t bp[2], bq[2];
                bp[0] = p0; bp[1] = p1; bq[0] = q0; bq[1] = q1;
                mma16816(S[nf * 2], ah, bp);
                mma16816(S[nf * 2], ah, bq);
                mma16816(S[nf * 2], al, bp);
                bp[0] = p2; bp[1] = p3; bq[0] = q2; bq[1] = q3;
                mma16816(S[nf * 2 + 1], ah, bp);
                mma16816(S[nf * 2 + 1], ah, bq);
                mma16816(S[nf * 2 + 1], al, bp);
            }
        }

        // ---- bias + mask ---------------------------------------------------
        if (j < 8) {
            const float* rr0 = rbd + ((size_t)bh * CL + l0) * CW + (CL - 1) - l0;
            const float* rr1 = rbd + ((size_t)bh * CL + l1) * CW + (CL - 1) - l1;
            int wb = j * 128 + qd * 2;
            #pragma unroll
            for (int u = 0; u < 16; ++u) {
                int w = wb + u * 8;
                S[u][0] = (w     <= l0 + CM) ? S[u][0] * TAUI + rr0[w]     : -1e30f;
                S[u][1] = (w + 1 <= l0 + CM) ? S[u][1] * TAUI + rr0[w + 1] : -1e30f;
                S[u][2] = (w     <= l1 + CM) ? S[u][2] * TAUI + rr1[w]     : -1e30f;
                S[u][3] = (w + 1 <= l1 + CM) ? S[u][3] * TAUI + rr1[w + 1] : -1e30f;
            }
        } else {
            int sb = (j - 8) * 128 + qd * 2;
            #pragma unroll
            for (int u = 0; u < 16; ++u) {
                int s = sb + u * 8;
                float a0 = agg_lower[(size_t)bh * CS + s];
                float a1 = agg_lower[(size_t)bh * CS + s + 1];
                float b0 = (a0 > 0.f) ? logf(fmaxf(a0, 1e-30f)) : -1e30f;
                float b1 = (a1 > 0.f) ? logf(fmaxf(a1, 1e-30f)) : -1e30f;
                S[u][0] = S[u][0] * TAUI + b0;
                S[u][1] = S[u][1] * TAUI + b1;
                S[u][2] = S[u][2] * TAUI + b0;
                S[u][3] = S[u][3] * TAUI + b1;
            }
        }

        // ---- online softmax update ----------------------------------------
        float mx0 = -3.4e38f, mx1 = -3.4e38f;
        #pragma unroll
        for (int u = 0; u < 16; ++u) {
            mx0 = fmaxf(mx0, fmaxf(S[u][0], S[u][1]));
            mx1 = fmaxf(mx1, fmaxf(S[u][2], S[u][3]));
        }
        mx0 = fmaxf(mx0, __shfl_xor_sync(0xffffffffu, mx0, 1));
        mx0 = fmaxf(mx0, __shfl_xor_sync(0xffffffffu, mx0, 2));
        mx1 = fmaxf(mx1, __shfl_xor_sync(0xffffffffu, mx1, 1));
        mx1 = fmaxf(mx1, __shfl_xor_sync(0xffffffffu, mx1, 2));
        float nm0 = fmaxf(m0, mx0), nm1 = fmaxf(m1, mx1);
        float al0 = __expf(m0 - nm0), al1 = __expf(m1 - nm1);
        m0 = nm0; m1 = nm1;
        float s0 = 0.f, s1 = 0.f;
        #pragma unroll
        for (int u = 0; u < 16; ++u) {
            S[u][0] = __expf(S[u][0] - m0);
            S[u][1] = __expf(S[u][1] - m0);
            S[u][2] = __expf(S[u][2] - m1);
            S[u][3] = __expf(S[u][3] - m1);
            s0 += S[u][0] + S[u][1];
            s1 += S[u][2] + S[u][3];
        }
        s0 += __shfl_xor_sync(0xffffffffu, s0, 1);
        s0 += __shfl_xor_sync(0xffffffffu, s0, 2);
        s1 += __shfl_xor_sync(0xffffffffu, s1, 1);
        s1 += __shfl_xor_sync(0xffffffffu, s1, 2);
        d0 = d0 * al0 + s0;
        d1 = d1 * al1 + s1;
        #pragma unroll
        for (int u = 0; u < 16; ++u) {
            O[u][0] *= al0; O[u][1] *= al0;
            O[u][2] *= al1; O[u][3] *= al1;
        }

        cpa_wait<0>();
        __syncthreads();                    // Vt_j ready; Kt region free
        if (ti + 1 < nt) { load_kt(tiles[ti + 1]); cpa_commit(); }

        // ---- O += P @ V (bf16x3; P from registers) -------------------------
        #pragma unroll
        for (int kg = 0; kg < 8; ++kg) {
            int u2 = kg * 2;
            uint32_t pah[4], pal[4];
            pah[0] = packbf(S[u2][0], S[u2][1]);
            pah[1] = packbf(S[u2][2], S[u2][3]);
            pah[2] = packbf(S[u2 + 1][0], S[u2 + 1][1]);
            pah[3] = packbf(S[u2 + 1][2], S[u2 + 1][3]);
            pal[0] = packbf_res(S[u2][0], S[u2][1], pah[0]);
            pal[1] = packbf_res(S[u2][2], S[u2][3], pah[1]);
            pal[2] = packbf_res(S[u2 + 1][0], S[u2 + 1][1], pah[2]);
            pal[3] = packbf_res(S[u2 + 1][2], S[u2 + 1][3], pah[3]);
            #pragma unroll
            for (int nf = 0; nf < 8; ++nf) {
                uint32_t base = sVT + bB + nf * (16 * APITCH) + kg * 32;
                uint32_t p0, p1, p2, p3, q0, q1, q2, q3;
                ldmx4(base,          p0, p1, p2, p3);
                ldmx4(base + APLANE, q0, q1, q2, q3);
                uint32_t bp[2], bq[2];
                bp[0] = p0; bp[1] = p1; bq[0] = q0; bq[1] = q1;
                mma16816(O[nf * 2], pah, bp);
                mma16816(O[nf * 2], pah, bq);
                mma16816(O[nf * 2], pal, bp);
                bp[0] = p2; bp[1] = p3; bq[0] = q2; bq[1] = q3;
                mma16816(O[nf * 2 + 1], pah, bp);
                mma16816(O[nf * 2 + 1], pah, bq);
                mma16816(O[nf * 2 + 1], pal, bp);
            }
        }
    }

    // ---- epilogue: O/denom * gate -> wvg hi/lo ------------------------------
    float i0 = 1.f / d0, i1 = 1.f / d1;
    #pragma unroll
    for (int u = 0; u < 16; ++u) {
        int c = (u << 3) + qd * 2;
        size_t o0 = ((size_t)b * CL + l0) * CDM + h * CDV + c;
        size_t o1 = ((size_t)b * CL + l1) * CDM + h * CDV + c;
        float2 g0 = *(const float2*)(gate + o0);
        float2 g1 = *(const float2*)(gate + o1);
        splitw(O[u][0] * i0 * g0.x, outh + o0,     outl + o0);
        splitw(O[u][1] * i0 * g0.y, outh + o0 + 1, outl + o0 + 1);
        splitw(O[u][2] * i1 * g1.x, outh + o1,     outl + o1);
        splitw(O[u][3] * i1 * g1.y, outh + o1 + 1, outl + o1 + 1);
    }
}

// ---------------------------------------------------------------------------
// Host launcher
// ---------------------------------------------------------------------------
#define SMEM_ATTN (3 * ABUF)   // 208896 bytes

extern "C" void kernel_launch(void* const* d_in, const int* in_sizes, int n_in,
                              void* d_out, int out_size) {
    const float* input     = (const float*)d_in[0];
    const float* xl_k_hat  = (const float*)d_in[2];
    const float* xl_v      = (const float*)d_in[3];
    const float* agg_upper = (const float*)d_in[4];
    const float* agg_lower = (const float*)d_in[5];
    const float* W_q       = (const float*)d_in[6];
    const float* W_kvg     = (const float*)d_in[7];
    const float* W_res     = (const float*)d_in[8];
    const float* x_u       = (const float*)d_in[9];
    const float* x_v       = (const float*)d_in[10];
    const float* xl_r      = (const float*)d_in[11];
    const float* codebook  = (const float*)d_in[12];
    float* out = (float*)d_out;

    float *qraw, *kvg, *vv, *gate, *rbd, *csq;
    unsigned long long* zpk;
    bf16 *xt_h, *xt_l, *wqt_h, *wqt_l, *wkvgt_h, *wkvgt_l, *wrest_h, *wrest_l;
    bf16 *qu_h, *qu_l, *qv_h, *qv_l, *kl_h, *kl_l, *khat_h, *khat_l;
    bf16 *cb_h, *cb_l, *xlr_h, *xlr_l, *vt_h, *vt_l, *wvg_h, *wvg_l;

    cudaGetSymbolAddress((void**)&qraw, g_qraw);
    cudaGetSymbolAddress((void**)&kvg, g_kvg);
    cudaGetSymbolAddress((void**)&vv, g_vv);
    cudaGetSymbolAddress((void**)&gate, g_gate);
    cudaGetSymbolAddress((void**)&rbd, g_rbd);
    cudaGetSymbolAddress((void**)&csq, g_csq);
    cudaGetSymbolAddress((void**)&zpk, g_zpk);
    cudaGetSymbolAddress((void**)&xt_h, g_xt_h);   cudaGetSymbolAddress((void**)&xt_l, g_xt_l);
    cudaGetSymbolAddress((void**)&wqt_h, g_wqt_h); cudaGetSymbolAddress((void**)&wqt_l, g_wqt_l);
    cudaGetSymbolAddress((void**)&wkvgt_h, g_wkvgt_h); cudaGetSymbolAddress((void**)&wkvgt_l, g_wkvgt_l);
    cudaGetSymbolAddress((void**)&wrest_h, g_wrest_h); cudaGetSymbolAddress((void**)&wrest_l, g_wrest_l);
    cudaGetSymbolAddress((void**)&qu_h, g_qu_h);   cudaGetSymbolAddress((void**)&qu_l, g_qu_l);
    cudaGetSymbolAddress((void**)&qv_h, g_qv_h);   cudaGetSymbolAddress((void**)&qv_l, g_qv_l);
    cudaGetSymbolAddress((void**)&kl_h, g_kl_h);   cudaGetSymbolAddress((void**)&kl_l, g_kl_l);
    cudaGetSymbolAddress((void**)&khat_h, g_khat_h); cudaGetSymbolAddress((void**)&khat_l, g_khat_l);
    cudaGetSymbolAddress((void**)&cb_h, g_cb_h);   cudaGetSymbolAddress((void**)&cb_l, g_cb_l);
    cudaGetSymbolAddress((void**)&xlr_h, g_xlr_h); cudaGetSymbolAddress((void**)&xlr_l, g_xlr_l);
    cudaGetSymbolAddress((void**)&vt_h, g_vt_h);   cudaGetSymbolAddress((void**)&vt_l, g_vt_l);
    cudaGetSymbolAddress((void**)&wvg_h, g_wvg_h); cudaGetSymbolAddress((void**)&wvg_l, g_wvg_l);

    cudaFuncSetAttribute(attn_kernel, cudaFuncAttributeMaxDynamicSharedMemorySize, SMEM_ATTN);

    // converts / transposes
    transpose_kernel<<<dim3(32, 32), 256>>>(W_q, wqt_h, wqt_l, 1024, 1024);
    transpose_kernel<<<dim3(96, 32), 256>>>(W_kvg, wkvgt_h, wkvgt_l, 1024, 3072);
    transpose_kernel<<<dim3(32, 32), 256>>>(W_res, wrest_h, wrest_l, 1024, 1024);
    convert_hl_kernel<<<(NBH * CM * CDK) / 1024, 256>>>(xl_k_hat, khat_h, khat_l);
    convert_hl_kernel<<<(CH * CS * CDK) / 1024, 256>>>(codebook, cb_h, cb_l);
    convert_hl_kernel<<<(CH * CW * CDK) / 1024, 256>>>(xl_r, xlr_h, xlr_l);
    csq_kernel<<<CH * CS, 128>>>(codebook, csq);
    zinit_kernel<<<NBH, 512>>>(zpk);

    // 1. LN(input)
    ln_rows_kernel<<<NROWS, 256>>>(input, xt_h, xt_l);

    // 2. projections
    mma_gemm_kernel<4><<<dim3(8, 32, 1), 256>>>(xt_h, xt_l, wqt_h, wqt_l,
                                                nullptr, nullptr, qraw, 1024, 1024, 1024);
    mma_gemm_kernel<4><<<dim3(24, 32, 1), 256>>>(xt_h, xt_l, wkvgt_h, wkvgt_l,
                                                 nullptr, nullptr, kvg, 3072, 1024, 1024);

    // 3. per-head LN, biases, silu
    transform_kernel<<<NROWS * CH / 8, 256>>>(qraw, kvg, x_u, x_v,
                                              qu_h, qu_l, qv_h, qv_l, kl_h, kl_l, vv, gate);

    // 4. V gather-transpose
    vt_kernel<<<dim3(SCW / 32, CDV / 32, NBH), 256>>>(xl_v, vv, agg_upper, vt_h, vt_l);

    // 5. VQ argmin
    mma_gemm_kernel<3><<<dim3(4, 4, NBH), 256>>>(kl_h, kl_l, cb_h, cb_l,
                                                 csq, zpk, nullptr, 512, 128, 128);

    // 6. BD (rel-shift bias source)
    mma_gemm_kernel<0><<<dim3(8, 4, NBH), 256>>>(qv_h, qv_l, xlr_h, xlr_l,
                                                 nullptr, nullptr, rbd, 1024, 128, 128);

    // 7. fused attention: scores + softmax + P@V + gate -> wvg hi/lo
    attn_kernel<<<dim3(4, 64), 256, SMEM_ATTN>>>(qu_h, qu_l, khat_h, khat_l,
                                                 cb_h, cb_l, vt_h, vt_l, zpk,
                                                 rbd, agg_lower, gate, wvg_h, wvg_l);

    // 8. output projection
    mma_gemm_kernel<4><<<dim3(8, 32, 1), 256>>>(wvg_h, wvg_l, wrest_h, wrest_l,
                                                nullptr, nullptr, out, 1024, 1024, 1024);
}

// round 9
// speedup vs baseline: 2.3818x; 1.0436x over previous
#include <cuda_runtime.h>
#include <cuda_bf16.h>
#include <cstdint>

// ---------------------------------------------------------------------------
// Problem constants
// ---------------------------------------------------------------------------
#define CB   8
#define CL   512
#define CM   512
#define CH   8
#define CDK  128
#define CDV  128
#define CS   512
#define CDM  1024
#define CW   1024   // W_REC
#define NBH  64
#define NROWS 4096
#define SCW  1536   // W + S

static __device__ __constant__ const float TAUI = 0.08838834764831845f; // 1/sqrt(128)

typedef __nv_bfloat16 bf16;

// ---------------------------------------------------------------------------
// Scratch
// ---------------------------------------------------------------------------
__device__ float g_qraw  [(size_t)NROWS * CDM];
__device__ float g_kvg   [(size_t)NROWS * 3072];
__device__ float g_vv    [(size_t)NBH * CL * CDV];
__device__ float g_gate  [(size_t)NROWS * CDM];
__device__ float g_rbd   [(size_t)NBH * CL * CW];
__device__ unsigned long long g_zpk[NBH * CL];
__device__ float g_csq   [CH * CS];
__device__ int   g_unit_ctr;

__device__ bf16 g_xt_h   [(size_t)NROWS * CDM];
__device__ bf16 g_xt_l   [(size_t)NROWS * CDM];
__device__ bf16 g_wqt_h  [(size_t)1024 * 1024];
__device__ bf16 g_wqt_l  [(size_t)1024 * 1024];
__device__ bf16 g_wkvgt_h[(size_t)3072 * 1024];
__device__ bf16 g_wkvgt_l[(size_t)3072 * 1024];
__device__ bf16 g_wrest_h[(size_t)1024 * 1024];
__device__ bf16 g_wrest_l[(size_t)1024 * 1024];
__device__ bf16 g_qu_h   [(size_t)NBH * CL * CDK];
__device__ bf16 g_qu_l   [(size_t)NBH * CL * CDK];
__device__ bf16 g_qv_h   [(size_t)NBH * CL * CDK];
__device__ bf16 g_qv_l   [(size_t)NBH * CL * CDK];
__device__ bf16 g_kl_h   [(size_t)NBH * CL * CDK];
__device__ bf16 g_kl_l   [(size_t)NBH * CL * CDK];
__device__ bf16 g_khat_h [(size_t)NBH * CM * CDK];
__device__ bf16 g_khat_l [(size_t)NBH * CM * CDK];
__device__ bf16 g_cb_h   [(size_t)CH * CS * CDK];
__device__ bf16 g_cb_l   [(size_t)CH * CS * CDK];
__device__ bf16 g_xlr_h  [(size_t)CH * CW * CDK];
__device__ bf16 g_xlr_l  [(size_t)CH * CW * CDK];
__device__ bf16 g_vt_h   [(size_t)NBH * CDV * SCW];
__device__ bf16 g_vt_l   [(size_t)NBH * CDV * SCW];
__device__ bf16 g_wvg_h  [(size_t)NROWS * CDM];
__device__ bf16 g_wvg_l  [(size_t)NROWS * CDM];

// ---------------------------------------------------------------------------
// primitives
// ---------------------------------------------------------------------------
__device__ __forceinline__ uint32_t cvta_s(const void* p) {
    return (uint32_t)__cvta_generic_to_shared(p);
}
__device__ __forceinline__ void ldmx4(uint32_t addr, uint32_t& r0, uint32_t& r1,
                                      uint32_t& r2, uint32_t& r3) {
    asm volatile("ldmatrix.sync.aligned.m8n8.x4.shared.b16 {%0,%1,%2,%3}, [%4];"
                 : "=r"(r0), "=r"(r1), "=r"(r2), "=r"(r3) : "r"(addr));
}
__device__ __forceinline__ void mma16816(float c[4], const uint32_t a[4], const uint32_t b[2]) {
    asm volatile(
        "mma.sync.aligned.m16n8k16.row.col.f32.bf16.bf16.f32 "
        "{%0,%1,%2,%3}, {%4,%5,%6,%7}, {%8,%9}, {%0,%1,%2,%3};"
        : "+f"(c[0]), "+f"(c[1]), "+f"(c[2]), "+f"(c[3])
        : "r"(a[0]), "r"(a[1]), "r"(a[2]), "r"(a[3]), "r"(b[0]), "r"(b[1]));
}
__device__ __forceinline__ void cpa16(uint32_t d, const void* s) {
    asm volatile("cp.async.ca.shared.global [%0], [%1], 16;" :: "r"(d), "l"(s));
}
__device__ __forceinline__ void cpa_commit() {
    asm volatile("cp.async.commit_group;");
}
template <int NN>
__device__ __forceinline__ void cpa_wait() {
    asm volatile("cp.async.wait_group %0;" :: "n"(NN));
}

__device__ __forceinline__ void splitw(float x, bf16* h, bf16* l) {
    bf16 hh = __float2bfloat16_rn(x);
    *h = hh;
    *l = __float2bfloat16_rn(x - __bfloat162float(hh));
}
__device__ __forceinline__ void split4(float4 v, bf16* hp, bf16* lp) {
    __nv_bfloat162 h0 = __floats2bfloat162_rn(v.x, v.y);
    __nv_bfloat162 h1 = __floats2bfloat162_rn(v.z, v.w);
    float2 f0 = __bfloat1622float2(h0);
    float2 f1 = __bfloat1622float2(h1);
    __nv_bfloat162 l0 = __floats2bfloat162_rn(v.x - f0.x, v.y - f0.y);
    __nv_bfloat162 l1 = __floats2bfloat162_rn(v.z - f1.x, v.w - f1.y);
    uint2 hv, lv;
    hv.x = *(uint32_t*)&h0; hv.y = *(uint32_t*)&h1;
    lv.x = *(uint32_t*)&l0; lv.y = *(uint32_t*)&l1;
    *(uint2*)hp = hv;
    *(uint2*)lp = lv;
}
__device__ __forceinline__ uint32_t packbf(float x, float y) {
    __nv_bfloat162 t = __floats2bfloat162_rn(x, y);
    return *(uint32_t*)&t;
}
__device__ __forceinline__ uint32_t packbf_res(float x, float y, uint32_t hp) {
    __nv_bfloat162 hv = *(__nv_bfloat162*)&hp;
    float2 f = __bfloat1622float2(hv);
    return packbf(x - f.x, y - f.y);
}

// ---------------------------------------------------------------------------
// reductions
// ---------------------------------------------------------------------------
__device__ __forceinline__ float block_sum(float v) {
    __shared__ float sb_[8];
    int tid = threadIdx.x;
    int nw  = blockDim.x >> 5;
    #pragma unroll
    for (int o = 16; o; o >>= 1) v += __shfl_down_sync(0xffffffffu, v, o);
    __syncthreads();
    if ((tid & 31) == 0) sb_[tid >> 5] = v;
    __syncthreads();
    float r = 0.f;
    for (int i = 0; i < nw; ++i) r += sb_[i];
    return r;
}
__device__ __forceinline__ float warp_sum(float v) {
    #pragma unroll
    for (int o = 16; o; o >>= 1) v += __shfl_xor_sync(0xffffffffu, v, o);
    return v;
}

// ---------------------------------------------------------------------------
// LayerNorm over DM=1024 -> bf16 hi/lo
// ---------------------------------------------------------------------------
__global__ void __launch_bounds__(256) ln_rows_kernel(const float* __restrict__ x,
                                                      bf16* __restrict__ yh,
                                                      bf16* __restrict__ yl) {
    int row = blockIdx.x;
    const float* xr = x + (size_t)row * CDM;
    int tid = threadIdx.x;
    float4 v = *(const float4*)(xr + tid * 4);
    float s = v.x + v.y + v.z + v.w;
    float mu = block_sum(s) * (1.f / 1024.f);
    v.x -= mu; v.y -= mu; v.z -= mu; v.w -= mu;
    float s2 = v.x * v.x + v.y * v.y + v.z * v.z + v.w * v.w;
    float rstd = rsqrtf(block_sum(s2) * (1.f / 1024.f) + 1e-6f);
    v.x *= rstd; v.y *= rstd; v.z *= rstd; v.w *= rstd;
    split4(v, yh + (size_t)row * CDM + tid * 4, yl + (size_t)row * CDM + tid * 4);
}

__global__ void __launch_bounds__(256) convert_hl_kernel(const float* __restrict__ src,
                                                         bf16* __restrict__ h,
                                                         bf16* __restrict__ l) {
    size_t idx = (size_t)blockIdx.x * 256 + threadIdx.x;
    float4 v = ((const float4*)src)[idx];
    split4(v, h + idx * 4, l + idx * 4);
}

__global__ void __launch_bounds__(256) transpose_kernel(const float* __restrict__ src,
                                                        bf16* __restrict__ dsth,
                                                        bf16* __restrict__ dstl,
                                                        int R, int C) {
    __shared__ float tile[32][33];
    int c0 = blockIdx.x * 32, r0 = blockIdx.y * 32;
    int x = threadIdx.x & 31, y = (threadIdx.x >> 5) * 4;
    #pragma unroll
    for (int i = 0; i < 4; ++i)
        tile[y + i][x] = src[(size_t)(r0 + y + i) * C + c0 + x];
    __syncthreads();
    #pragma unroll
    for (int i = 0; i < 4; ++i) {
        size_t o = (size_t)(c0 + y + i) * R + r0 + x;
        splitw(tile[x][y + i], dsth + o, dstl + o);
    }
}

__global__ void __launch_bounds__(256) vt_kernel(const float* __restrict__ xl_v,
                                                 const float* __restrict__ vv,
                                                 const float* __restrict__ aggu,
                                                 bf16* __restrict__ vth,
                                                 bf16* __restrict__ vtl) {
    __shared__ float tile[32][33];
    int zb = blockIdx.z;
    int w0 = blockIdx.x * 32, v0 = blockIdx.y * 32;
    int x = threadIdx.x & 31, y = (threadIdx.x >> 5) * 4;
    #pragma unroll
    for (int i = 0; i < 4; ++i) {
        int w = w0 + y + i;
        const float* srcrow;
        if (w < CM)      srcrow = xl_v + ((size_t)zb * CM + w) * CDV;
        else if (w < CW) srcrow = vv   + ((size_t)zb * CL + (w - CM)) * CDV;
        else             srcrow = aggu + ((size_t)zb * CS + (w - CW)) * CDV;
        tile[y + i][x] = srcrow[v0 + x];
    }
    __syncthreads();
    #pragma unroll
    for (int i = 0; i < 4; ++i) {
        size_t o = ((size_t)zb * CDV + v0 + y + i) * SCW + w0 + x;
        splitw(tile[x][y + i], vth + o, vtl + o);
    }
}

__global__ void __launch_bounds__(256) transform_kernel(const float* __restrict__ qraw,
                                                        const float* __restrict__ kvg,
                                                        const float* __restrict__ x_u,
                                                        const float* __restrict__ x_v,
                                                        bf16* __restrict__ quh, bf16* __restrict__ qul,
                                                        bf16* __restrict__ qvh, bf16* __restrict__ qvl,
                                                        bf16* __restrict__ klh, bf16* __restrict__ kll,
                                                        float* __restrict__ vv,
                                                        float* __restrict__ gate) {
    int wid  = threadIdx.x >> 5;
    int lane = threadIdx.x & 31;
    int idx = blockIdx.x * 8 + wid;
    int h  = idx & 7;
    int bl = idx >> 3;
    int b = bl >> 9, l = bl & 511;
    int d0 = lane * 4;

    float4 q = *(const float4*)(qraw + (size_t)bl * CDM + h * CDK + d0);
    float mu = warp_sum(q.x + q.y + q.z + q.w) * (1.f / 128.f);
    q.x -= mu; q.y -= mu; q.z -= mu; q.w -= mu;
    float var = warp_sum(q.x * q.x + q.y * q.y + q.z * q.z + q.w * q.w) * (1.f / 128.f);
    float rs = rsqrtf(var + 1e-6f);
    float4 xu = *(const float4*)(x_u + h * CDK + d0);
    float4 xv = *(const float4*)(x_v + h * CDK + d0);
    size_t o = (((size_t)b * CH + h) * CL + l) * CDK + d0;
    split4(make_float4(q.x * rs + xu.x, q.y * rs + xu.y, q.z * rs + xu.z, q.w * rs + xu.w),
           quh + o, qul + o);
    split4(make_float4(q.x * rs + xv.x, q.y * rs + xv.y, q.z * rs + xv.z, q.w * rs + xv.w),
           qvh + o, qvl + o);

    float4 k = *(const float4*)(kvg + (size_t)bl * 3072 + h * CDK + d0);
    float kmu = warp_sum(k.x + k.y + k.z + k.w) * (1.f / 128.f);
    k.x -= kmu; k.y -= kmu; k.z -= kmu; k.w -= kmu;
    float kvar = warp_sum(k.x * k.x + k.y * k.y + k.z * k.z + k.w * k.w) * (1.f / 128.f);
    float krs = rsqrtf(kvar + 1e-6f);
    split4(make_float4(k.x * krs, k.y * krs, k.z * krs, k.w * krs), klh + o, kll + o);

    *(float4*)(vv + o) = *(const float4*)(kvg + (size_t)bl * 3072 + 1024 + h * CDK + d0);

    float4 gg = *(const float4*)(kvg + (size_t)bl * 3072 + 2048 + h * CDK + d0);
    float4 gs;
    gs.x = gg.x / (1.f + __expf(-gg.x));
    gs.y = gg.y / (1.f + __expf(-gg.y));
    gs.z = gg.z / (1.f + __expf(-gg.z));
    gs.w = gg.w / (1.f + __expf(-gg.w));
    *(float4*)(gate + (size_t)bl * CDM + h * CDK + d0) = gs;
}

__global__ void __launch_bounds__(128) csq_kernel(const float* __restrict__ cb,
                                                  float* __restrict__ csq) {
    int row = blockIdx.x;
    float v = cb[(size_t)row * CDK + threadIdx.x];
    v = block_sum(v * v);
    if (threadIdx.x == 0) csq[row] = v;
}

__global__ void zinit_kernel(unsigned long long* zpk, int* ctr) {
    if (blockIdx.x == 0 && threadIdx.x == 0) *ctr = 0;
    zpk[blockIdx.x * 512 + threadIdx.x] = ~0ull;
}

// ---------------------------------------------------------------------------
// NT tensor-core GEMM (bf16x3, 3-stage cp.async). MODE: 0=BD, 3=VQ, 4=PROJ
// ---------------------------------------------------------------------------
#define STG_B 12288
#define CMP_B 6144
template <int MODE>
__global__ void __launch_bounds__(256) mma_gemm_kernel(
    const bf16* __restrict__ Ah, const bf16* __restrict__ Al,
    const bf16* __restrict__ Bh, const bf16* __restrict__ Bl,
    const float* __restrict__ csq,
    unsigned long long* zpk_out,
    float* __restrict__ outp,
    int N, int K, int lda) {

    __shared__ __align__(16) bf16 SA[3][2][128][24];
    __shared__ __align__(16) bf16 SB[3][2][128][24];

    int tid  = threadIdx.x;
    int lane = tid & 31, warp = tid >> 5;
    int wm = warp >> 2, wn = warp & 3;
    int bm = blockIdx.y * 128;
    int bn = blockIdx.x * 128;
    int bh = blockIdx.z;
    int h  = bh & 7;

    // BD dead-tile skip: rel-shift never reads rbd[l][c] with c < 511 - l,
    // so tiles entirely below the read frontier are skipped.
    if (MODE == 0 && (bn + bm) < 257) return;

    size_t aoff = (MODE == 4) ? 0 : (size_t)bh * CL * CDK;

    int srow = tid >> 1;
    int sc8  = (tid & 1) * 8;
    const bf16* a_h = Ah + aoff + (size_t)(bm + srow) * lda + sc8;
    const bf16* a_l = Al + aoff + (size_t)(bm + srow) * lda + sc8;
    const bf16 *b_h, *b_l;
    {
        int n = bn + srow;
        size_t boff;
        if (MODE == 0)      boff = ((size_t)h * CW + n) * CDK;
        else if (MODE == 3) boff = ((size_t)h * CS + n) * CDK;
        else                boff = (size_t)n * K;
        b_h = Bh + boff + sc8; b_l = Bl + boff + sc8;
    }

    uint32_t sA = cvta_s(&SA[0][0][0][0]);
    uint32_t sB = cvta_s(&SB[0][0][0][0]);
    uint32_t dA = sA + (uint32_t)(srow * 24 + sc8) * 2;
    uint32_t dB = sB + (uint32_t)(srow * 24 + sc8) * 2;

    int a_off = (wm * 64 + (lane & 15)) * 24 + ((lane >> 4) << 3);
    int b_off = (wn * 32 + ((lane >> 4) << 3) + (lane & 7)) * 24 + (((lane >> 3) & 1) << 3);

    float acc[4][4][4] = {};
    int T = K >> 4;

    cpa16(dA,         a_h);  cpa16(dA + CMP_B, a_l);
    cpa16(dB,         b_h);  cpa16(dB + CMP_B, b_l);
    cpa_commit();

    #pragma unroll 1
    for (int kt = 0; kt < T; ++kt) {
        if (kt + 1 < T) {
            int st = (kt + 1) % 3;
            int k0 = (kt + 1) * 16;
            cpa16(dA + st * STG_B,         a_h + k0);
            cpa16(dA + st * STG_B + CMP_B, a_l + k0);
            cpa16(dB + st * STG_B,         b_h + k0);
            cpa16(dB + st * STG_B + CMP_B, b_l + k0);
            cpa_commit();
            cpa_wait<1>();
        } else {
            cpa_wait<0>();
        }
        __syncthreads();

        int cs = kt % 3;
        uint32_t aH = sA + cs * STG_B + (uint32_t)a_off * 2;
        uint32_t bH = sB + cs * STG_B + (uint32_t)b_off * 2;
        uint32_t ah[4][4], al[4][4], bhf[4][2], blf[4][2];
        #pragma unroll
        for (int t = 0; t < 4; ++t) {
            ldmx4(aH + t * 768,         ah[t][0], ah[t][1], ah[t][2], ah[t][3]);
            ldmx4(aH + CMP_B + t * 768, al[t][0], al[t][1], al[t][2], al[t][3]);
        }
        #pragma unroll
        for (int u2 = 0; u2 < 2; ++u2) {
            uint32_t r0, r1, r2, r3;
            ldmx4(bH + u2 * 768, r0, r1, r2, r3);
            bhf[2 * u2][0] = r0; bhf[2 * u2][1] = r1;
            bhf[2 * u2 + 1][0] = r2; bhf[2 * u2 + 1][1] = r3;
            ldmx4(bH + CMP_B + u2 * 768, r0, r1, r2, r3);
            blf[2 * u2][0] = r0; blf[2 * u2][1] = r1;
            blf[2 * u2 + 1][0] = r2; blf[2 * u2 + 1][1] = r3;
        }
        #pragma unroll
        for (int t = 0; t < 4; ++t)
            #pragma unroll
            for (int u = 0; u < 4; ++u) {
                mma16816(acc[t][u], ah[t], bhf[u]);
                mma16816(acc[t][u], ah[t], blf[u]);
                mma16816(acc[t][u], al[t], bhf[u]);
            }
    }

    int g  = lane >> 2;
    int qd = lane & 3;

    if constexpr (MODE == 4) {
        #pragma unroll
        for (int t = 0; t < 4; ++t) {
            int r = bm + wm * 64 + t * 16 + g;
            #pragma unroll
            for (int u = 0; u < 4; ++u) {
                int c = bn + wn * 32 + u * 8 + qd * 2;
                *(float2*)(outp + (size_t)r * N + c) =
                    make_float2(acc[t][u][0], acc[t][u][1]);
                *(float2*)(outp + (size_t)(r + 8) * N + c) =
                    make_float2(acc[t][u][2], acc[t][u][3]);
            }
        }
    } else if constexpr (MODE == 0) {
        #pragma unroll
        for (int t = 0; t < 4; ++t) {
            int l = bm + wm * 64 + t * 16 + g;
            #pragma unroll
            for (int u = 0; u < 4; ++u) {
                int c = bn + wn * 32 + u * 8 + qd * 2;
                *(float2*)(outp + ((size_t)bh * CL + l) * CW + c) =
                    make_float2(acc[t][u][0] * TAUI, acc[t][u][1] * TAUI);
                *(float2*)(outp + ((size_t)bh * CL + l + 8) * CW + c) =
                    make_float2(acc[t][u][2] * TAUI, acc[t][u][3] * TAUI);
            }
        }
    } else {   // MODE 3: VQ argmin
        unsigned long long* zmin = reinterpret_cast<unsigned long long*>(&SA[0][0][0][0]);
        __syncthreads();
        if (tid < 128) zmin[tid] = ~0ull;
        __syncthreads();
        #pragma unroll
        for (int t = 0; t < 4; ++t) {
            unsigned long long b0 = ~0ull, b1 = ~0ull;
            #pragma unroll
            for (int u = 0; u < 4; ++u) {
                #pragma unroll
                for (int p = 0; p < 2; ++p) {
                    int s = bn + wn * 32 + u * 8 + qd * 2 + p;
                    float cs = csq[h * CS + s];
                    {
                        float val = cs - 2.f * acc[t][u][p];
                        unsigned uu = __float_as_uint(val);
                        uu = (uu & 0x80000000u) ? ~uu : (uu | 0x80000000u);
                        unsigned long long key = ((unsigned long long)uu << 32) | (unsigned)s;
                        if (key < b0) b0 = key;
                    }
                    {
                        float val = cs - 2.f * acc[t][u][2 + p];
                        unsigned uu = __float_as_uint(val);
                        uu = (uu & 0x80000000u) ? ~uu : (uu | 0x80000000u);
                        unsigned long long key = ((unsigned long long)uu << 32) | (unsigned)s;
                        if (key < b1) b1 = key;
                    }
                }
            }
            unsigned long long o;
            o = __shfl_xor_sync(0xffffffffu, b0, 1); if (o < b0) b0 = o;
            o = __shfl_xor_sync(0xffffffffu, b0, 2); if (o < b0) b0 = o;
            o = __shfl_xor_sync(0xffffffffu, b1, 1); if (o < b1) b1 = o;
            o = __shfl_xor_sync(0xffffffffu, b1, 2); if (o < b1) b1 = o;
            if (qd == 0) {
                atomicMin(&zmin[wm * 64 + t * 16 + g], b0);
                atomicMin(&zmin[wm * 64 + t * 16 + g + 8], b1);
            }
        }
        __syncthreads();
        if (tid < 128)
            atomicMin(&zpk_out[(size_t)bh * CL + bm + tid], zmin[tid]);
    }
}

// ---------------------------------------------------------------------------
// Fused attention (persistent, work-stealing): scores + online softmax + P@V
// Unit = (bm 128 q-rows, bh). Warp tile = 16 rows x full 128-key tile.
// ---------------------------------------------------------------------------
#define APITCH 272      // row pitch bytes (136 bf16)
#define APLANE 34816    // 128 * 272
#define ABUF   69632    // hi + lo
#define NUNITS 256
__global__ void __launch_bounds__(256) attn_kernel(
    const bf16* __restrict__ quh, const bf16* __restrict__ qul,
    const bf16* __restrict__ khat_h, const bf16* __restrict__ khat_l,
    const bf16* __restrict__ cb_h, const bf16* __restrict__ cb_l,
    const bf16* __restrict__ vt_h, const bf16* __restrict__ vt_l,
    const unsigned long long* __restrict__ zpk,
    const float* __restrict__ rbd,
    const float* __restrict__ agg_lower,
    const float* __restrict__ gate,
    int* __restrict__ unit_ctr,
    bf16* __restrict__ outh, bf16* __restrict__ outl) {

    extern __shared__ __align__(16) char smem_raw[];
    uint32_t sQU = cvta_s(smem_raw);
    uint32_t sKT = sQU + ABUF;
    uint32_t sVT = sQU + 2 * ABUF;
    __shared__ int s_unit;

    int tid  = threadIdx.x;
    int lane = tid & 31, warp = tid >> 5;
    int g = lane >> 2, qd = lane & 3;

    for (;;) {
        __syncthreads();                      // smem + s_unit reuse guard
        if (tid == 0) s_unit = atomicAdd(unit_ctr, 1);
        __syncthreads();
        int unit = s_unit;
        if (unit >= NUNITS) break;

        int bm = (unit >> 6) * 128;
        int bh = unit & 63;
        int h  = bh & 7;
        int b  = bh >> 3;

        // key tile schedule (skip fully-masked recent tiles)
        int tiles[12]; int nt = 0;
        #pragma unroll
        for (int j = 0; j < 12; ++j)
            if (!(j < 8 && j * 128 >= bm + CM + 128)) tiles[nt++] = j;

        auto load_qu = [&]() {
            size_t qoff = (size_t)bh * CL * CDK;
            #pragma unroll
            for (int i = 0; i < 8; ++i) {
                int id = tid + i * 256;
                int r = id >> 4, c = id & 15;
                uint32_t d = sQU + r * APITCH + c * 16;
                cpa16(d,          quh + qoff + (size_t)(bm + r) * CDK + c * 8);
                cpa16(d + APLANE, qul + qoff + (size_t)(bm + r) * CDK + c * 8);
            }
        };
        auto load_kt = [&](int j) {
            #pragma unroll
            for (int i = 0; i < 8; ++i) {
                int id = tid + i * 256;
                int r = id >> 4, c = id & 15;
                int n = j * 128 + r;
                const bf16 *sh, *sl;
                if (j < 4) {
                    size_t o = ((size_t)bh * CM + n) * CDK;
                    sh = khat_h + o; sl = khat_l + o;
                } else if (j < 8) {
                    unsigned zi = (unsigned)(zpk[(size_t)bh * CL + (n - CM)] & 0xffffffffull);
                    size_t o = ((size_t)h * CS + zi) * CDK;
                    sh = cb_h + o; sl = cb_l + o;
                } else {
                    size_t o = ((size_t)h * CS + (n - CW)) * CDK;
                    sh = cb_h + o; sl = cb_l + o;
                }
                uint32_t d = sKT + r * APITCH + c * 16;
                cpa16(d,          sh + c * 8);
                cpa16(d + APLANE, sl + c * 8);
            }
        };
        auto load_vt = [&](int j) {
            #pragma unroll
            for (int i = 0; i < 8; ++i) {
                int id = tid + i * 256;
                int r = id >> 4, c = id & 15;
                size_t o = ((size_t)bh * CDV + r) * SCW + j * 128 + c * 8;
                uint32_t d = sVT + r * APITCH + c * 16;
                cpa16(d,          vt_h + o);
                cpa16(d + APLANE, vt_l + o);
            }
        };

        uint32_t quB = sQU + (uint32_t)(warp * 16 + (lane & 15)) * APITCH + ((lane >> 4) << 4);
        uint32_t bB  = (uint32_t)((((lane >> 4) << 3) + (lane & 7)) * APITCH) + (((lane >> 3) & 1) << 4);

        int l0 = bm + warp * 16 + g;
        int l1 = l0 + 8;

        float O[16][4] = {};
        float m0 = -3.4e38f, m1 = -3.4e38f, d0 = 0.f, d1 = 0.f;

        load_qu();
        load_kt(tiles[0]);
        cpa_commit();

        #pragma unroll 1
        for (int ti = 0; ti < nt; ++ti) {
            int j = tiles[ti];
            cpa_wait<0>();
            __syncthreads();                    // Kt_j (and qu) ready; Vt free
            load_vt(j);
            cpa_commit();

            // ---- S = qu @ Kt^T (bf16x3) -----------------------------------
            float S[16][4] = {};
            #pragma unroll
            for (int kg = 0; kg < 8; ++kg) {
                uint32_t ah[4], al[4];
                ldmx4(quB + kg * 32,          ah[0], ah[1], ah[2], ah[3]);
                ldmx4(quB + APLANE + kg * 32, al[0], al[1], al[2], al[3]);
                #pragma unroll
                for (int nf = 0; nf < 8; ++nf) {
                    uint32_t base = sKT + bB + nf * (16 * APITCH) + kg * 32;
                    uint32_t p0, p1, p2, p3, q0, q1, q2, q3;
                    ldmx4(base,          p0, p1, p2, p3);
                    ldmx4(base + APLANE, q0, q1, q2, q3);
                    uint32_t bp[2], bq[2];
                    bp[0] = p0; bp[1] = p1; bq[0] = q0; bq[1] = q1;
                    mma16816(S[nf * 2], ah, bp);
                    mma16816(S[nf * 2], ah, bq);
                    mma16816(S[nf * 2], al, bp);
                    bp[0] = p2; bp[1] = p3; bq[0] = q2; bq[1] = q3;
                    mma16816(S[nf * 2 + 1], ah, bp);
                    mma16816(S[nf * 2 + 1], ah, bq);
                    mma16816(S[nf * 2 + 1], al, bp);
                }
            }

            // ---- bias + mask ------------------------------------------------
            if (j < 8) {
                const float* rr0 = rbd + ((size_t)bh * CL + l0) * CW + (CL - 1) - l0;
                const float* rr1 = rbd + ((size_t)bh * CL + l1) * CW + (CL - 1) - l1;
                int wb = j * 128 + qd * 2;
                #pragma unroll
                for (int u = 0; u < 16; ++u) {
                    int w = wb + u * 8;
                    S[u][0] = (w     <= l0 + CM) ? S[u][0] * TAUI + rr0[w]     : -1e30f;
                    S[u][1] = (w + 1 <= l0 + CM) ? S[u][1] * TAUI + rr0[w + 1] : -1e30f;
                    S[u][2] = (w     <= l1 + CM) ? S[u][2] * TAUI + rr1[w]     : -1e30f;
                    S[u][3] = (w + 1 <= l1 + CM) ? S[u][3] * TAUI + rr1[w + 1] : -1e30f;
                }
            } else {
                int sb = (j - 8) * 128 + qd * 2;
                #pragma unroll
                for (int u = 0; u < 16; ++u) {
                    int s = sb + u * 8;
                    float a0 = agg_lower[(size_t)bh * CS + s];
                    float a1 = agg_lower[(size_t)bh * CS + s + 1];
                    float b0 = (a0 > 0.f) ? logf(fmaxf(a0, 1e-30f)) : -1e30f;
                    float b1 = (a1 > 0.f) ? logf(fmaxf(a1, 1e-30f)) : -1e30f;
                    S[u][0] = S[u][0] * TAUI + b0;
                    S[u][1] = S[u][1] * TAUI + b1;
                    S[u][2] = S[u][2] * TAUI + b0;
                    S[u][3] = S[u][3] * TAUI + b1;
                }
            }

            // ---- online softmax update -------------------------------------
            float mx0 = -3.4e38f, mx1 = -3.4e38f;
            #pragma unroll
            for (int u = 0; u < 16; ++u) {
                mx0 = fmaxf(mx0, fmaxf(S[u][0], S[u][1]));
                mx1 = fmaxf(mx1, fmaxf(S[u][2], S[u][3]));
            }
            mx0 = fmaxf(mx0, __shfl_xor_sync(0xffffffffu, mx0, 1));
            mx0 = fmaxf(mx0, __shfl_xor_sync(0xffffffffu, mx0, 2));
            mx1 = fmaxf(mx1, __shfl_xor_sync(0xffffffffu, mx1, 1));
            mx1 = fmaxf(mx1, __shfl_xor_sync(0xffffffffu, mx1, 2));
            float nm0 = fmaxf(m0, mx0), nm1 = fmaxf(m1, mx1);
            float al0 = __expf(m0 - nm0), al1 = __expf(m1 - nm1);
            m0 = nm0; m1 = nm1;
            float s0 = 0.f, s1 = 0.f;
            #pragma unroll
            for (int u = 0; u < 16; ++u) {
                S[u][0] = __expf(S[u][0] - m0);
                S[u][1] = __expf(S[u][1] - m0);
                S[u][2] = __expf(S[u][2] - m1);
                S[u][3] = __expf(S[u][3] - m1);
                s0 += S[u][0] + S[u][1];
                s1 += S[u][2] + S[u][3];
            }
            s0 += __shfl_xor_sync(0xffffffffu, s0, 1);
            s0 += __shfl_xor_sync(0xffffffffu, s0, 2);
            s1 += __shfl_xor_sync(0xffffffffu, s1, 1);
            s1 += __shfl_xor_sync(0xffffffffu, s1, 2);
            d0 = d0 * al0 + s0;
            d1 = d1 * al1 + s1;
            #pragma unroll
            for (int u = 0; u < 16; ++u) {
                O[u][0] *= al0; O[u][1] *= al0;
                O[u][2] *= al1; O[u][3] *= al1;
            }

            cpa_wait<0>();
            __syncthreads();                    // Vt_j ready; Kt free
            if (ti + 1 < nt) { load_kt(tiles[ti + 1]); cpa_commit(); }

            // ---- O += P @ V (bf16x3; P from registers) ----------------------
            #pragma unroll
            for (int kg = 0; kg < 8; ++kg) {
                int u2 = kg * 2;
                uint32_t pah[4], pal[4];
                pah[0] = packbf(S[u2][0], S[u2][1]);
                pah[1] = packbf(S[u2][2], S[u2][3]);
                pah[2] = packbf(S[u2 + 1][0], S[u2 + 1][1]);
                pah[3] = packbf(S[u2 + 1][2], S[u2 + 1][3]);
                pal[0] = packbf_res(S[u2][0], S[u2][1], pah[0]);
                pal[1] = packbf_res(S[u2][2], S[u2][3], pah[1]);
                pal[2] = packbf_res(S[u2 + 1][0], S[u2 + 1][1], pah[2]);
                pal[3] = packbf_res(S[u2 + 1][2], S[u2 + 1][3], pah[3]);
                #pragma unroll
                for (int nf = 0; nf < 8; ++nf) {
                    uint32_t base = sVT + bB + nf * (16 * APITCH) + kg * 32;
                    uint32_t p0, p1, p2, p3, q0, q1, q2, q3;
                    ldmx4(base,          p0, p1, p2, p3);
                    ldmx4(base + APLANE, q0, q1, q2, q3);
                    uint32_t bp[2], bq[2];
                    bp[0] = p0; bp[1] = p1; bq[0] = q0; bq[1] = q1;
                    mma16816(O[nf * 2], pah, bp);
                    mma16816(O[nf * 2], pah, bq);
                    mma16816(O[nf * 2], pal, bp);
                    bp[0] = p2; bp[1] = p3; bq[0] = q2; bq[1] = q3;
                    mma16816(O[nf * 2 + 1], pah, bp);
                    mma16816(O[nf * 2 + 1], pah, bq);
                    mma16816(O[nf * 2 + 1], pal, bp);
                }
            }
        }

        // ---- epilogue: O/denom * gate -> wvg hi/lo --------------------------
        float i0 = 1.f / d0, i1 = 1.f / d1;
        #pragma unroll
        for (int u = 0; u < 16; ++u) {
            int c = (u << 3) + qd * 2;
            size_t o0 = ((size_t)b * CL + l0) * CDM + h * CDV + c;
            size_t o1 = ((size_t)b * CL + l1) * CDM + h * CDV + c;
            float2 g0 = *(const float2*)(gate + o0);
            float2 g1 = *(const float2*)(gate + o1);
            splitw(O[u][0] * i0 * g0.x, outh + o0,     outl + o0);
            splitw(O[u][1] * i0 * g0.y, outh + o0 + 1, outl + o0 + 1);
            splitw(O[u][2] * i1 * g1.x, outh + o1,     outl + o1);
            splitw(O[u][3] * i1 * g1.y, outh + o1 + 1, outl + o1 + 1);
        }
    }
}

// ---------------------------------------------------------------------------
// Host launcher
// ---------------------------------------------------------------------------
#define SMEM_ATTN (3 * ABUF)   // 208896 bytes
#define ATTN_GRID 148

extern "C" void kernel_launch(void* const* d_in, const int* in_sizes, int n_in,
                              void* d_out, int out_size) {
    const float* input     = (const float*)d_in[0];
    const float* xl_k_hat  = (const float*)d_in[2];
    const float* xl_v      = (const float*)d_in[3];
    const float* agg_upper = (const float*)d_in[4];
    const float* agg_lower = (const float*)d_in[5];
    const float* W_q       = (const float*)d_in[6];
    const float* W_kvg     = (const float*)d_in[7];
    const float* W_res     = (const float*)d_in[8];
    const float* x_u       = (const float*)d_in[9];
    const float* x_v       = (const float*)d_in[10];
    const float* xl_r      = (const float*)d_in[11];
    const float* codebook  = (const float*)d_in[12];
    float* out = (float*)d_out;

    float *qraw, *kvg, *vv, *gate, *rbd, *csq;
    unsigned long long* zpk;
    int* ctr;
    bf16 *xt_h, *xt_l, *wqt_h, *wqt_l, *wkvgt_h, *wkvgt_l, *wrest_h, *wrest_l;
    bf16 *qu_h, *qu_l, *qv_h, *qv_l, *kl_h, *kl_l, *khat_h, *khat_l;
    bf16 *cb_h, *cb_l, *xlr_h, *xlr_l, *vt_h, *vt_l, *wvg_h, *wvg_l;

    cudaGetSymbolAddress((void**)&qraw, g_qraw);
    cudaGetSymbolAddress((void**)&kvg, g_kvg);
    cudaGetSymbolAddress((void**)&vv, g_vv);
    cudaGetSymbolAddress((void**)&gate, g_gate);
    cudaGetSymbolAddress((void**)&rbd, g_rbd);
    cudaGetSymbolAddress((void**)&csq, g_csq);
    cudaGetSymbolAddress((void**)&zpk, g_zpk);
    cudaGetSymbolAddress((void**)&ctr, g_unit_ctr);
    cudaGetSymbolAddress((void**)&xt_h, g_xt_h);   cudaGetSymbolAddress((void**)&xt_l, g_xt_l);
    cudaGetSymbolAddress((void**)&wqt_h, g_wqt_h); cudaGetSymbolAddress((void**)&wqt_l, g_wqt_l);
    cudaGetSymbolAddress((void**)&wkvgt_h, g_wkvgt_h); cudaGetSymbolAddress((void**)&wkvgt_l, g_wkvgt_l);
    cudaGetSymbolAddress((void**)&wrest_h, g_wrest_h); cudaGetSymbolAddress((void**)&wrest_l, g_wrest_l);
    cudaGetSymbolAddress((void**)&qu_h, g_qu_h);   cudaGetSymbolAddress((void**)&qu_l, g_qu_l);
    cudaGetSymbolAddress((void**)&qv_h, g_qv_h);   cudaGetSymbolAddress((void**)&qv_l, g_qv_l);
    cudaGetSymbolAddress((void**)&kl_h, g_kl_h);   cudaGetSymbolAddress((void**)&kl_l, g_kl_l);
    cudaGetSymbolAddress((void**)&khat_h, g_khat_h); cudaGetSymbolAddress((void**)&khat_l, g_khat_l);
    cudaGetSymbolAddress((void**)&cb_h, g_cb_h);   cudaGetSymbolAddress((void**)&cb_l, g_cb_l);
    cudaGetSymbolAddress((void**)&xlr_h, g_xlr_h); cudaGetSymbolAddress((void**)&xlr_l, g_xlr_l);
    cudaGetSymbolAddress((void**)&vt_h, g_vt_h);   cudaGetSymbolAddress((void**)&vt_l, g_vt_l);
    cudaGetSymbolAddress((void**)&wvg_h, g_wvg_h); cudaGetSymbolAddress((void**)&wvg_l, g_wvg_l);

    cudaFuncSetAttribute(attn_kernel, cudaFuncAttributeMaxDynamicSharedMemorySize, SMEM_ATTN);

    // converts / transposes
    transpose_kernel<<<dim3(32, 32), 256>>>(W_q, wqt_h, wqt_l, 1024, 1024);
    transpose_kernel<<<dim3(96, 32), 256>>>(W_kvg, wkvgt_h, wkvgt_l, 1024, 3072);
    transpose_kernel<<<dim3(32, 32), 256>>>(W_res, wrest_h, wrest_l, 1024, 1024);
    convert_hl_kernel<<<(NBH * CM * CDK) / 1024, 256>>>(xl_k_hat, khat_h, khat_l);
    convert_hl_kernel<<<(CH * CS * CDK) / 1024, 256>>>(codebook, cb_h, cb_l);
    convert_hl_kernel<<<(CH * CW * CDK) / 1024, 256>>>(xl_r, xlr_h, xlr_l);
    csq_kernel<<<CH * CS, 128>>>(codebook, csq);
    zinit_kernel<<<NBH, 512>>>(zpk, ctr);

    // 1. LN(input)
    ln_rows_kernel<<<NROWS, 256>>>(input, xt_h, xt_l);

    // 2. projections
    mma_gemm_kernel<4><<<dim3(8, 32, 1), 256>>>(xt_h, xt_l, wqt_h, wqt_l,
                                                nullptr, nullptr, qraw, 1024, 1024, 1024);
    mma_gemm_kernel<4><<<dim3(24, 32, 1), 256>>>(xt_h, xt_l, wkvgt_h, wkvgt_l,
                                                 nullptr, nullptr, kvg, 3072, 1024, 1024);

    // 3. per-head LN, biases, silu
    transform_kernel<<<NROWS * CH / 8, 256>>>(qraw, kvg, x_u, x_v,
                                              qu_h, qu_l, qv_h, qv_l, kl_h, kl_l, vv, gate);

    // 4. V gather-transpose
    vt_kernel<<<dim3(SCW / 32, CDV / 32, NBH), 256>>>(xl_v, vv, agg_upper, vt_h, vt_l);

    // 5. VQ argmin
    mma_gemm_kernel<3><<<dim3(4, 4, NBH), 256>>>(kl_h, kl_l, cb_h, cb_l,
                                                 csq, zpk, nullptr, 512, 128, 128);

    // 6. BD (rel-shift bias source; dead tiles skipped in-kernel)
    mma_gemm_kernel<0><<<dim3(8, 4, NBH), 256>>>(qv_h, qv_l, xlr_h, xlr_l,
                                                 nullptr, nullptr, rbd, 1024, 128, 128);

    // 7. fused attention (persistent work-stealing)
    attn_kernel<<<ATTN_GRID, 256, SMEM_ATTN>>>(qu_h, qu_l, khat_h, khat_l,
                                               cb_h, cb_l, vt_h, vt_l, zpk,
                                               rbd, agg_lower, gate, ctr, wvg_h, wvg_l);

    // 8. output projection
    mma_gemm_kernel<4><<<dim3(8, 32, 1), 256>>>(wvg_h, wvg_l, wrest_h, wrest_l,
                                                nullptr, nullptr, out, 1024, 1024, 1024);
}

// round 10
// speedup vs baseline: 2.4169x; 1.0147x over previous
#include <cuda_runtime.h>
#include <cuda_bf16.h>
#include <cstdint>

// ---------------------------------------------------------------------------
// Problem constants
// ---------------------------------------------------------------------------
#define CB   8
#define CL   512
#define CM   512
#define CH   8
#define CDK  128
#define CDV  128
#define CS   512
#define CDM  1024
#define CW   1024   // W_REC
#define NBH  64
#define NROWS 4096
#define SCW  1536   // W + S

static __device__ __constant__ const float TAUI = 0.08838834764831845f; // 1/sqrt(128)

typedef __nv_bfloat16 bf16;

// ---------------------------------------------------------------------------
// Scratch
// ---------------------------------------------------------------------------
__device__ float g_qraw  [(size_t)NROWS * CDM];
__device__ float g_kvg   [(size_t)NROWS * 3072];
__device__ float g_vv    [(size_t)NBH * CL * CDV];
__device__ float g_gate  [(size_t)NROWS * CDM];
__device__ float g_rbd   [(size_t)NBH * CL * CW];
__device__ unsigned long long g_zpk[NBH * CL];
__device__ float g_csq   [CH * CS];
__device__ int   g_unit_ctr;

__device__ bf16 g_xt_h   [(size_t)NROWS * CDM];
__device__ bf16 g_xt_l   [(size_t)NROWS * CDM];
__device__ bf16 g_wqt_h  [(size_t)1024 * 1024];
__device__ bf16 g_wqt_l  [(size_t)1024 * 1024];
__device__ bf16 g_wkvgt_h[(size_t)3072 * 1024];
__device__ bf16 g_wkvgt_l[(size_t)3072 * 1024];
__device__ bf16 g_wrest_h[(size_t)1024 * 1024];
__device__ bf16 g_wrest_l[(size_t)1024 * 1024];
__device__ bf16 g_qu_h   [(size_t)NBH * CL * CDK];
__device__ bf16 g_qu_l   [(size_t)NBH * CL * CDK];
__device__ bf16 g_qv_h   [(size_t)NBH * CL * CDK];
__device__ bf16 g_qv_l   [(size_t)NBH * CL * CDK];
__device__ bf16 g_kl_h   [(size_t)NBH * CL * CDK];
__device__ bf16 g_kl_l   [(size_t)NBH * CL * CDK];
__device__ bf16 g_khat_h [(size_t)NBH * CM * CDK];
__device__ bf16 g_khat_l [(size_t)NBH * CM * CDK];
__device__ bf16 g_cb_h   [(size_t)CH * CS * CDK];
__device__ bf16 g_cb_l   [(size_t)CH * CS * CDK];
__device__ bf16 g_xlr_h  [(size_t)CH * CW * CDK];
__device__ bf16 g_xlr_l  [(size_t)CH * CW * CDK];
__device__ bf16 g_vt_h   [(size_t)NBH * CDV * SCW];
__device__ bf16 g_vt_l   [(size_t)NBH * CDV * SCW];
__device__ bf16 g_wvg_h  [(size_t)NROWS * CDM];
__device__ bf16 g_wvg_l  [(size_t)NROWS * CDM];

// ---------------------------------------------------------------------------
// primitives
// ---------------------------------------------------------------------------
__device__ __forceinline__ uint32_t cvta_s(const void* p) {
    return (uint32_t)__cvta_generic_to_shared(p);
}
__device__ __forceinline__ void ldmx4(uint32_t addr, uint32_t& r0, uint32_t& r1,
                                      uint32_t& r2, uint32_t& r3) {
    asm volatile("ldmatrix.sync.aligned.m8n8.x4.shared.b16 {%0,%1,%2,%3}, [%4];"
                 : "=r"(r0), "=r"(r1), "=r"(r2), "=r"(r3) : "r"(addr));
}
__device__ __forceinline__ void mma16816(float c[4], const uint32_t a[4], const uint32_t b[2]) {
    asm volatile(
        "mma.sync.aligned.m16n8k16.row.col.f32.bf16.bf16.f32 "
        "{%0,%1,%2,%3}, {%4,%5,%6,%7}, {%8,%9}, {%0,%1,%2,%3};"
        : "+f"(c[0]), "+f"(c[1]), "+f"(c[2]), "+f"(c[3])
        : "r"(a[0]), "r"(a[1]), "r"(a[2]), "r"(a[3]), "r"(b[0]), "r"(b[1]));
}
__device__ __forceinline__ void cpa16(uint32_t d, const void* s) {
    asm volatile("cp.async.ca.shared.global [%0], [%1], 16;" :: "r"(d), "l"(s));
}
__device__ __forceinline__ void cpa_commit() {
    asm volatile("cp.async.commit_group;");
}
template <int NN>
__device__ __forceinline__ void cpa_wait() {
    asm volatile("cp.async.wait_group %0;" :: "n"(NN));
}

__device__ __forceinline__ void splitw(float x, bf16* h, bf16* l) {
    bf16 hh = __float2bfloat16_rn(x);
    *h = hh;
    *l = __float2bfloat16_rn(x - __bfloat162float(hh));
}
__device__ __forceinline__ void split4(float4 v, bf16* hp, bf16* lp) {
    __nv_bfloat162 h0 = __floats2bfloat162_rn(v.x, v.y);
    __nv_bfloat162 h1 = __floats2bfloat162_rn(v.z, v.w);
    float2 f0 = __bfloat1622float2(h0);
    float2 f1 = __bfloat1622float2(h1);
    __nv_bfloat162 l0 = __floats2bfloat162_rn(v.x - f0.x, v.y - f0.y);
    __nv_bfloat162 l1 = __floats2bfloat162_rn(v.z - f1.x, v.w - f1.y);
    uint2 hv, lv;
    hv.x = *(uint32_t*)&h0; hv.y = *(uint32_t*)&h1;
    lv.x = *(uint32_t*)&l0; lv.y = *(uint32_t*)&l1;
    *(uint2*)hp = hv;
    *(uint2*)lp = lv;
}
__device__ __forceinline__ uint32_t packbf(float x, float y) {
    __nv_bfloat162 t = __floats2bfloat162_rn(x, y);
    return *(uint32_t*)&t;
}
__device__ __forceinline__ uint32_t packbf_res(float x, float y, uint32_t hp) {
    __nv_bfloat162 hv = *(__nv_bfloat162*)&hp;
    float2 f = __bfloat1622float2(hv);
    return packbf(x - f.x, y - f.y);
}

// ---------------------------------------------------------------------------
// reductions
// ---------------------------------------------------------------------------
__device__ __forceinline__ float block_sum(float v) {
    __shared__ float sb_[8];
    int tid = threadIdx.x;
    int nw  = blockDim.x >> 5;
    #pragma unroll
    for (int o = 16; o; o >>= 1) v += __shfl_down_sync(0xffffffffu, v, o);
    __syncthreads();
    if ((tid & 31) == 0) sb_[tid >> 5] = v;
    __syncthreads();
    float r = 0.f;
    for (int i = 0; i < nw; ++i) r += sb_[i];
    return r;
}
__device__ __forceinline__ float warp_sum(float v) {
    #pragma unroll
    for (int o = 16; o; o >>= 1) v += __shfl_xor_sync(0xffffffffu, v, o);
    return v;
}

// ---------------------------------------------------------------------------
// Fused preprocessing: all independent converts/transposes/LN/csq/zinit
// segmented over one grid.
// ---------------------------------------------------------------------------
#define PS0 1024                 // Wq transpose  (1024x1024)
#define PS1 (PS0 + 3072)         // Wkvg transpose (1024x3072)
#define PS2 (PS1 + 1024)         // Wres transpose (1024x1024)
#define PS3 (PS2 + 4096)         // khat convert
#define PS4 (PS3 + 512)          // cb convert
#define PS5 (PS4 + 1024)         // xlr convert
#define PS6 (PS5 + 4096)         // LN rows
#define PS7 (PS6 + 512)          // csq (8 rows/block)
#define PS8 (PS7 + 32)           // zinit
#define PREP_GRID PS8

__device__ __forceinline__ void do_transpose(const float* __restrict__ src,
                                             bf16* __restrict__ dh,
                                             bf16* __restrict__ dl,
                                             int R, int C, int id,
                                             float (*tile)[33]) {
    int bx = id % (C >> 5), by = id / (C >> 5);
    int c0 = bx * 32, r0 = by * 32;
    int x = threadIdx.x & 31, y = (threadIdx.x >> 5) * 4;
    #pragma unroll
    for (int i = 0; i < 4; ++i)
        tile[y + i][x] = src[(size_t)(r0 + y + i) * C + c0 + x];
    __syncthreads();
    #pragma unroll
    for (int i = 0; i < 4; ++i) {
        size_t o = (size_t)(c0 + y + i) * R + r0 + x;
        splitw(tile[x][y + i], dh + o, dl + o);
    }
}
__device__ __forceinline__ void do_convert(const float* __restrict__ src,
                                           bf16* __restrict__ h,
                                           bf16* __restrict__ l, int id) {
    size_t idx = (size_t)id * 256 + threadIdx.x;
    float4 v = ((const float4*)src)[idx];
    split4(v, h + idx * 4, l + idx * 4);
}

__global__ void __launch_bounds__(256) prep_kernel(
    const float* __restrict__ W_q, const float* __restrict__ W_kvg,
    const float* __restrict__ W_res,
    const float* __restrict__ xl_k_hat, const float* __restrict__ codebook,
    const float* __restrict__ xl_r, const float* __restrict__ input,
    bf16* wqt_h, bf16* wqt_l, bf16* wkvgt_h, bf16* wkvgt_l,
    bf16* wrest_h, bf16* wrest_l,
    bf16* khat_h, bf16* khat_l, bf16* cb_h, bf16* cb_l,
    bf16* xlr_h, bf16* xlr_l, bf16* xt_h, bf16* xt_l,
    float* csq, unsigned long long* zpk, int* ctr) {

    __shared__ float tile[32][33];
    int bid = blockIdx.x;
    int tid = threadIdx.x;

    if (bid < PS0) {
        do_transpose(W_q, wqt_h, wqt_l, 1024, 1024, bid, tile);
    } else if (bid < PS1) {
        do_transpose(W_kvg, wkvgt_h, wkvgt_l, 1024, 3072, bid - PS0, tile);
    } else if (bid < PS2) {
        do_transpose(W_res, wrest_h, wrest_l, 1024, 1024, bid - PS1, tile);
    } else if (bid < PS3) {
        do_convert(xl_k_hat, khat_h, khat_l, bid - PS2);
    } else if (bid < PS4) {
        do_convert(codebook, cb_h, cb_l, bid - PS3);
    } else if (bid < PS5) {
        do_convert(xl_r, xlr_h, xlr_l, bid - PS4);
    } else if (bid < PS6) {
        int row = bid - PS5;
        const float* xr = input + (size_t)row * CDM;
        float4 v = *(const float4*)(xr + tid * 4);
        float s = v.x + v.y + v.z + v.w;
        float mu = block_sum(s) * (1.f / 1024.f);
        v.x -= mu; v.y -= mu; v.z -= mu; v.w -= mu;
        float s2 = v.x * v.x + v.y * v.y + v.z * v.z + v.w * v.w;
        float rstd = rsqrtf(block_sum(s2) * (1.f / 1024.f) + 1e-6f);
        v.x *= rstd; v.y *= rstd; v.z *= rstd; v.w *= rstd;
        split4(v, xt_h + (size_t)row * CDM + tid * 4, xt_l + (size_t)row * CDM + tid * 4);
    } else if (bid < PS7) {
        int wid  = tid >> 5, lane = tid & 31;
        int row = (bid - PS6) * 8 + wid;                 // CH*CS = 4096 rows
        float4 v = *(const float4*)(codebook + (size_t)row * CDK + lane * 4);
        float s = warp_sum(v.x * v.x + v.y * v.y + v.z * v.z + v.w * v.w);
        if (lane == 0) csq[row] = s;
    } else {
        int id = bid - PS7;
        size_t base = (size_t)id * 1024 + tid * 4;       // 32*1024 = 32768 = NBH*CL
        zpk[base + 0] = ~0ull; zpk[base + 1] = ~0ull;
        zpk[base + 2] = ~0ull; zpk[base + 3] = ~0ull;
        if (id == 0 && tid == 0) *ctr = 0;
    }
}

// ---------------------------------------------------------------------------
// Vt[bh][v][w] from gathered V rows, split
// ---------------------------------------------------------------------------
__global__ void __launch_bounds__(256) vt_kernel(const float* __restrict__ xl_v,
                                                 const float* __restrict__ vv,
                                                 const float* __restrict__ aggu,
                                                 bf16* __restrict__ vth,
                                                 bf16* __restrict__ vtl) {
    __shared__ float tile[32][33];
    int zb = blockIdx.z;
    int w0 = blockIdx.x * 32, v0 = blockIdx.y * 32;
    int x = threadIdx.x & 31, y = (threadIdx.x >> 5) * 4;
    #pragma unroll
    for (int i = 0; i < 4; ++i) {
        int w = w0 + y + i;
        const float* srcrow;
        if (w < CM)      srcrow = xl_v + ((size_t)zb * CM + w) * CDV;
        else if (w < CW) srcrow = vv   + ((size_t)zb * CL + (w - CM)) * CDV;
        else             srcrow = aggu + ((size_t)zb * CS + (w - CW)) * CDV;
        tile[y + i][x] = srcrow[v0 + x];
    }
    __syncthreads();
    #pragma unroll
    for (int i = 0; i < 4; ++i) {
        size_t o = ((size_t)zb * CDV + v0 + y + i) * SCW + w0 + x;
        splitw(tile[x][y + i], vth + o, vtl + o);
    }
}

__global__ void __launch_bounds__(256) transform_kernel(const float* __restrict__ qraw,
                                                        const float* __restrict__ kvg,
                                                        const float* __restrict__ x_u,
                                                        const float* __restrict__ x_v,
                                                        bf16* __restrict__ quh, bf16* __restrict__ qul,
                                                        bf16* __restrict__ qvh, bf16* __restrict__ qvl,
                                                        bf16* __restrict__ klh, bf16* __restrict__ kll,
                                                        float* __restrict__ vv,
                                                        float* __restrict__ gate) {
    int wid  = threadIdx.x >> 5;
    int lane = threadIdx.x & 31;
    int idx = blockIdx.x * 8 + wid;
    int h  = idx & 7;
    int bl = idx >> 3;
    int b = bl >> 9, l = bl & 511;
    int d0 = lane * 4;

    float4 q = *(const float4*)(qraw + (size_t)bl * CDM + h * CDK + d0);
    float mu = warp_sum(q.x + q.y + q.z + q.w) * (1.f / 128.f);
    q.x -= mu; q.y -= mu; q.z -= mu; q.w -= mu;
    float var = warp_sum(q.x * q.x + q.y * q.y + q.z * q.z + q.w * q.w) * (1.f / 128.f);
    float rs = rsqrtf(var + 1e-6f);
    float4 xu = *(const float4*)(x_u + h * CDK + d0);
    float4 xv = *(const float4*)(x_v + h * CDK + d0);
    size_t o = (((size_t)b * CH + h) * CL + l) * CDK + d0;
    split4(make_float4(q.x * rs + xu.x, q.y * rs + xu.y, q.z * rs + xu.z, q.w * rs + xu.w),
           quh + o, qul + o);
    split4(make_float4(q.x * rs + xv.x, q.y * rs + xv.y, q.z * rs + xv.z, q.w * rs + xv.w),
           qvh + o, qvl + o);

    float4 k = *(const float4*)(kvg + (size_t)bl * 3072 + h * CDK + d0);
    float kmu = warp_sum(k.x + k.y + k.z + k.w) * (1.f / 128.f);
    k.x -= kmu; k.y -= kmu; k.z -= kmu; k.w -= kmu;
    float kvar = warp_sum(k.x * k.x + k.y * k.y + k.z * k.z + k.w * k.w) * (1.f / 128.f);
    float krs = rsqrtf(kvar + 1e-6f);
    split4(make_float4(k.x * krs, k.y * krs, k.z * krs, k.w * krs), klh + o, kll + o);

    *(float4*)(vv + o) = *(const float4*)(kvg + (size_t)bl * 3072 + 1024 + h * CDK + d0);

    float4 gg = *(const float4*)(kvg + (size_t)bl * 3072 + 2048 + h * CDK + d0);
    float4 gs;
    gs.x = gg.x / (1.f + __expf(-gg.x));
    gs.y = gg.y / (1.f + __expf(-gg.y));
    gs.z = gg.z / (1.f + __expf(-gg.z));
    gs.w = gg.w / (1.f + __expf(-gg.w));
    *(float4*)(gate + (size_t)bl * CDM + h * CDK + d0) = gs;
}

// ---------------------------------------------------------------------------
// NT tensor-core GEMM (bf16x3, 3-stage cp.async). MODE: 0=BD, 3=VQ, 4=PROJ
// ---------------------------------------------------------------------------
#define STG_B 12288
#define CMP_B 6144
template <int MODE>
__global__ void __launch_bounds__(256) mma_gemm_kernel(
    const bf16* __restrict__ Ah, const bf16* __restrict__ Al,
    const bf16* __restrict__ Bh, const bf16* __restrict__ Bl,
    const float* __restrict__ csq,
    unsigned long long* zpk_out,
    float* __restrict__ outp,
    int N, int K, int lda) {

    __shared__ __align__(16) bf16 SA[3][2][128][24];
    __shared__ __align__(16) bf16 SB[3][2][128][24];

    int tid  = threadIdx.x;
    int lane = tid & 31, warp = tid >> 5;
    int wm = warp >> 2, wn = warp & 3;
    int bm = blockIdx.y * 128;
    int bn = blockIdx.x * 128;
    int bh = blockIdx.z;
    int h  = bh & 7;

    // BD dead-tile skip: rel-shift never reads rbd[l][c] with c < 511 - l.
    if (MODE == 0 && (bn + bm) < 257) return;

    size_t aoff = (MODE == 4) ? 0 : (size_t)bh * CL * CDK;

    int srow = tid >> 1;
    int sc8  = (tid & 1) * 8;
    const bf16* a_h = Ah + aoff + (size_t)(bm + srow) * lda + sc8;
    const bf16* a_l = Al + aoff + (size_t)(bm + srow) * lda + sc8;
    const bf16 *b_h, *b_l;
    {
        int n = bn + srow;
        size_t boff;
        if (MODE == 0)      boff = ((size_t)h * CW + n) * CDK;
        else if (MODE == 3) boff = ((size_t)h * CS + n) * CDK;
        else                boff = (size_t)n * K;
        b_h = Bh + boff + sc8; b_l = Bl + boff + sc8;
    }

    uint32_t sA = cvta_s(&SA[0][0][0][0]);
    uint32_t sB = cvta_s(&SB[0][0][0][0]);
    uint32_t dA = sA + (uint32_t)(srow * 24 + sc8) * 2;
    uint32_t dB = sB + (uint32_t)(srow * 24 + sc8) * 2;

    int a_off = (wm * 64 + (lane & 15)) * 24 + ((lane >> 4) << 3);
    int b_off = (wn * 32 + ((lane >> 4) << 3) + (lane & 7)) * 24 + (((lane >> 3) & 1) << 3);

    float acc[4][4][4] = {};
    int T = K >> 4;

    cpa16(dA,         a_h);  cpa16(dA + CMP_B, a_l);
    cpa16(dB,         b_h);  cpa16(dB + CMP_B, b_l);
    cpa_commit();

    #pragma unroll 1
    for (int kt = 0; kt < T; ++kt) {
        if (kt + 1 < T) {
            int st = (kt + 1) % 3;
            int k0 = (kt + 1) * 16;
            cpa16(dA + st * STG_B,         a_h + k0);
            cpa16(dA + st * STG_B + CMP_B, a_l + k0);
            cpa16(dB + st * STG_B,         b_h + k0);
            cpa16(dB + st * STG_B + CMP_B, b_l + k0);
            cpa_commit();
            cpa_wait<1>();
        } else {
            cpa_wait<0>();
        }
        __syncthreads();

        int cs = kt % 3;
        uint32_t aH = sA + cs * STG_B + (uint32_t)a_off * 2;
        uint32_t bH = sB + cs * STG_B + (uint32_t)b_off * 2;
        uint32_t ah[4][4], al[4][4], bhf[4][2], blf[4][2];
        #pragma unroll
        for (int t = 0; t < 4; ++t) {
            ldmx4(aH + t * 768,         ah[t][0], ah[t][1], ah[t][2], ah[t][3]);
            ldmx4(aH + CMP_B + t * 768, al[t][0], al[t][1], al[t][2], al[t][3]);
        }
        #pragma unroll
        for (int u2 = 0; u2 < 2; ++u2) {
            uint32_t r0, r1, r2, r3;
            ldmx4(bH + u2 * 768, r0, r1, r2, r3);
            bhf[2 * u2][0] = r0; bhf[2 * u2][1] = r1;
            bhf[2 * u2 + 1][0] = r2; bhf[2 * u2 + 1][1] = r3;
            ldmx4(bH + CMP_B + u2 * 768, r0, r1, r2, r3);
            blf[2 * u2][0] = r0; blf[2 * u2][1] = r1;
            blf[2 * u2 + 1][0] = r2; blf[2 * u2 + 1][1] = r3;
        }
        #pragma unroll
        for (int t = 0; t < 4; ++t)
            #pragma unroll
            for (int u = 0; u < 4; ++u) {
                mma16816(acc[t][u], ah[t], bhf[u]);
                mma16816(acc[t][u], ah[t], blf[u]);
                mma16816(acc[t][u], al[t], bhf[u]);
            }
    }

    int g  = lane >> 2;
    int qd = lane & 3;

    if constexpr (MODE == 4) {
        #pragma unroll
        for (int t = 0; t < 4; ++t) {
            int r = bm + wm * 64 + t * 16 + g;
            #pragma unroll
            for (int u = 0; u < 4; ++u) {
                int c = bn + wn * 32 + u * 8 + qd * 2;
                *(float2*)(outp + (size_t)r * N + c) =
                    make_float2(acc[t][u][0], acc[t][u][1]);
                *(float2*)(outp + (size_t)(r + 8) * N + c) =
                    make_float2(acc[t][u][2], acc[t][u][3]);
            }
        }
    } else if constexpr (MODE == 0) {
        #pragma unroll
        for (int t = 0; t < 4; ++t) {
            int l = bm + wm * 64 + t * 16 + g;
            #pragma unroll
            for (int u = 0; u < 4; ++u) {
                int c = bn + wn * 32 + u * 8 + qd * 2;
                *(float2*)(outp + ((size_t)bh * CL + l) * CW + c) =
                    make_float2(acc[t][u][0] * TAUI, acc[t][u][1] * TAUI);
                *(float2*)(outp + ((size_t)bh * CL + l + 8) * CW + c) =
                    make_float2(acc[t][u][2] * TAUI, acc[t][u][3] * TAUI);
            }
        }
    } else {   // MODE 3: VQ argmin
        unsigned long long* zmin = reinterpret_cast<unsigned long long*>(&SA[0][0][0][0]);
        __syncthreads();
        if (tid < 128) zmin[tid] = ~0ull;
        __syncthreads();
        #pragma unroll
        for (int t = 0; t < 4; ++t) {
            unsigned long long b0 = ~0ull, b1 = ~0ull;
            #pragma unroll
            for (int u = 0; u < 4; ++u) {
                #pragma unroll
                for (int p = 0; p < 2; ++p) {
                    int s = bn + wn * 32 + u * 8 + qd * 2 + p;
                    float cs = csq[h * CS + s];
                    {
                        float val = cs - 2.f * acc[t][u][p];
                        unsigned uu = __float_as_uint(val);
                        uu = (uu & 0x80000000u) ? ~uu : (uu | 0x80000000u);
                        unsigned long long key = ((unsigned long long)uu << 32) | (unsigned)s;
                        if (key < b0) b0 = key;
                    }
                    {
                        float val = cs - 2.f * acc[t][u][2 + p];
                        unsigned uu = __float_as_uint(val);
                        uu = (uu & 0x80000000u) ? ~uu : (uu | 0x80000000u);
                        unsigned long long key = ((unsigned long long)uu << 32) | (unsigned)s;
                        if (key < b1) b1 = key;
                    }
                }
            }
            unsigned long long o;
            o = __shfl_xor_sync(0xffffffffu, b0, 1); if (o < b0) b0 = o;
            o = __shfl_xor_sync(0xffffffffu, b0, 2); if (o < b0) b0 = o;
            o = __shfl_xor_sync(0xffffffffu, b1, 1); if (o < b1) b1 = o;
            o = __shfl_xor_sync(0xffffffffu, b1, 2); if (o < b1) b1 = o;
            if (qd == 0) {
                atomicMin(&zmin[wm * 64 + t * 16 + g], b0);
                atomicMin(&zmin[wm * 64 + t * 16 + g + 8], b1);
            }
        }
        __syncthreads();
        if (tid < 128)
            atomicMin(&zpk_out[(size_t)bh * CL + bm + tid], zmin[tid]);
    }
}

// ---------------------------------------------------------------------------
// Fused attention (persistent, work-stealing): scores + online softmax + P@V
// ---------------------------------------------------------------------------
#define APITCH 272      // row pitch bytes (136 bf16)
#define APLANE 34816    // 128 * 272
#define ABUF   69632    // hi + lo
#define NUNITS 256
__global__ void __launch_bounds__(256) attn_kernel(
    const bf16* __restrict__ quh, const bf16* __restrict__ qul,
    const bf16* __restrict__ khat_h, const bf16* __restrict__ khat_l,
    const bf16* __restrict__ cb_h, const bf16* __restrict__ cb_l,
    const bf16* __restrict__ vt_h, const bf16* __restrict__ vt_l,
    const unsigned long long* __restrict__ zpk,
    const float* __restrict__ rbd,
    const float* __restrict__ agg_lower,
    const float* __restrict__ gate,
    int* __restrict__ unit_ctr,
    bf16* __restrict__ outh, bf16* __restrict__ outl) {

    extern __shared__ __align__(16) char smem_raw[];
    uint32_t sQU = cvta_s(smem_raw);
    uint32_t sKT = sQU + ABUF;
    uint32_t sVT = sQU + 2 * ABUF;
    __shared__ int s_unit;

    int tid  = threadIdx.x;
    int lane = tid & 31, warp = tid >> 5;
    int g = lane >> 2, qd = lane & 3;

    for (;;) {
        __syncthreads();                      // smem + s_unit reuse guard
        if (tid == 0) s_unit = atomicAdd(unit_ctr, 1);
        __syncthreads();
        int unit = s_unit;
        if (unit >= NUNITS) break;

        int bm = (unit >> 6) * 128;
        int bh = unit & 63;
        int h  = bh & 7;
        int b  = bh >> 3;

        int tiles[12]; int nt = 0;
        #pragma unroll
        for (int j = 0; j < 12; ++j)
            if (!(j < 8 && j * 128 >= bm + CM + 128)) tiles[nt++] = j;

        auto load_qu = [&]() {
            size_t qoff = (size_t)bh * CL * CDK;
            #pragma unroll
            for (int i = 0; i < 8; ++i) {
                int id = tid + i * 256;
                int r = id >> 4, c = id & 15;
                uint32_t d = sQU + r * APITCH + c * 16;
                cpa16(d,          quh + qoff + (size_t)(bm + r) * CDK + c * 8);
                cpa16(d + APLANE, qul + qoff + (size_t)(bm + r) * CDK + c * 8);
            }
        };
        auto load_kt = [&](int j) {
            #pragma unroll
            for (int i = 0; i < 8; ++i) {
                int id = tid + i * 256;
                int r = id >> 4, c = id & 15;
                int n = j * 128 + r;
                const bf16 *sh, *sl;
                if (j < 4) {
                    size_t o = ((size_t)bh * CM + n) * CDK;
                    sh = khat_h + o; sl = khat_l + o;
                } else if (j < 8) {
                    unsigned zi = (unsigned)(zpk[(size_t)bh * CL + (n - CM)] & 0xffffffffull);
                    size_t o = ((size_t)h * CS + zi) * CDK;
                    sh = cb_h + o; sl = cb_l + o;
                } else {
                    size_t o = ((size_t)h * CS + (n - CW)) * CDK;
                    sh = cb_h + o; sl = cb_l + o;
                }
                uint32_t d = sKT + r * APITCH + c * 16;
                cpa16(d,          sh + c * 8);
                cpa16(d + APLANE, sl + c * 8);
            }
        };
        auto load_vt = [&](int j) {
            #pragma unroll
            for (int i = 0; i < 8; ++i) {
                int id = tid + i * 256;
                int r = id >> 4, c = id & 15;
                size_t o = ((size_t)bh * CDV + r) * SCW + j * 128 + c * 8;
                uint32_t d = sVT + r * APITCH + c * 16;
                cpa16(d,          vt_h + o);
                cpa16(d + APLANE, vt_l + o);
            }
        };

        uint32_t quB = sQU + (uint32_t)(warp * 16 + (lane & 15)) * APITCH + ((lane >> 4) << 4);
        uint32_t bB  = (uint32_t)((((lane >> 4) << 3) + (lane & 7)) * APITCH) + (((lane >> 3) & 1) << 4);

        int l0 = bm + warp * 16 + g;
        int l1 = l0 + 8;

        float O[16][4] = {};
        float m0 = -3.4e38f, m1 = -3.4e38f, d0 = 0.f, d1 = 0.f;

        load_qu();
        load_kt(tiles[0]);
        cpa_commit();

        #pragma unroll 1
        for (int ti = 0; ti < nt; ++ti) {
            int j = tiles[ti];
            cpa_wait<0>();
            __syncthreads();                    // Kt_j (and qu) ready; Vt free
            load_vt(j);
            cpa_commit();

            // ---- S = qu @ Kt^T (bf16x3) -----------------------------------
            float S[16][4] = {};
            #pragma unroll
            for (int kg = 0; kg < 8; ++kg) {
                uint32_t ah[4], al[4];
                ldmx4(quB + kg * 32,          ah[0], ah[1], ah[2], ah[3]);
                ldmx4(quB + APLANE + kg * 32, al[0], al[1], al[2], al[3]);
                #pragma unroll
                for (int nf = 0; nf < 8; ++nf) {
                    uint32_t base = sKT + bB + nf * (16 * APITCH) + kg * 32;
                    uint32_t p0, p1, p2, p3, q0, q1, q2, q3;
                    ldmx4(base,          p0, p1, p2, p3);
                    ldmx4(base + APLANE, q0, q1, q2, q3);
                    uint32_t bp[2], bq[2];
                    bp[0] = p0; bp[1] = p1; bq[0] = q0; bq[1] = q1;
                    mma16816(S[nf * 2], ah, bp);
                    mma16816(S[nf * 2], ah, bq);
                    mma16816(S[nf * 2], al, bp);
                    bp[0] = p2; bp[1] = p3; bq[0] = q2; bq[1] = q3;
                    mma16816(S[nf * 2 + 1], ah, bp);
                    mma16816(S[nf * 2 + 1], ah, bq);
                    mma16816(S[nf * 2 + 1], al, bp);
                }
            }

            // ---- bias + mask ------------------------------------------------
            if (j < 8) {
                const float* rr0 = rbd + ((size_t)bh * CL + l0) * CW + (CL - 1) - l0;
                const float* rr1 = rbd + ((size_t)bh * CL + l1) * CW + (CL - 1) - l1;
                int wb = j * 128 + qd * 2;
                #pragma unroll
                for (int u = 0; u < 16; ++u) {
                    int w = wb + u * 8;
                    S[u][0] = (w     <= l0 + CM) ? S[u][0] * TAUI + rr0[w]     : -1e30f;
                    S[u][1] = (w + 1 <= l0 + CM) ? S[u][1] * TAUI + rr0[w + 1] : -1e30f;
                    S[u][2] = (w     <= l1 + CM) ? S[u][2] * TAUI + rr1[w]     : -1e30f;
                    S[u][3] = (w + 1 <= l1 + CM) ? S[u][3] * TAUI + rr1[w + 1] : -1e30f;
                }
            } else {
                int sb = (j - 8) * 128 + qd * 2;
                #pragma unroll
                for (int u = 0; u < 16; ++u) {
                    int s = sb + u * 8;
                    float a0 = agg_lower[(size_t)bh * CS + s];
                    float a1 = agg_lower[(size_t)bh * CS + s + 1];
                    float b0 = (a0 > 0.f) ? logf(fmaxf(a0, 1e-30f)) : -1e30f;
                    float b1 = (a1 > 0.f) ? logf(fmaxf(a1, 1e-30f)) : -1e30f;
                    S[u][0] = S[u][0] * TAUI + b0;
                    S[u][1] = S[u][1] * TAUI + b1;
                    S[u][2] = S[u][2] * TAUI + b0;
                    S[u][3] = S[u][3] * TAUI + b1;
                }
            }

            // ---- online softmax update -------------------------------------
            float mx0 = -3.4e38f, mx1 = -3.4e38f;
            #pragma unroll
            for (int u = 0; u < 16; ++u) {
                mx0 = fmaxf(mx0, fmaxf(S[u][0], S[u][1]));
                mx1 = fmaxf(mx1, fmaxf(S[u][2], S[u][3]));
            }
            mx0 = fmaxf(mx0, __shfl_xor_sync(0xffffffffu, mx0, 1));
            mx0 = fmaxf(mx0, __shfl_xor_sync(0xffffffffu, mx0, 2));
            mx1 = fmaxf(mx1, __shfl_xor_sync(0xffffffffu, mx1, 1));
            mx1 = fmaxf(mx1, __shfl_xor_sync(0xffffffffu, mx1, 2));
            float nm0 = fmaxf(m0, mx0), nm1 = fmaxf(m1, mx1);
            float al0 = __expf(m0 - nm0), al1 = __expf(m1 - nm1);
            m0 = nm0; m1 = nm1;
            float s0 = 0.f, s1 = 0.f;
            #pragma unroll
            for (int u = 0; u < 16; ++u) {
                S[u][0] = __expf(S[u][0] - m0);
                S[u][1] = __expf(S[u][1] - m0);
                S[u][2] = __expf(S[u][2] - m1);
                S[u][3] = __expf(S[u][3] - m1);
                s0 += S[u][0] + S[u][1];
                s1 += S[u][2] + S[u][3];
            }
            s0 += __shfl_xor_sync(0xffffffffu, s0, 1);
            s0 += __shfl_xor_sync(0xffffffffu, s0, 2);
            s1 += __shfl_xor_sync(0xffffffffu, s1, 1);
            s1 += __shfl_xor_sync(0xffffffffu, s1, 2);
            d0 = d0 * al0 + s0;
            d1 = d1 * al1 + s1;
            #pragma unroll
            for (int u = 0; u < 16; ++u) {
                O[u][0] *= al0; O[u][1] *= al0;
                O[u][2] *= al1; O[u][3] *= al1;
            }

            cpa_wait<0>();
            __syncthreads();                    // Vt_j ready; Kt free
            if (ti + 1 < nt) { load_kt(tiles[ti + 1]); cpa_commit(); }

            // ---- O += P @ V (bf16x3; P from registers) ----------------------
            #pragma unroll
            for (int kg = 0; kg < 8; ++kg) {
                int u2 = kg * 2;
                uint32_t pah[4], pal[4];
                pah[0] = packbf(S[u2][0], S[u2][1]);
                pah[1] = packbf(S[u2][2], S[u2][3]);
                pah[2] = packbf(S[u2 + 1][0], S[u2 + 1][1]);
                pah[3] = packbf(S[u2 + 1][2], S[u2 + 1][3]);
                pal[0] = packbf_res(S[u2][0], S[u2][1], pah[0]);
                pal[1] = packbf_res(S[u2][2], S[u2][3], pah[1]);
                pal[2] = packbf_res(S[u2 + 1][0], S[u2 + 1][1], pah[2]);
                pal[3] = packbf_res(S[u2 + 1][2], S[u2 + 1][3], pah[3]);
                #pragma unroll
                for (int nf = 0; nf < 8; ++nf) {
                    uint32_t base = sVT + bB + nf * (16 * APITCH) + kg * 32;
                    uint32_t p0, p1, p2, p3, q0, q1, q2, q3;
                    ldmx4(base,          p0, p1, p2, p3);
                    ldmx4(base + APLANE, q0, q1, q2, q3);
                    uint32_t bp[2], bq[2];
                    bp[0] = p0; bp[1] = p1; bq[0] = q0; bq[1] = q1;
                    mma16816(O[nf * 2], pah, bp);
                    mma16816(O[nf * 2], pah, bq);
                    mma16816(O[nf * 2], pal, bp);
                    bp[0] = p2; bp[1] = p3; bq[0] = q2; bq[1] = q3;
                    mma16816(O[nf * 2 + 1], pah, bp);
                    mma16816(O[nf * 2 + 1], pah, bq);
                    mma16816(O[nf * 2 + 1], pal, bp);
                }
            }
        }

        // ---- epilogue: O/denom * gate -> wvg hi/lo --------------------------
        float i0 = 1.f / d0, i1 = 1.f / d1;
        #pragma unroll
        for (int u = 0; u < 16; ++u) {
            int c = (u << 3) + qd * 2;
            size_t o0 = ((size_t)b * CL + l0) * CDM + h * CDV + c;
            size_t o1 = ((size_t)b * CL + l1) * CDM + h * CDV + c;
            float2 g0 = *(const float2*)(gate + o0);
            float2 g1 = *(const float2*)(gate + o1);
            splitw(O[u][0] * i0 * g0.x, outh + o0,     outl + o0);
            splitw(O[u][1] * i0 * g0.y, outh + o0 + 1, outl + o0 + 1);
            splitw(O[u][2] * i1 * g1.x, outh + o1,     outl + o1);
            splitw(O[u][3] * i1 * g1.y, outh + o1 + 1, outl + o1 + 1);
        }
    }
}

// ---------------------------------------------------------------------------
// Host launcher
// ---------------------------------------------------------------------------
#define SMEM_ATTN (3 * ABUF)   // 208896 bytes
#define ATTN_GRID 148

extern "C" void kernel_launch(void* const* d_in, const int* in_sizes, int n_in,
                              void* d_out, int out_size) {
    const float* input     = (const float*)d_in[0];
    const float* xl_k_hat  = (const float*)d_in[2];
    const float* xl_v      = (const float*)d_in[3];
    const float* agg_upper = (const float*)d_in[4];
    const float* agg_lower = (const float*)d_in[5];
    const float* W_q       = (const float*)d_in[6];
    const float* W_kvg     = (const float*)d_in[7];
    const float* W_res     = (const float*)d_in[8];
    const float* x_u       = (const float*)d_in[9];
    const float* x_v       = (const float*)d_in[10];
    const float* xl_r      = (const float*)d_in[11];
    const float* codebook  = (const float*)d_in[12];
    float* out = (float*)d_out;

    float *qraw, *kvg, *vv, *gate, *rbd, *csq;
    unsigned long long* zpk;
    int* ctr;
    bf16 *xt_h, *xt_l, *wqt_h, *wqt_l, *wkvgt_h, *wkvgt_l, *wrest_h, *wrest_l;
    bf16 *qu_h, *qu_l, *qv_h, *qv_l, *kl_h, *kl_l, *khat_h, *khat_l;
    bf16 *cb_h, *cb_l, *xlr_h, *xlr_l, *vt_h, *vt_l, *wvg_h, *wvg_l;

    cudaGetSymbolAddress((void**)&qraw, g_qraw);
    cudaGetSymbolAddress((void**)&kvg, g_kvg);
    cudaGetSymbolAddress((void**)&vv, g_vv);
    cudaGetSymbolAddress((void**)&gate, g_gate);
    cudaGetSymbolAddress((void**)&rbd, g_rbd);
    cudaGetSymbolAddress((void**)&csq, g_csq);
    cudaGetSymbolAddress((void**)&zpk, g_zpk);
    cudaGetSymbolAddress((void**)&ctr, g_unit_ctr);
    cudaGetSymbolAddress((void**)&xt_h, g_xt_h);   cudaGetSymbolAddress((void**)&xt_l, g_xt_l);
    cudaGetSymbolAddress((void**)&wqt_h, g_wqt_h); cudaGetSymbolAddress((void**)&wqt_l, g_wqt_l);
    cudaGetSymbolAddress((void**)&wkvgt_h, g_wkvgt_h); cudaGetSymbolAddress((void**)&wkvgt_l, g_wkvgt_l);
    cudaGetSymbolAddress((void**)&wrest_h, g_wrest_h); cudaGetSymbolAddress((void**)&wrest_l, g_wrest_l);
    cudaGetSymbolAddress((void**)&qu_h, g_qu_h);   cudaGetSymbolAddress((void**)&qu_l, g_qu_l);
    cudaGetSymbolAddress((void**)&qv_h, g_qv_h);   cudaGetSymbolAddress((void**)&qv_l, g_qv_l);
    cudaGetSymbolAddress((void**)&kl_h, g_kl_h);   cudaGetSymbolAddress((void**)&kl_l, g_kl_l);
    cudaGetSymbolAddress((void**)&khat_h, g_khat_h); cudaGetSymbolAddress((void**)&khat_l, g_khat_l);
    cudaGetSymbolAddress((void**)&cb_h, g_cb_h);   cudaGetSymbolAddress((void**)&cb_l, g_cb_l);
    cudaGetSymbolAddress((void**)&xlr_h, g_xlr_h); cudaGetSymbolAddress((void**)&xlr_l, g_xlr_l);
    cudaGetSymbolAddress((void**)&vt_h, g_vt_h);   cudaGetSymbolAddress((void**)&vt_l, g_vt_l);
    cudaGetSymbolAddress((void**)&wvg_h, g_wvg_h); cudaGetSymbolAddress((void**)&wvg_l, g_wvg_l);

    cudaFuncSetAttribute(attn_kernel, cudaFuncAttributeMaxDynamicSharedMemorySize, SMEM_ATTN);

    // 0. fused preprocessing (transposes, converts, LN, csq, zpk/ctr init)
    prep_kernel<<<PREP_GRID, 256>>>(W_q, W_kvg, W_res, xl_k_hat, codebook, xl_r, input,
                                    wqt_h, wqt_l, wkvgt_h, wkvgt_l, wrest_h, wrest_l,
                                    khat_h, khat_l, cb_h, cb_l, xlr_h, xlr_l,
                                    xt_h, xt_l, csq, zpk, ctr);

    // 1. projections
    mma_gemm_kernel<4><<<dim3(8, 32, 1), 256>>>(xt_h, xt_l, wqt_h, wqt_l,
                                                nullptr, nullptr, qraw, 1024, 1024, 1024);
    mma_gemm_kernel<4><<<dim3(24, 32, 1), 256>>>(xt_h, xt_l, wkvgt_h, wkvgt_l,
                                                 nullptr, nullptr, kvg, 3072, 1024, 1024);

    // 2. per-head LN, biases, silu
    transform_kernel<<<NROWS * CH / 8, 256>>>(qraw, kvg, x_u, x_v,
                                              qu_h, qu_l, qv_h, qv_l, kl_h, kl_l, vv, gate);

    // 3. V gather-transpose
    vt_kernel<<<dim3(SCW / 32, CDV / 32, NBH), 256>>>(xl_v, vv, agg_upper, vt_h, vt_l);

    // 4. VQ argmin
    mma_gemm_kernel<3><<<dim3(4, 4, NBH), 256>>>(kl_h, kl_l, cb_h, cb_l,
                                                 csq, zpk, nullptr, 512, 128, 128);

    // 5. BD (rel-shift bias source; dead tiles skipped in-kernel)
    mma_gemm_kernel<0><<<dim3(8, 4, NBH), 256>>>(qv_h, qv_l, xlr_h, xlr_l,
                                                 nullptr, nullptr, rbd, 1024, 128, 128);

    // 6. fused attention (persistent work-stealing)
    attn_kernel<<<ATTN_GRID, 256, SMEM_ATTN>>>(qu_h, qu_l, khat_h, khat_l,
                                               cb_h, cb_l, vt_h, vt_l, zpk,
                                               rbd, agg_lower, gate, ctr, wvg_h, wvg_l);

    // 7. output projection
    mma_gemm_kernel<4><<<dim3(8, 32, 1), 256>>>(wvg_h, wvg_l, wrest_h, wrest_l,
                                                nullptr, nullptr, out, 1024, 1024, 1024);
}